// round 1
// baseline (speedup 1.0000x reference)
#include <cuda_runtime.h>
#include <math.h>

#define BATCH 2
#define SEQ   2048
#define EMB   1024
#define HEADS 16
#define HDIM  64
#define MROWS (BATCH*SEQ)   /* 4096 */
#define QKVN  (3*EMB)       /* 3072 */

// ---- scratch (device globals: allocation-free per harness rules) ----
__device__ float g_W  [(size_t)EMB*QKVN];      // packed [e][3*1024] QKV weights
__device__ float g_WoT[(size_t)EMB*EMB];       // Wo transposed: [k][n]
__device__ float g_QKV[(size_t)MROWS*QKVN];    // [bt][ Q(1024) | K(1024) | V(1024) ]
__device__ float g_att[(size_t)MROWS*EMB];     // attended, [bt][h*64+i]

// ------------------------------------------------------------------
// Repack weights: g_W[e*3072 + which*1024 + h*64 + i] = W{q,k,v}[h][e][i]
// ------------------------------------------------------------------
__global__ void pack_qkv_w(const float* __restrict__ Wq,
                           const float* __restrict__ Wk,
                           const float* __restrict__ Wv) {
    int idx = blockIdx.x * blockDim.x + threadIdx.x;
    if (idx >= EMB * QKVN) return;
    int e  = idx / QKVN;
    int n  = idx % QKVN;
    int wh = n >> 10;          // 0=Q,1=K,2=V
    int hi = n & 1023;
    int h  = hi >> 6, i = hi & 63;
    const float* src = (wh == 0) ? Wq : (wh == 1) ? Wk : Wv;
    g_W[idx] = src[(size_t)h * (EMB * HDIM) + e * HDIM + i];
}

__global__ void pack_wot(const float* __restrict__ Wo) {
    int idx = blockIdx.x * blockDim.x + threadIdx.x;
    if (idx >= EMB * EMB) return;
    int k = idx >> 10, n = idx & 1023;
    g_WoT[idx] = Wo[(size_t)n * EMB + k];   // WoT[k][n] = Wo[n][k]
}

// ------------------------------------------------------------------
// fp32 SGEMM: C[M,N] = A[M,K] * B[K,N], all row-major.
// 128x128 block, BK=8, 256 threads, 8x8 per thread.
// M%128==0, N%128==0, K%8==0 assumed.
// ------------------------------------------------------------------
__global__ __launch_bounds__(256) void sgemm128(const float* __restrict__ A,
                                                const float* __restrict__ B,
                                                float* __restrict__ C,
                                                int M, int N, int K) {
    __shared__ float As[8][128];
    __shared__ float Bs[8][128];

    const int tid  = threadIdx.x;
    const int brow = blockIdx.y;
    const int bcol = blockIdx.x;

    const float* Ablk = A + (size_t)brow * 128 * K;
    const float* Bblk = B + (size_t)bcol * 128;

    const int a_r = tid >> 1;          // 0..127
    const int a_c = (tid & 1) * 4;     // 0 or 4
    const int b_r = tid >> 5;          // 0..7
    const int b_c = (tid & 31) * 4;    // 0..124

    const int tx = tid & 15;           // col group
    const int ty = tid >> 4;           // row group

    float acc[8][8];
#pragma unroll
    for (int i = 0; i < 8; i++)
#pragma unroll
        for (int j = 0; j < 8; j++) acc[i][j] = 0.f;

    for (int kt = 0; kt < K; kt += 8) {
        float4 av = *(const float4*)(Ablk + (size_t)a_r * K + kt + a_c);
        float4 bv = *(const float4*)(Bblk + (size_t)(kt + b_r) * N + b_c);
        __syncthreads();
        As[a_c + 0][a_r] = av.x;
        As[a_c + 1][a_r] = av.y;
        As[a_c + 2][a_r] = av.z;
        As[a_c + 3][a_r] = av.w;
        *(float4*)(&Bs[b_r][b_c]) = bv;
        __syncthreads();

#pragma unroll
        for (int k = 0; k < 8; k++) {
            float ar[8], br[8];
#pragma unroll
            for (int i = 0; i < 8; i++) ar[i] = As[k][ty * 8 + i];
#pragma unroll
            for (int j = 0; j < 8; j++) br[j] = Bs[k][tx * 8 + j];
#pragma unroll
            for (int i = 0; i < 8; i++)
#pragma unroll
                for (int j = 0; j < 8; j++) acc[i][j] += ar[i] * br[j];
        }
    }

#pragma unroll
    for (int i = 0; i < 8; i++) {
        float* Crow = C + (size_t)(brow * 128 + ty * 8 + i) * N + bcol * 128 + tx * 8;
        *(float4*)(Crow)     = make_float4(acc[i][0], acc[i][1], acc[i][2], acc[i][3]);
        *(float4*)(Crow + 4) = make_float4(acc[i][4], acc[i][5], acc[i][6], acc[i][7]);
    }
}

// ------------------------------------------------------------------
// Flash attention (fp32, online softmax).
// Block = (qtile=64 rows) x (head) x (batch). 256 threads = 8 warps.
// Warp w owns query rows w*8..w*8+7; lane l owns keys {l, l+32} of each
// 64-key tile, and output dims {l, l+32}.
// scale = 1/sqrt(SEQ) (reference scales by sqrt(seq_len)!).
// ------------------------------------------------------------------
__global__ __launch_bounds__(256) void flash_kernel(const float* __restrict__ QKV,
                                                    float* __restrict__ Out) {
    extern __shared__ float sm[];
    float* Qs = sm;                    // [64][64]   broadcast reads -> no pad
    float* Ks = sm + 64 * 64;          // [64][65]   pad: lane-varying row reads
    float* Vs = Ks + 64 * 65;          // [64][64]   contiguous-lane reads
    float* Ps = Vs + 64 * 64;          // [8][8][64] broadcast reads

    const int b  = blockIdx.z;
    const int h  = blockIdx.y;
    const int qt = blockIdx.x;
    const int tid = threadIdx.x;
    const int w  = tid >> 5;
    const int l  = tid & 31;

    const float scale = rsqrtf((float)SEQ);

    const float* qbase = QKV + (size_t)(b * SEQ) * QKVN + h * HDIM;

    // load + pre-scale Q tile
    for (int i = tid; i < 64 * 64; i += 256) {
        int r = i >> 6, e = i & 63;
        Qs[r * 64 + e] = qbase[(size_t)(qt * 64 + r) * QKVN + e] * scale;
    }

    float m[8], lsum[8], acc0[8], acc1[8];
#pragma unroll
    for (int r = 0; r < 8; r++) { m[r] = -1e30f; lsum[r] = 0.f; acc0[r] = 0.f; acc1[r] = 0.f; }

    __syncthreads();

    for (int kt = 0; kt < SEQ / 64; kt++) {
        __syncthreads();  // previous tile's PV reads of Vs/Ps complete
        const float* kbase = QKV + (size_t)(b * SEQ + kt * 64) * QKVN + EMB + h * HDIM;
        const float* vbase = kbase + EMB;
        for (int i = tid; i < 64 * 64; i += 256) {
            int r = i >> 6, e = i & 63;
            Ks[r * 65 + e] = kbase[(size_t)r * QKVN + e];
            Vs[r * 64 + e] = vbase[(size_t)r * QKVN + e];
        }
        __syncthreads();

        // S = Q K^T  (per lane: 8 rows x 2 keys)
        float s0[8], s1[8];
#pragma unroll
        for (int r = 0; r < 8; r++) { s0[r] = 0.f; s1[r] = 0.f; }
#pragma unroll 4
        for (int e = 0; e < 64; e++) {
            float k0 = Ks[l * 65 + e];
            float k1 = Ks[(l + 32) * 65 + e];
#pragma unroll
            for (int r = 0; r < 8; r++) {
                float q = Qs[(w * 8 + r) * 64 + e];
                s0[r] += q * k0;
                s1[r] += q * k1;
            }
        }

        // online softmax per row
#pragma unroll
        for (int r = 0; r < 8; r++) {
            float mx = fmaxf(s0[r], s1[r]);
#pragma unroll
            for (int off = 16; off > 0; off >>= 1)
                mx = fmaxf(mx, __shfl_xor_sync(0xffffffffu, mx, off));
            float mnew = fmaxf(m[r], mx);
            float p0 = __expf(s0[r] - mnew);
            float p1 = __expf(s1[r] - mnew);
            float alpha = __expf(m[r] - mnew);
            m[r] = mnew;
            float psum = p0 + p1;
#pragma unroll
            for (int off = 16; off > 0; off >>= 1)
                psum += __shfl_xor_sync(0xffffffffu, psum, off);
            lsum[r] = lsum[r] * alpha + psum;
            acc0[r] *= alpha;
            acc1[r] *= alpha;
            Ps[((w * 8 + r) << 6) + l]      = p0;
            Ps[((w * 8 + r) << 6) + l + 32] = p1;
        }
        __syncwarp();

        // O += P V  (per lane: 8 rows x 2 dims {l, l+32})
#pragma unroll 4
        for (int j = 0; j < 64; j++) {
            float v0 = Vs[j * 64 + l];
            float v1 = Vs[j * 64 + l + 32];
#pragma unroll
            for (int r = 0; r < 8; r++) {
                float p = Ps[((w * 8 + r) << 6) + j];
                acc0[r] += p * v0;
                acc1[r] += p * v1;
            }
        }
    }

    // write normalized output
#pragma unroll
    for (int r = 0; r < 8; r++) {
        float il = 1.0f / lsum[r];
        size_t row = (size_t)(b * SEQ + qt * 64 + w * 8 + r);
        Out[row * EMB + h * HDIM + l]      = acc0[r] * il;
        Out[row * EMB + h * HDIM + l + 32] = acc1[r] * il;
    }
}

// ------------------------------------------------------------------
extern "C" void kernel_launch(void* const* d_in, const int* in_sizes, int n_in,
                              void* d_out, int out_size) {
    const float* x  = (const float*)d_in[0];
    const float* Wq = (const float*)d_in[1];
    const float* Wk = (const float*)d_in[2];
    const float* Wv = (const float*)d_in[3];
    const float* Wo = (const float*)d_in[4];
    float* out = (float*)d_out;

    float *gW, *gWoT, *gQKV, *gAtt;
    cudaGetSymbolAddress((void**)&gW,   g_W);
    cudaGetSymbolAddress((void**)&gWoT, g_WoT);
    cudaGetSymbolAddress((void**)&gQKV, g_QKV);
    cudaGetSymbolAddress((void**)&gAtt, g_att);

    // flash kernel needs 65792 B dynamic smem (> 48K default)
    static int smem_set = 0;
    const int FLASH_SMEM = (64*64 + 64*65 + 64*64 + 8*8*64) * (int)sizeof(float);
    cudaFuncSetAttribute(flash_kernel, cudaFuncAttributeMaxDynamicSharedMemorySize, FLASH_SMEM);
    (void)smem_set;

    // 1) repack weights
    pack_qkv_w<<<(EMB * QKVN + 255) / 256, 256>>>(Wq, Wk, Wv);
    pack_wot<<<(EMB * EMB + 255) / 256, 256>>>(Wo);

    // 2) fused QKV projection: [4096,1024] x [1024,3072] -> g_QKV
    {
        dim3 grid(QKVN / 128, MROWS / 128);
        sgemm128<<<grid, 256>>>(x, gW, gQKV, MROWS, QKVN, EMB);
    }

    // 3) attention (flash, fp32)
    {
        dim3 grid(SEQ / 64, HEADS, BATCH);
        flash_kernel<<<grid, 256, FLASH_SMEM>>>(gQKV, gAtt);
    }

    // 4) output projection: [4096,1024] x [1024,1024] -> out
    {
        dim3 grid(EMB / 128, MROWS / 128);
        sgemm128<<<grid, 256>>>(gAtt, gWoT, out, MROWS, EMB, EMB);
    }
}

// round 3
// speedup vs baseline: 2.7455x; 2.7455x over previous
#include <cuda_runtime.h>
#include <cuda_bf16.h>
#include <stdint.h>
#include <math.h>

#define BATCH 2
#define SEQ   2048
#define EMB   1024
#define HEADS 16
#define HDIM  64
#define MROWS (BATCH*SEQ)   /* 4096 */
#define QKVN  (3*EMB)       /* 3072 */
#define KDIM  EMB

#define QSCALE 0.02209708691207961f   /* 1/sqrt(2048) */

// ---------------- scratch (device globals; allocation-free) ----------------
__device__ __align__(256) __nv_bfloat16 g_xh [(size_t)MROWS*EMB];
__device__ __align__(256) __nv_bfloat16 g_xl [(size_t)MROWS*EMB];
__device__ __align__(256) __nv_bfloat16 g_Bqh[(size_t)QKVN*EMB];
__device__ __align__(256) __nv_bfloat16 g_Bql[(size_t)QKVN*EMB];
__device__ __align__(256) __nv_bfloat16 g_Boh[(size_t)EMB*EMB];
__device__ __align__(256) __nv_bfloat16 g_Bol[(size_t)EMB*EMB];
__device__ __align__(256) __nv_bfloat16 g_QKVh[(size_t)MROWS*QKVN];
__device__ __align__(256) __nv_bfloat16 g_QKVl[(size_t)MROWS*QKVN];
__device__ __align__(256) __nv_bfloat16 g_Ah [(size_t)MROWS*EMB];
__device__ __align__(256) __nv_bfloat16 g_Al [(size_t)MROWS*EMB];

// ---------------- helpers ----------------
__device__ __forceinline__ uint32_t cvta_smem(const void* p) {
    uint32_t a;
    asm("{ .reg .u64 t; cvta.to.shared.u64 t, %1; cvt.u32.u64 %0, t; }" : "=r"(a) : "l"(p));
    return a;
}
__device__ __forceinline__ void cp16(uint32_t dst, const void* src) {
    asm volatile("cp.async.cg.shared.global [%0], [%1], 16;" :: "r"(dst), "l"(src));
}
#define CP_COMMIT() asm volatile("cp.async.commit_group;" ::: "memory")
#define CP_WAIT1()  asm volatile("cp.async.wait_group 1;" ::: "memory")
#define CP_WAIT0()  asm volatile("cp.async.wait_group 0;" ::: "memory")

__device__ __forceinline__ void ldsm4(uint32_t& r0, uint32_t& r1, uint32_t& r2, uint32_t& r3,
                                      uint32_t addr) {
    asm volatile("ldmatrix.sync.aligned.m8n8.x4.shared.b16 {%0,%1,%2,%3},[%4];"
                 : "=r"(r0), "=r"(r1), "=r"(r2), "=r"(r3) : "r"(addr));
}
__device__ __forceinline__ void ldsm4t(uint32_t& r0, uint32_t& r1, uint32_t& r2, uint32_t& r3,
                                       uint32_t addr) {
    asm volatile("ldmatrix.sync.aligned.m8n8.x4.trans.shared.b16 {%0,%1,%2,%3},[%4];"
                 : "=r"(r0), "=r"(r1), "=r"(r2), "=r"(r3) : "r"(addr));
}
__device__ __forceinline__ void mma_bf(float c[4], const uint32_t a[4], uint32_t b0, uint32_t b1) {
    asm volatile("mma.sync.aligned.m16n8k16.row.col.f32.bf16.bf16.f32 "
                 "{%0,%1,%2,%3}, {%4,%5,%6,%7}, {%8,%9}, {%0,%1,%2,%3};"
                 : "+f"(c[0]), "+f"(c[1]), "+f"(c[2]), "+f"(c[3])
                 : "r"(a[0]), "r"(a[1]), "r"(a[2]), "r"(a[3]), "r"(b0), "r"(b1));
}

__device__ __forceinline__ uint32_t packbf(float x, float y) {
    __nv_bfloat162 t = __floats2bfloat162_rn(x, y);
    return *reinterpret_cast<uint32_t*>(&t);
}
__device__ __forceinline__ uint32_t packres(float x, float y, uint32_t h) {
    __nv_bfloat162 hh = *reinterpret_cast<__nv_bfloat162*>(&h);
    return packbf(x - __bfloat162float(hh.x), y - __bfloat162float(hh.y));
}
__device__ __forceinline__ void split2(float v, __nv_bfloat16& hi, __nv_bfloat16& lo) {
    hi = __float2bfloat16(v);
    lo = __float2bfloat16(v - __bfloat162float(hi));
}

// ---------------- packing kernels ----------------
__global__ void split_x(const float* __restrict__ x,
                        __nv_bfloat16* __restrict__ hi, __nv_bfloat16* __restrict__ lo, int n) {
    int i = blockIdx.x * blockDim.x + threadIdx.x;
    if (i >= n) return;
    split2(x[i], hi[i], lo[i]);
}

// B_qkv[n][k]; n = wh*1024 + h*64 + i ; Q part pre-scaled by 1/sqrt(SEQ)
__global__ void pack_qkv(const float* __restrict__ Wq, const float* __restrict__ Wk,
                         const float* __restrict__ Wv,
                         __nv_bfloat16* __restrict__ hi, __nv_bfloat16* __restrict__ lo) {
    int idx = blockIdx.x * blockDim.x + threadIdx.x;
    if (idx >= QKVN * EMB) return;
    int n = idx >> 10, k = idx & 1023;
    int wh = n >> 10, hid = (n >> 6) & 15, i = n & 63;
    const float* src = (wh == 0) ? Wq : (wh == 1) ? Wk : Wv;
    float v = src[(size_t)hid * (EMB * HDIM) + (size_t)k * HDIM + i];
    if (wh == 0) v *= QSCALE;
    split2(v, hi[idx], lo[idx]);
}

__global__ void pack_wo(const float* __restrict__ Wo,
                        __nv_bfloat16* __restrict__ hi, __nv_bfloat16* __restrict__ lo) {
    int idx = blockIdx.x * blockDim.x + threadIdx.x;
    if (idx >= EMB * EMB) return;
    split2(Wo[idx], hi[idx], lo[idx]);
}

// ---------------- GEMM: C[M,N] = A[M,K] * B[N,K]^T, bf16 3-pass split, mma.sync ----------------
// CTA: 256 thr (8 warps 4x2), tile 128x128, BK=32, 2-stage cp.async.
// smem tile pitch 40 bf16 (80B): conflict-free ldmatrix.
// MODE 0: fp32 C out.  MODE 1: bf16 hi/lo out (Ch/Cl).
template<int MODE>
__global__ __launch_bounds__(256)
void gemm_mma(const __nv_bfloat16* __restrict__ Ah, const __nv_bfloat16* __restrict__ Al,
              const __nv_bfloat16* __restrict__ Bh, const __nv_bfloat16* __restrict__ Bl,
              float* __restrict__ C, __nv_bfloat16* __restrict__ Ch,
              __nv_bfloat16* __restrict__ Cl, int N) {
    extern __shared__ __align__(16) char smraw[];
    uint32_t smb = cvta_smem(smraw);
    const int tid = threadIdx.x, lane = tid & 31, wid = tid >> 5;
    const int wm = wid & 3, wn = wid >> 2;
    const int nb = blockIdx.x, mb = blockIdx.y;

    const __nv_bfloat16* gsrc[4] = {
        Ah + (size_t)mb * 128 * KDIM, Al + (size_t)mb * 128 * KDIM,
        Bh + (size_t)nb * 128 * KDIM, Bl + (size_t)nb * 128 * KDIM };

    auto ldchunk = [&](int buf, int ck) {
        uint32_t bb = smb + buf * 40960;
#pragma unroll
        for (int q = 0; q < 8; q++) {
            int i = q * 256 + tid;          // 0..2047
            int t = i >> 9;
            int r = (i >> 2) & 127;
            int sg = i & 3;
            cp16(bb + t * 10240 + r * 80 + sg * 16,
                 gsrc[t] + (size_t)r * KDIM + ck * 32 + sg * 8);
        }
    };

    ldchunk(0, 0); CP_COMMIT();
    ldchunk(1, 1); CP_COMMIT();

    float acc[2][8][4];
#pragma unroll
    for (int a = 0; a < 2; a++)
#pragma unroll
        for (int b = 0; b < 8; b++)
#pragma unroll
            for (int c = 0; c < 4; c++) acc[a][b][c] = 0.f;

    for (int c = 0; c < 32; c++) {
        if (c < 31) CP_WAIT1(); else CP_WAIT0();
        __syncthreads();
        uint32_t bb = smb + (c & 1) * 40960;

#pragma unroll
        for (int s = 0; s < 2; s++) {
            uint32_t ah[2][4], al[2][4];
#pragma unroll
            for (int mt = 0; mt < 2; mt++) {
                uint32_t row = 32 * wm + 16 * mt + ((lane >> 3) & 1) * 8 + (lane & 7);
                uint32_t kb  = (lane >> 4) * 16 + s * 32;
                uint32_t ad  = bb + row * 80 + kb;
                ldsm4(ah[mt][0], ah[mt][1], ah[mt][2], ah[mt][3], ad);
                ldsm4(al[mt][0], al[mt][1], al[mt][2], al[mt][3], ad + 10240);
            }
#pragma unroll
            for (int np = 0; np < 4; np++) {
                uint32_t row = 64 * wn + 16 * np + ((lane >> 4) & 1) * 8 + (lane & 7);
                uint32_t kb  = ((lane >> 3) & 1) * 16 + s * 32;
                uint32_t bd  = bb + 20480 + row * 80 + kb;
                uint32_t bh0, bh1, bh2, bh3, bl0, bl1, bl2, bl3;
                ldsm4(bh0, bh1, bh2, bh3, bd);
                ldsm4(bl0, bl1, bl2, bl3, bd + 10240);
#pragma unroll
                for (int mt = 0; mt < 2; mt++) {
                    mma_bf(acc[mt][2 * np],     ah[mt], bh0, bh1);
                    mma_bf(acc[mt][2 * np],     al[mt], bh0, bh1);
                    mma_bf(acc[mt][2 * np],     ah[mt], bl0, bl1);
                    mma_bf(acc[mt][2 * np + 1], ah[mt], bh2, bh3);
                    mma_bf(acc[mt][2 * np + 1], al[mt], bh2, bh3);
                    mma_bf(acc[mt][2 * np + 1], ah[mt], bl2, bl3);
                }
            }
        }
        __syncthreads();
        if (c + 2 < 32) { ldchunk(c & 1, c + 2); CP_COMMIT(); }
    }

    const int grp = lane >> 2, qr = lane & 3;
#pragma unroll
    for (int mt = 0; mt < 2; mt++) {
        size_t r0 = (size_t)mb * 128 + 32 * wm + 16 * mt + grp;
#pragma unroll
        for (int nt = 0; nt < 8; nt++) {
            int col = nb * 128 + 64 * wn + 8 * nt + 2 * qr;
            float* c4 = acc[mt][nt];
            if (MODE == 0) {
                *(float2*)&C[r0 * N + col]       = make_float2(c4[0], c4[1]);
                *(float2*)&C[(r0 + 8) * N + col] = make_float2(c4[2], c4[3]);
            } else {
                uint32_t h0 = packbf(c4[0], c4[1]), l0 = packres(c4[0], c4[1], h0);
                uint32_t h1 = packbf(c4[2], c4[3]), l1 = packres(c4[2], c4[3], h1);
                *(uint32_t*)&Ch[r0 * N + col]       = h0;
                *(uint32_t*)&Cl[r0 * N + col]       = l0;
                *(uint32_t*)&Ch[(r0 + 8) * N + col] = h1;
                *(uint32_t*)&Cl[(r0 + 8) * N + col] = l1;
            }
        }
    }
}

// ---------------- Flash attention via mma.sync ----------------
// CTA = (qtile 128 rows, head, batch), 256 thr / 8 warps, warp owns 16 rows.
// K/V tiles of 128 keys double-buffered in smem (pitch 72 bf16 = 144B).
// S = Q K^T 3-pass bf16 split; online softmax in regs; P split in regs; PV 3-pass.
#define FPITCH 144          /* bytes per smem row */
#define FTILE  18432        /* 128*144 */
#define FSTAGE 73728        /* 4 tiles */

__global__ __launch_bounds__(256)
void flash_mma(const __nv_bfloat16* __restrict__ Qh, const __nv_bfloat16* __restrict__ Ql,
               __nv_bfloat16* __restrict__ Oh, __nv_bfloat16* __restrict__ Ol) {
    extern __shared__ __align__(16) char smraw[];
    uint32_t smb = cvta_smem(smraw);

    const int tid = threadIdx.x, lane = tid & 31, w = tid >> 5;
    const int grp = lane >> 2, qr = lane & 3;
    const int qt = blockIdx.x, h = blockIdx.y, b = blockIdx.z;

    const size_t batch_row = (size_t)b * SEQ;

    // K/V gmem bases (hi/lo)
    const __nv_bfloat16* kvsrc[4] = {
        Qh + batch_row * QKVN + EMB + h * HDIM,          // Kh
        Ql + batch_row * QKVN + EMB + h * HDIM,          // Kl
        Qh + batch_row * QKVN + 2 * EMB + h * HDIM,      // Vh
        Ql + batch_row * QKVN + 2 * EMB + h * HDIM };    // Vl

    auto ldtile = [&](int buf, int kt) {
        uint32_t bb = smb + buf * FSTAGE;
        size_t rbase = (size_t)kt * 128;
#pragma unroll
        for (int q = 0; q < 16; q++) {
            int i = q * 256 + tid;          // 0..4095
            int t = i >> 10;
            int r = (i >> 3) & 127;
            int sg = i & 7;
            cp16(bb + t * FTILE + r * FPITCH + sg * 16,
                 kvsrc[t] + (rbase + r) * QKVN + sg * 8);
        }
    };

    // ---- load Q fragments (pre-scaled by 1/sqrt(SEQ) in pack) ----
    uint32_t qh[4][4], ql[4][4];
    {
        size_t r0 = batch_row + (size_t)qt * 128 + w * 16 + grp;
        const __nv_bfloat16* qb_h = Qh + r0 * QKVN + h * HDIM;
        const __nv_bfloat16* qb_l = Ql + r0 * QKVN + h * HDIM;
#pragma unroll
        for (int t = 0; t < 4; t++) {
            int c0 = t * 16 + 2 * qr;
            qh[t][0] = *(const uint32_t*)(qb_h + c0);
            qh[t][1] = *(const uint32_t*)(qb_h + 8 * QKVN + c0);
            qh[t][2] = *(const uint32_t*)(qb_h + c0 + 8);
            qh[t][3] = *(const uint32_t*)(qb_h + 8 * QKVN + c0 + 8);
            ql[t][0] = *(const uint32_t*)(qb_l + c0);
            ql[t][1] = *(const uint32_t*)(qb_l + 8 * QKVN + c0);
            ql[t][2] = *(const uint32_t*)(qb_l + c0 + 8);
            ql[t][3] = *(const uint32_t*)(qb_l + 8 * QKVN + c0 + 8);
        }
    }

    float o[8][4];
#pragma unroll
    for (int j = 0; j < 8; j++)
#pragma unroll
        for (int c = 0; c < 4; c++) o[j][c] = 0.f;
    float m0 = -1e30f, m1 = -1e30f, l0 = 0.f, l1 = 0.f;

    ldtile(0, 0); CP_COMMIT();
    ldtile(1, 1); CP_COMMIT();

    for (int kt = 0; kt < SEQ / 128; kt++) {
        if (kt < SEQ / 128 - 1) CP_WAIT1(); else CP_WAIT0();
        __syncthreads();
        uint32_t sb  = smb + (kt & 1) * FSTAGE;
        uint32_t khb = sb, klb = sb + FTILE, vhb = sb + 2 * FTILE, vlb = sb + 3 * FTILE;

        // ---- S = Q K^T (16 x 128 per warp), 3-pass split ----
        float s[16][4];
#pragma unroll
        for (int j = 0; j < 16; j++) {
            uint32_t ka = khb + (8 * j + (lane & 7)) * FPITCH + (lane >> 3) * 16;
            uint32_t la = ka + (klb - khb);
            uint32_t h0, h1, h2, h3, h4, h5, h6, h7;
            uint32_t e0, e1, e2, e3, e4, e5, e6, e7;
            ldsm4(h0, h1, h2, h3, ka);
            ldsm4(h4, h5, h6, h7, ka + 64);
            ldsm4(e0, e1, e2, e3, la);
            ldsm4(e4, e5, e6, e7, la + 64);
            s[j][0] = s[j][1] = s[j][2] = s[j][3] = 0.f;
            mma_bf(s[j], qh[0], h0, h1); mma_bf(s[j], ql[0], h0, h1); mma_bf(s[j], qh[0], e0, e1);
            mma_bf(s[j], qh[1], h2, h3); mma_bf(s[j], ql[1], h2, h3); mma_bf(s[j], qh[1], e2, e3);
            mma_bf(s[j], qh[2], h4, h5); mma_bf(s[j], ql[2], h4, h5); mma_bf(s[j], qh[2], e4, e5);
            mma_bf(s[j], qh[3], h6, h7); mma_bf(s[j], ql[3], h6, h7); mma_bf(s[j], qh[3], e6, e7);
        }

        // ---- online softmax (rows grp, grp+8) ----
        float n0 = m0, n1 = m1;
#pragma unroll
        for (int j = 0; j < 16; j++) {
            n0 = fmaxf(n0, fmaxf(s[j][0], s[j][1]));
            n1 = fmaxf(n1, fmaxf(s[j][2], s[j][3]));
        }
        n0 = fmaxf(n0, __shfl_xor_sync(0xffffffffu, n0, 1));
        n0 = fmaxf(n0, __shfl_xor_sync(0xffffffffu, n0, 2));
        n1 = fmaxf(n1, __shfl_xor_sync(0xffffffffu, n1, 1));
        n1 = fmaxf(n1, __shfl_xor_sync(0xffffffffu, n1, 2));
        float a0 = __expf(m0 - n0), a1 = __expf(m1 - n1);
        m0 = n0; m1 = n1;
        float rs0 = 0.f, rs1 = 0.f;
#pragma unroll
        for (int j = 0; j < 16; j++) {
            s[j][0] = __expf(s[j][0] - n0); rs0 += s[j][0];
            s[j][1] = __expf(s[j][1] - n0); rs0 += s[j][1];
            s[j][2] = __expf(s[j][2] - n1); rs1 += s[j][2];
            s[j][3] = __expf(s[j][3] - n1); rs1 += s[j][3];
        }
        rs0 += __shfl_xor_sync(0xffffffffu, rs0, 1);
        rs0 += __shfl_xor_sync(0xffffffffu, rs0, 2);
        rs1 += __shfl_xor_sync(0xffffffffu, rs1, 1);
        rs1 += __shfl_xor_sync(0xffffffffu, rs1, 2);
        l0 = l0 * a0 + rs0;
        l1 = l1 * a1 + rs1;
#pragma unroll
        for (int j = 0; j < 8; j++) {
            o[j][0] *= a0; o[j][1] *= a0; o[j][2] *= a1; o[j][3] *= a1;
        }

        // ---- O += P V, P split in regs, 3-pass ----
#pragma unroll
        for (int kcp = 0; kcp < 4; kcp++) {
            uint32_t ph[2][4], pl[2][4];
#pragma unroll
            for (int u = 0; u < 2; u++) {
                int nt = 4 * kcp + 2 * u;
                ph[u][0] = packbf(s[nt][0], s[nt][1]);     pl[u][0] = packres(s[nt][0], s[nt][1], ph[u][0]);
                ph[u][1] = packbf(s[nt][2], s[nt][3]);     pl[u][1] = packres(s[nt][2], s[nt][3], ph[u][1]);
                ph[u][2] = packbf(s[nt+1][0], s[nt+1][1]); pl[u][2] = packres(s[nt+1][0], s[nt+1][1], ph[u][2]);
                ph[u][3] = packbf(s[nt+1][2], s[nt+1][3]); pl[u][3] = packres(s[nt+1][2], s[nt+1][3], ph[u][3]);
            }
#pragma unroll
            for (int j2 = 0; j2 < 8; j2++) {
                uint32_t va = vhb + (32 * kcp + lane) * FPITCH + j2 * 16;
                uint32_t v0, v1, v2, v3, u0, u1, u2, u3;
                ldsm4t(v0, v1, v2, v3, va);
                ldsm4t(u0, u1, u2, u3, va + (vlb - vhb));
                mma_bf(o[j2], ph[0], v0, v1);
                mma_bf(o[j2], pl[0], v0, v1);
                mma_bf(o[j2], ph[0], u0, u1);
                mma_bf(o[j2], ph[1], v2, v3);
                mma_bf(o[j2], pl[1], v2, v3);
                mma_bf(o[j2], ph[1], u2, u3);
            }
        }

        __syncthreads();
        if (kt + 2 < SEQ / 128) { ldtile(kt & 1, kt + 2); CP_COMMIT(); }
    }

    // ---- epilogue: normalize, split bf16, store ----
    float inv0 = 1.f / l0, inv1 = 1.f / l1;
    size_t r0 = batch_row + (size_t)qt * 128 + w * 16 + grp;
#pragma unroll
    for (int j2 = 0; j2 < 8; j2++) {
        int c = h * HDIM + 8 * j2 + 2 * qr;
        float x0 = o[j2][0] * inv0, x1 = o[j2][1] * inv0;
        float x2 = o[j2][2] * inv1, x3 = o[j2][3] * inv1;
        uint32_t h0 = packbf(x0, x1), lo0 = packres(x0, x1, h0);
        uint32_t h1 = packbf(x2, x3), lo1 = packres(x2, x3, h1);
        *(uint32_t*)&Oh[r0 * EMB + c]       = h0;
        *(uint32_t*)&Ol[r0 * EMB + c]       = lo0;
        *(uint32_t*)&Oh[(r0 + 8) * EMB + c] = h1;
        *(uint32_t*)&Ol[(r0 + 8) * EMB + c] = lo1;
    }
}

// ------------------------------------------------------------------
extern "C" void kernel_launch(void* const* d_in, const int* in_sizes, int n_in,
                              void* d_out, int out_size) {
    const float* x  = (const float*)d_in[0];
    const float* Wq = (const float*)d_in[1];
    const float* Wk = (const float*)d_in[2];
    const float* Wv = (const float*)d_in[3];
    const float* Wo = (const float*)d_in[4];
    float* out = (float*)d_out;

    __nv_bfloat16 *gxh, *gxl, *gBqh, *gBql, *gBoh, *gBol, *gQh, *gQl, *gAh, *gAl;
    cudaGetSymbolAddress((void**)&gxh,  g_xh);
    cudaGetSymbolAddress((void**)&gxl,  g_xl);
    cudaGetSymbolAddress((void**)&gBqh, g_Bqh);
    cudaGetSymbolAddress((void**)&gBql, g_Bql);
    cudaGetSymbolAddress((void**)&gBoh, g_Boh);
    cudaGetSymbolAddress((void**)&gBol, g_Bol);
    cudaGetSymbolAddress((void**)&gQh,  g_QKVh);
    cudaGetSymbolAddress((void**)&gQl,  g_QKVl);
    cudaGetSymbolAddress((void**)&gAh,  g_Ah);
    cudaGetSymbolAddress((void**)&gAl,  g_Al);

    const int GSMEM = 2 * 40960;
    const int FSMEM = 2 * FSTAGE;
    cudaFuncSetAttribute(gemm_mma<0>, cudaFuncAttributeMaxDynamicSharedMemorySize, GSMEM);
    cudaFuncSetAttribute(gemm_mma<1>, cudaFuncAttributeMaxDynamicSharedMemorySize, GSMEM);
    cudaFuncSetAttribute(flash_mma,   cudaFuncAttributeMaxDynamicSharedMemorySize, FSMEM);

    split_x<<<(MROWS * EMB + 255) / 256, 256>>>(x, gxh, gxl, MROWS * EMB);
    pack_qkv<<<(QKVN * EMB + 255) / 256, 256>>>(Wq, Wk, Wv, gBqh, gBql);
    pack_wo<<<(EMB * EMB + 255) / 256, 256>>>(Wo, gBoh, gBol);

    // QKV projection -> bf16 hi/lo QKV
    gemm_mma<1><<<dim3(QKVN / 128, MROWS / 128), 256, GSMEM>>>(
        gxh, gxl, gBqh, gBql, nullptr, gQh, gQl, QKVN);

    // attention
    flash_mma<<<dim3(SEQ / 128, HEADS, BATCH), 256, FSMEM>>>(gQh, gQl, gAh, gAl);

    // output projection -> fp32 out
    gemm_mma<0><<<dim3(EMB / 128, MROWS / 128), 256, GSMEM>>>(
        gAh, gAl, gBoh, gBol, out, nullptr, nullptr, EMB);
}

// round 4
// speedup vs baseline: 3.0344x; 1.1052x over previous
#include <cuda_runtime.h>
#include <cuda_bf16.h>
#include <stdint.h>
#include <math.h>

#define BATCH 2
#define SEQ   2048
#define EMB   1024
#define HEADS 16
#define HDIM  64
#define MROWS (BATCH*SEQ)   /* 4096 */
#define QKVN  (3*EMB)       /* 3072 */
#define KDIM  EMB

#define QSCALE 0.02209708691207961f   /* 1/sqrt(2048) */

// ---------------- scratch (device globals; allocation-free) ----------------
__device__ __align__(256) __nv_bfloat16 g_xh [(size_t)MROWS*EMB];
__device__ __align__(256) __nv_bfloat16 g_xl [(size_t)MROWS*EMB];
__device__ __align__(256) __nv_bfloat16 g_Bqh[(size_t)QKVN*EMB];
__device__ __align__(256) __nv_bfloat16 g_Bql[(size_t)QKVN*EMB];
__device__ __align__(256) __nv_bfloat16 g_Boh[(size_t)EMB*EMB];
__device__ __align__(256) __nv_bfloat16 g_Bol[(size_t)EMB*EMB];
__device__ __align__(256) __nv_bfloat16 g_QKVh[(size_t)MROWS*QKVN];
__device__ __align__(256) __nv_bfloat16 g_QKVl[(size_t)MROWS*QKVN];
__device__ __align__(256) __nv_bfloat16 g_Ah [(size_t)MROWS*EMB];
__device__ __align__(256) __nv_bfloat16 g_Al [(size_t)MROWS*EMB];

// ---------------- helpers ----------------
__device__ __forceinline__ uint32_t cvta_smem(const void* p) {
    uint32_t a;
    asm("{ .reg .u64 t; cvta.to.shared.u64 t, %1; cvt.u32.u64 %0, t; }" : "=r"(a) : "l"(p));
    return a;
}
__device__ __forceinline__ void cp16(uint32_t dst, const void* src) {
    asm volatile("cp.async.cg.shared.global [%0], [%1], 16;" :: "r"(dst), "l"(src));
}
#define CP_COMMIT() asm volatile("cp.async.commit_group;" ::: "memory")
#define CP_WAIT1()  asm volatile("cp.async.wait_group 1;" ::: "memory")
#define CP_WAIT0()  asm volatile("cp.async.wait_group 0;" ::: "memory")

__device__ __forceinline__ void ldsm4(uint32_t& r0, uint32_t& r1, uint32_t& r2, uint32_t& r3,
                                      uint32_t addr) {
    asm volatile("ldmatrix.sync.aligned.m8n8.x4.shared.b16 {%0,%1,%2,%3},[%4];"
                 : "=r"(r0), "=r"(r1), "=r"(r2), "=r"(r3) : "r"(addr));
}
__device__ __forceinline__ void ldsm4t(uint32_t& r0, uint32_t& r1, uint32_t& r2, uint32_t& r3,
                                       uint32_t addr) {
    asm volatile("ldmatrix.sync.aligned.m8n8.x4.trans.shared.b16 {%0,%1,%2,%3},[%4];"
                 : "=r"(r0), "=r"(r1), "=r"(r2), "=r"(r3) : "r"(addr));
}
__device__ __forceinline__ void mma_bf(float c[4], const uint32_t a[4], uint32_t b0, uint32_t b1) {
    asm volatile("mma.sync.aligned.m16n8k16.row.col.f32.bf16.bf16.f32 "
                 "{%0,%1,%2,%3}, {%4,%5,%6,%7}, {%8,%9}, {%0,%1,%2,%3};"
                 : "+f"(c[0]), "+f"(c[1]), "+f"(c[2]), "+f"(c[3])
                 : "r"(a[0]), "r"(a[1]), "r"(a[2]), "r"(a[3]), "r"(b0), "r"(b1));
}

__device__ __forceinline__ uint32_t packbf(float x, float y) {
    __nv_bfloat162 t = __floats2bfloat162_rn(x, y);
    return *reinterpret_cast<uint32_t*>(&t);
}
__device__ __forceinline__ uint32_t packres(float x, float y, uint32_t h) {
    __nv_bfloat162 hh = *reinterpret_cast<__nv_bfloat162*>(&h);
    return packbf(x - __bfloat162float(hh.x), y - __bfloat162float(hh.y));
}
__device__ __forceinline__ void split2(float v, __nv_bfloat16& hi, __nv_bfloat16& lo) {
    hi = __float2bfloat16(v);
    lo = __float2bfloat16(v - __bfloat162float(hi));
}

// ---------------- packing kernels ----------------
__global__ void split_x(const float* __restrict__ x,
                        __nv_bfloat16* __restrict__ hi, __nv_bfloat16* __restrict__ lo, int n) {
    int i = blockIdx.x * blockDim.x + threadIdx.x;
    if (i >= n) return;
    split2(x[i], hi[i], lo[i]);
}

__global__ void pack_qkv(const float* __restrict__ Wq, const float* __restrict__ Wk,
                         const float* __restrict__ Wv,
                         __nv_bfloat16* __restrict__ hi, __nv_bfloat16* __restrict__ lo) {
    int idx = blockIdx.x * blockDim.x + threadIdx.x;
    if (idx >= QKVN * EMB) return;
    int n = idx >> 10, k = idx & 1023;
    int wh = n >> 10, hid = (n >> 6) & 15, i = n & 63;
    const float* src = (wh == 0) ? Wq : (wh == 1) ? Wk : Wv;
    float v = src[(size_t)hid * (EMB * HDIM) + (size_t)k * HDIM + i];
    if (wh == 0) v *= QSCALE;
    split2(v, hi[idx], lo[idx]);
}

__global__ void pack_wo(const float* __restrict__ Wo,
                        __nv_bfloat16* __restrict__ hi, __nv_bfloat16* __restrict__ lo) {
    int idx = blockIdx.x * blockDim.x + threadIdx.x;
    if (idx >= EMB * EMB) return;
    split2(Wo[idx], hi[idx], lo[idx]);
}

// ---------------- GEMM: C[M,N] = A[M,K] * B[N,K]^T, bf16 3-pass split, mma.sync ----------------
// 256 thr (8 warps 4x2), tile 128x128, BK=32, 2-stage cp.async, 2 CTAs/SM.
template<int MODE>
__global__ __launch_bounds__(256, 2)
void gemm_mma(const __nv_bfloat16* __restrict__ Ah, const __nv_bfloat16* __restrict__ Al,
              const __nv_bfloat16* __restrict__ Bh, const __nv_bfloat16* __restrict__ Bl,
              float* __restrict__ C, __nv_bfloat16* __restrict__ Ch,
              __nv_bfloat16* __restrict__ Cl, int N) {
    extern __shared__ __align__(16) char smraw[];
    uint32_t smb = cvta_smem(smraw);
    const int tid = threadIdx.x, lane = tid & 31, wid = tid >> 5;
    const int wm = wid & 3, wn = wid >> 2;
    const int nb = blockIdx.x, mb = blockIdx.y;

    const __nv_bfloat16* gsrc[4] = {
        Ah + (size_t)mb * 128 * KDIM, Al + (size_t)mb * 128 * KDIM,
        Bh + (size_t)nb * 128 * KDIM, Bl + (size_t)nb * 128 * KDIM };

    auto ldchunk = [&](int buf, int ck) {
        uint32_t bb = smb + buf * 40960;
#pragma unroll
        for (int q = 0; q < 8; q++) {
            int i = q * 256 + tid;          // 0..2047
            int t = i >> 9;
            int r = (i >> 2) & 127;
            int sg = i & 3;
            cp16(bb + t * 10240 + r * 80 + sg * 16,
                 gsrc[t] + (size_t)r * KDIM + ck * 32 + sg * 8);
        }
    };

    ldchunk(0, 0); CP_COMMIT();
    ldchunk(1, 1); CP_COMMIT();

    float acc[2][8][4];
#pragma unroll
    for (int a = 0; a < 2; a++)
#pragma unroll
        for (int b = 0; b < 8; b++)
#pragma unroll
            for (int c = 0; c < 4; c++) acc[a][b][c] = 0.f;

    for (int c = 0; c < 32; c++) {
        if (c < 31) CP_WAIT1(); else CP_WAIT0();
        __syncthreads();
        uint32_t bb = smb + (c & 1) * 40960;

#pragma unroll
        for (int s = 0; s < 2; s++) {
            uint32_t ah[2][4], al[2][4];
#pragma unroll
            for (int mt = 0; mt < 2; mt++) {
                uint32_t row = 32 * wm + 16 * mt + ((lane >> 3) & 1) * 8 + (lane & 7);
                uint32_t kb  = (lane >> 4) * 16 + s * 32;
                uint32_t ad  = bb + row * 80 + kb;
                ldsm4(ah[mt][0], ah[mt][1], ah[mt][2], ah[mt][3], ad);
                ldsm4(al[mt][0], al[mt][1], al[mt][2], al[mt][3], ad + 10240);
            }
#pragma unroll
            for (int np = 0; np < 4; np++) {
                uint32_t row = 64 * wn + 16 * np + ((lane >> 4) & 1) * 8 + (lane & 7);
                uint32_t kb  = ((lane >> 3) & 1) * 16 + s * 32;
                uint32_t bd  = bb + 20480 + row * 80 + kb;
                uint32_t bh0, bh1, bh2, bh3, bl0, bl1, bl2, bl3;
                ldsm4(bh0, bh1, bh2, bh3, bd);
                ldsm4(bl0, bl1, bl2, bl3, bd + 10240);
#pragma unroll
                for (int mt = 0; mt < 2; mt++) {
                    mma_bf(acc[mt][2 * np],     ah[mt], bh0, bh1);
                    mma_bf(acc[mt][2 * np],     al[mt], bh0, bh1);
                    mma_bf(acc[mt][2 * np],     ah[mt], bl0, bl1);
                    mma_bf(acc[mt][2 * np + 1], ah[mt], bh2, bh3);
                    mma_bf(acc[mt][2 * np + 1], al[mt], bh2, bh3);
                    mma_bf(acc[mt][2 * np + 1], ah[mt], bl2, bl3);
                }
            }
        }
        __syncthreads();
        if (c + 2 < 32) { ldchunk(c & 1, c + 2); CP_COMMIT(); }
    }

    const int grp = lane >> 2, qr = lane & 3;
#pragma unroll
    for (int mt = 0; mt < 2; mt++) {
        size_t r0 = (size_t)mb * 128 + 32 * wm + 16 * mt + grp;
#pragma unroll
        for (int nt = 0; nt < 8; nt++) {
            int col = nb * 128 + 64 * wn + 8 * nt + 2 * qr;
            float* c4 = acc[mt][nt];
            if (MODE == 0) {
                *(float2*)&C[r0 * N + col]       = make_float2(c4[0], c4[1]);
                *(float2*)&C[(r0 + 8) * N + col] = make_float2(c4[2], c4[3]);
            } else {
                uint32_t h0 = packbf(c4[0], c4[1]), l0 = packres(c4[0], c4[1], h0);
                uint32_t h1 = packbf(c4[2], c4[3]), l1 = packres(c4[2], c4[3], h1);
                *(uint32_t*)&Ch[r0 * N + col]       = h0;
                *(uint32_t*)&Cl[r0 * N + col]       = l0;
                *(uint32_t*)&Ch[(r0 + 8) * N + col] = h1;
                *(uint32_t*)&Cl[(r0 + 8) * N + col] = l1;
            }
        }
    }
}

// ---------------- Flash attention via mma.sync ----------------
// CTA = (qtile 128 rows, head, batch), 256 thr / 8 warps, warp owns 16 rows.
// K/V tiles of 64 keys double-buffered (pitch 72 bf16 = 144B) -> 72KB smem, 2 CTAs/SM.
#define FPITCH 144          /* bytes per smem row */
#define FTILE  9216         /* 64*144 */
#define FSTAGE 36864        /* 4 tensors */
#define NKT    (SEQ/64)     /* 32 key tiles */

__global__ __launch_bounds__(256, 2)
void flash_mma(const __nv_bfloat16* __restrict__ Qh, const __nv_bfloat16* __restrict__ Ql,
               __nv_bfloat16* __restrict__ Oh, __nv_bfloat16* __restrict__ Ol) {
    extern __shared__ __align__(16) char smraw[];
    uint32_t smb = cvta_smem(smraw);

    const int tid = threadIdx.x, lane = tid & 31, w = tid >> 5;
    const int grp = lane >> 2, qr = lane & 3;
    const int qt = blockIdx.x, h = blockIdx.y, b = blockIdx.z;

    const size_t batch_row = (size_t)b * SEQ;

    const __nv_bfloat16* kvsrc[4] = {
        Qh + batch_row * QKVN + EMB + h * HDIM,          // Kh
        Ql + batch_row * QKVN + EMB + h * HDIM,          // Kl
        Qh + batch_row * QKVN + 2 * EMB + h * HDIM,      // Vh
        Ql + batch_row * QKVN + 2 * EMB + h * HDIM };    // Vl

    auto ldtile = [&](int buf, int kt) {
        uint32_t bb = smb + buf * FSTAGE;
        size_t rbase = (size_t)kt * 64;
#pragma unroll
        for (int q = 0; q < 8; q++) {
            int i = q * 256 + tid;          // 0..2047
            int t = i >> 9;                 // tensor
            int r = (i >> 3) & 63;          // key row
            int sg = i & 7;                 // 16B segment
            cp16(bb + t * FTILE + r * FPITCH + sg * 16,
                 kvsrc[t] + (rbase + r) * QKVN + sg * 8);
        }
    };

    // ---- Q fragments (pre-scaled by 1/sqrt(SEQ) in pack) ----
    uint32_t qh[4][4], ql[4][4];
    {
        size_t r0 = batch_row + (size_t)qt * 128 + w * 16 + grp;
        const __nv_bfloat16* qb_h = Qh + r0 * QKVN + h * HDIM;
        const __nv_bfloat16* qb_l = Ql + r0 * QKVN + h * HDIM;
#pragma unroll
        for (int t = 0; t < 4; t++) {
            int c0 = t * 16 + 2 * qr;
            qh[t][0] = *(const uint32_t*)(qb_h + c0);
            qh[t][1] = *(const uint32_t*)(qb_h + 8 * QKVN + c0);
            qh[t][2] = *(const uint32_t*)(qb_h + c0 + 8);
            qh[t][3] = *(const uint32_t*)(qb_h + 8 * QKVN + c0 + 8);
            ql[t][0] = *(const uint32_t*)(qb_l + c0);
            ql[t][1] = *(const uint32_t*)(qb_l + 8 * QKVN + c0);
            ql[t][2] = *(const uint32_t*)(qb_l + c0 + 8);
            ql[t][3] = *(const uint32_t*)(qb_l + 8 * QKVN + c0 + 8);
        }
    }

    float o[8][4];
#pragma unroll
    for (int j = 0; j < 8; j++)
#pragma unroll
        for (int c = 0; c < 4; c++) o[j][c] = 0.f;
    float m0 = -1e30f, m1 = -1e30f, l0 = 0.f, l1 = 0.f;

    ldtile(0, 0); CP_COMMIT();
    ldtile(1, 1); CP_COMMIT();

    for (int kt = 0; kt < NKT; kt++) {
        if (kt < NKT - 1) CP_WAIT1(); else CP_WAIT0();
        __syncthreads();
        uint32_t sb  = smb + (kt & 1) * FSTAGE;
        uint32_t khb = sb, klb = sb + FTILE, vhb = sb + 2 * FTILE, vlb = sb + 3 * FTILE;

        // ---- S = Q K^T (16 x 64 per warp), 3-pass split ----
        float s[8][4];
#pragma unroll
        for (int j = 0; j < 8; j++) {
            uint32_t ka = khb + (8 * j + (lane & 7)) * FPITCH + (lane >> 3) * 16;
            uint32_t la = ka + FTILE;
            uint32_t h0, h1, h2, h3, h4, h5, h6, h7;
            uint32_t e0, e1, e2, e3, e4, e5, e6, e7;
            ldsm4(h0, h1, h2, h3, ka);
            ldsm4(h4, h5, h6, h7, ka + 64);
            ldsm4(e0, e1, e2, e3, la);
            ldsm4(e4, e5, e6, e7, la + 64);
            s[j][0] = s[j][1] = s[j][2] = s[j][3] = 0.f;
            mma_bf(s[j], qh[0], h0, h1); mma_bf(s[j], ql[0], h0, h1); mma_bf(s[j], qh[0], e0, e1);
            mma_bf(s[j], qh[1], h2, h3); mma_bf(s[j], ql[1], h2, h3); mma_bf(s[j], qh[1], e2, e3);
            mma_bf(s[j], qh[2], h4, h5); mma_bf(s[j], ql[2], h4, h5); mma_bf(s[j], qh[2], e4, e5);
            mma_bf(s[j], qh[3], h6, h7); mma_bf(s[j], ql[3], h6, h7); mma_bf(s[j], qh[3], e6, e7);
        }

        // ---- online softmax (rows grp, grp+8) ----
        float n0 = m0, n1 = m1;
#pragma unroll
        for (int j = 0; j < 8; j++) {
            n0 = fmaxf(n0, fmaxf(s[j][0], s[j][1]));
            n1 = fmaxf(n1, fmaxf(s[j][2], s[j][3]));
        }
        n0 = fmaxf(n0, __shfl_xor_sync(0xffffffffu, n0, 1));
        n0 = fmaxf(n0, __shfl_xor_sync(0xffffffffu, n0, 2));
        n1 = fmaxf(n1, __shfl_xor_sync(0xffffffffu, n1, 1));
        n1 = fmaxf(n1, __shfl_xor_sync(0xffffffffu, n1, 2));
        float a0 = __expf(m0 - n0), a1 = __expf(m1 - n1);
        m0 = n0; m1 = n1;
        float rs0 = 0.f, rs1 = 0.f;
#pragma unroll
        for (int j = 0; j < 8; j++) {
            s[j][0] = __expf(s[j][0] - n0); rs0 += s[j][0];
            s[j][1] = __expf(s[j][1] - n0); rs0 += s[j][1];
            s[j][2] = __expf(s[j][2] - n1); rs1 += s[j][2];
            s[j][3] = __expf(s[j][3] - n1); rs1 += s[j][3];
        }
        rs0 += __shfl_xor_sync(0xffffffffu, rs0, 1);
        rs0 += __shfl_xor_sync(0xffffffffu, rs0, 2);
        rs1 += __shfl_xor_sync(0xffffffffu, rs1, 1);
        rs1 += __shfl_xor_sync(0xffffffffu, rs1, 2);
        l0 = l0 * a0 + rs0;
        l1 = l1 * a1 + rs1;
#pragma unroll
        for (int j = 0; j < 8; j++) {
            o[j][0] *= a0; o[j][1] *= a0; o[j][2] *= a1; o[j][3] *= a1;
        }

        // ---- O += P V, P split in regs, 3-pass ----
#pragma unroll
        for (int kcp = 0; kcp < 2; kcp++) {
            uint32_t ph[2][4], pl[2][4];
#pragma unroll
            for (int u = 0; u < 2; u++) {
                int nt = 4 * kcp + 2 * u;
                ph[u][0] = packbf(s[nt][0], s[nt][1]);     pl[u][0] = packres(s[nt][0], s[nt][1], ph[u][0]);
                ph[u][1] = packbf(s[nt][2], s[nt][3]);     pl[u][1] = packres(s[nt][2], s[nt][3], ph[u][1]);
                ph[u][2] = packbf(s[nt+1][0], s[nt+1][1]); pl[u][2] = packres(s[nt+1][0], s[nt+1][1], ph[u][2]);
                ph[u][3] = packbf(s[nt+1][2], s[nt+1][3]); pl[u][3] = packres(s[nt+1][2], s[nt+1][3], ph[u][3]);
            }
#pragma unroll
            for (int j2 = 0; j2 < 8; j2++) {
                uint32_t va = vhb + (32 * kcp + lane) * FPITCH + j2 * 16;
                uint32_t v0, v1, v2, v3, u0, u1, u2, u3;
                ldsm4t(v0, v1, v2, v3, va);
                ldsm4t(u0, u1, u2, u3, va + FTILE);
                mma_bf(o[j2], ph[0], v0, v1);
                mma_bf(o[j2], pl[0], v0, v1);
                mma_bf(o[j2], ph[0], u0, u1);
                mma_bf(o[j2], ph[1], v2, v3);
                mma_bf(o[j2], pl[1], v2, v3);
                mma_bf(o[j2], ph[1], u2, u3);
            }
        }

        __syncthreads();
        if (kt + 2 < NKT) { ldtile(kt & 1, kt + 2); CP_COMMIT(); }
    }

    // ---- epilogue: normalize, split bf16, store ----
    float inv0 = 1.f / l0, inv1 = 1.f / l1;
    size_t r0 = batch_row + (size_t)qt * 128 + w * 16 + grp;
#pragma unroll
    for (int j2 = 0; j2 < 8; j2++) {
        int c = h * HDIM + 8 * j2 + 2 * qr;
        float x0 = o[j2][0] * inv0, x1 = o[j2][1] * inv0;
        float x2 = o[j2][2] * inv1, x3 = o[j2][3] * inv1;
        uint32_t h0 = packbf(x0, x1), lo0 = packres(x0, x1, h0);
        uint32_t h1 = packbf(x2, x3), lo1 = packres(x2, x3, h1);
        *(uint32_t*)&Oh[r0 * EMB + c]       = h0;
        *(uint32_t*)&Ol[r0 * EMB + c]       = lo0;
        *(uint32_t*)&Oh[(r0 + 8) * EMB + c] = h1;
        *(uint32_t*)&Ol[(r0 + 8) * EMB + c] = lo1;
    }
}

// ------------------------------------------------------------------
extern "C" void kernel_launch(void* const* d_in, const int* in_sizes, int n_in,
                              void* d_out, int out_size) {
    const float* x  = (const float*)d_in[0];
    const float* Wq = (const float*)d_in[1];
    const float* Wk = (const float*)d_in[2];
    const float* Wv = (const float*)d_in[3];
    const float* Wo = (const float*)d_in[4];
    float* out = (float*)d_out;

    __nv_bfloat16 *gxh, *gxl, *gBqh, *gBql, *gBoh, *gBol, *gQh, *gQl, *gAh, *gAl;
    cudaGetSymbolAddress((void**)&gxh,  g_xh);
    cudaGetSymbolAddress((void**)&gxl,  g_xl);
    cudaGetSymbolAddress((void**)&gBqh, g_Bqh);
    cudaGetSymbolAddress((void**)&gBql, g_Bql);
    cudaGetSymbolAddress((void**)&gBoh, g_Boh);
    cudaGetSymbolAddress((void**)&gBol, g_Bol);
    cudaGetSymbolAddress((void**)&gQh,  g_QKVh);
    cudaGetSymbolAddress((void**)&gQl,  g_QKVl);
    cudaGetSymbolAddress((void**)&gAh,  g_Ah);
    cudaGetSymbolAddress((void**)&gAl,  g_Al);

    const int GSMEM = 2 * 40960;
    const int FSMEM = 2 * FSTAGE;
    cudaFuncSetAttribute(gemm_mma<0>, cudaFuncAttributeMaxDynamicSharedMemorySize, GSMEM);
    cudaFuncSetAttribute(gemm_mma<1>, cudaFuncAttributeMaxDynamicSharedMemorySize, GSMEM);
    cudaFuncSetAttribute(flash_mma,   cudaFuncAttributeMaxDynamicSharedMemorySize, FSMEM);

    split_x<<<(MROWS * EMB + 255) / 256, 256>>>(x, gxh, gxl, MROWS * EMB);
    pack_qkv<<<(QKVN * EMB + 255) / 256, 256>>>(Wq, Wk, Wv, gBqh, gBql);
    pack_wo<<<(EMB * EMB + 255) / 256, 256>>>(Wo, gBoh, gBol);

    // QKV projection -> bf16 hi/lo QKV
    gemm_mma<1><<<dim3(QKVN / 128, MROWS / 128), 256, GSMEM>>>(
        gxh, gxl, gBqh, gBql, nullptr, gQh, gQl, QKVN);

    // attention
    flash_mma<<<dim3(SEQ / 128, HEADS, BATCH), 256, FSMEM>>>(gQh, gQl, gAh, gAl);

    // output projection -> fp32 out
    gemm_mma<0><<<dim3(EMB / 128, MROWS / 128), 256, GSMEM>>>(
        gAh, gAl, gBoh, gBol, out, nullptr, nullptr, EMB);
}

// round 5
// speedup vs baseline: 3.0356x; 1.0004x over previous
#include <cuda_runtime.h>
#include <cuda_bf16.h>
#include <stdint.h>
#include <math.h>

#define BATCH 2
#define SEQ   2048
#define EMB   1024
#define HEADS 16
#define HDIM  64
#define MROWS (BATCH*SEQ)   /* 4096 */
#define QKVN  (3*EMB)       /* 3072 */
#define KDIM  EMB

#define QSCALE 0.02209708691207961f   /* 1/sqrt(2048) */

// ---------------- scratch (device globals; allocation-free) ----------------
__device__ __align__(256) __nv_bfloat16 g_xh [(size_t)MROWS*EMB];
__device__ __align__(256) __nv_bfloat16 g_xl [(size_t)MROWS*EMB];
__device__ __align__(256) __nv_bfloat16 g_Bqh[(size_t)QKVN*EMB];
__device__ __align__(256) __nv_bfloat16 g_Bql[(size_t)QKVN*EMB];
__device__ __align__(256) __nv_bfloat16 g_Boh[(size_t)EMB*EMB];
__device__ __align__(256) __nv_bfloat16 g_Bol[(size_t)EMB*EMB];
__device__ __align__(256) __nv_bfloat16 g_QKVh[(size_t)MROWS*QKVN];
__device__ __align__(256) __nv_bfloat16 g_QKVl[(size_t)MROWS*QKVN];
__device__ __align__(256) __nv_bfloat16 g_Ah [(size_t)MROWS*EMB];
__device__ __align__(256) __nv_bfloat16 g_Al [(size_t)MROWS*EMB];

// ---------------- helpers ----------------
__device__ __forceinline__ uint32_t cvta_smem(const void* p) {
    uint32_t a;
    asm("{ .reg .u64 t; cvta.to.shared.u64 t, %1; cvt.u32.u64 %0, t; }" : "=r"(a) : "l"(p));
    return a;
}
__device__ __forceinline__ void cp16(uint32_t dst, const void* src) {
    asm volatile("cp.async.cg.shared.global [%0], [%1], 16;" :: "r"(dst), "l"(src));
}
#define CP_COMMIT() asm volatile("cp.async.commit_group;" ::: "memory")
#define CP_WAIT1()  asm volatile("cp.async.wait_group 1;" ::: "memory")
#define CP_WAIT0()  asm volatile("cp.async.wait_group 0;" ::: "memory")

__device__ __forceinline__ void ldsm4(uint32_t& r0, uint32_t& r1, uint32_t& r2, uint32_t& r3,
                                      uint32_t addr) {
    asm volatile("ldmatrix.sync.aligned.m8n8.x4.shared.b16 {%0,%1,%2,%3},[%4];"
                 : "=r"(r0), "=r"(r1), "=r"(r2), "=r"(r3) : "r"(addr));
}
__device__ __forceinline__ void ldsm4t(uint32_t& r0, uint32_t& r1, uint32_t& r2, uint32_t& r3,
                                       uint32_t addr) {
    asm volatile("ldmatrix.sync.aligned.m8n8.x4.trans.shared.b16 {%0,%1,%2,%3},[%4];"
                 : "=r"(r0), "=r"(r1), "=r"(r2), "=r"(r3) : "r"(addr));
}
// NOTE: non-volatile — register-only dataflow; lets ptxas interleave HMMA chains.
__device__ __forceinline__ void mma_bf(float c[4], const uint32_t a[4], uint32_t b0, uint32_t b1) {
    asm("mma.sync.aligned.m16n8k16.row.col.f32.bf16.bf16.f32 "
        "{%0,%1,%2,%3}, {%4,%5,%6,%7}, {%8,%9}, {%0,%1,%2,%3};"
        : "+f"(c[0]), "+f"(c[1]), "+f"(c[2]), "+f"(c[3])
        : "r"(a[0]), "r"(a[1]), "r"(a[2]), "r"(a[3]), "r"(b0), "r"(b1));
}

__device__ __forceinline__ uint32_t packbf(float x, float y) {
    __nv_bfloat162 t = __floats2bfloat162_rn(x, y);
    return *reinterpret_cast<uint32_t*>(&t);
}
__device__ __forceinline__ uint32_t packres(float x, float y, uint32_t h) {
    __nv_bfloat162 hh = *reinterpret_cast<__nv_bfloat162*>(&h);
    return packbf(x - __bfloat162float(hh.x), y - __bfloat162float(hh.y));
}
__device__ __forceinline__ void split2(float v, __nv_bfloat16& hi, __nv_bfloat16& lo) {
    hi = __float2bfloat16(v);
    lo = __float2bfloat16(v - __bfloat162float(hi));
}

// ---------------- packing kernels ----------------
__global__ void split_x(const float* __restrict__ x,
                        __nv_bfloat16* __restrict__ hi, __nv_bfloat16* __restrict__ lo, int n) {
    int i = blockIdx.x * blockDim.x + threadIdx.x;
    if (i >= n) return;
    split2(x[i], hi[i], lo[i]);
}

__global__ void pack_qkv(const float* __restrict__ Wq, const float* __restrict__ Wk,
                         const float* __restrict__ Wv,
                         __nv_bfloat16* __restrict__ hi, __nv_bfloat16* __restrict__ lo) {
    int idx = blockIdx.x * blockDim.x + threadIdx.x;
    if (idx >= QKVN * EMB) return;
    int n = idx >> 10, k = idx & 1023;
    int wh = n >> 10, hid = (n >> 6) & 15, i = n & 63;
    const float* src = (wh == 0) ? Wq : (wh == 1) ? Wk : Wv;
    float v = src[(size_t)hid * (EMB * HDIM) + (size_t)k * HDIM + i];
    if (wh == 0) v *= QSCALE;
    split2(v, hi[idx], lo[idx]);
}

__global__ void pack_wo(const float* __restrict__ Wo,
                        __nv_bfloat16* __restrict__ hi, __nv_bfloat16* __restrict__ lo) {
    int idx = blockIdx.x * blockDim.x + threadIdx.x;
    if (idx >= EMB * EMB) return;
    split2(Wo[idx], hi[idx], lo[idx]);
}

// ---------------- GEMM: C[M,N] = A[M,K] * B[N,K]^T, bf16 3-pass split, mma.sync ----------------
// 256 thr (8 warps 4x2), tile 128x128, BK=32, 2-stage cp.async, 2 CTAs/SM.
template<int MODE>
__global__ __launch_bounds__(256, 2)
void gemm_mma(const __nv_bfloat16* __restrict__ Ah, const __nv_bfloat16* __restrict__ Al,
              const __nv_bfloat16* __restrict__ Bh, const __nv_bfloat16* __restrict__ Bl,
              float* __restrict__ C, __nv_bfloat16* __restrict__ Ch,
              __nv_bfloat16* __restrict__ Cl, int N) {
    extern __shared__ __align__(16) char smraw[];
    uint32_t smb = cvta_smem(smraw);
    const int tid = threadIdx.x, lane = tid & 31, wid = tid >> 5;
    const int wm = wid & 3, wn = wid >> 2;
    const int nb = blockIdx.x, mb = blockIdx.y;

    const __nv_bfloat16* gsrc[4] = {
        Ah + (size_t)mb * 128 * KDIM, Al + (size_t)mb * 128 * KDIM,
        Bh + (size_t)nb * 128 * KDIM, Bl + (size_t)nb * 128 * KDIM };

    auto ldchunk = [&](int buf, int ck) {
        uint32_t bb = smb + buf * 40960;
#pragma unroll
        for (int q = 0; q < 8; q++) {
            int i = q * 256 + tid;          // 0..2047
            int t = i >> 9;
            int r = (i >> 2) & 127;
            int sg = i & 3;
            cp16(bb + t * 10240 + r * 80 + sg * 16,
                 gsrc[t] + (size_t)r * KDIM + ck * 32 + sg * 8);
        }
    };

    ldchunk(0, 0); CP_COMMIT();
    ldchunk(1, 1); CP_COMMIT();

    float acc[2][8][4];
#pragma unroll
    for (int a = 0; a < 2; a++)
#pragma unroll
        for (int b = 0; b < 8; b++)
#pragma unroll
            for (int c = 0; c < 4; c++) acc[a][b][c] = 0.f;

    for (int c = 0; c < 32; c++) {
        if (c < 31) CP_WAIT1(); else CP_WAIT0();
        __syncthreads();
        uint32_t bb = smb + (c & 1) * 40960;

#pragma unroll
        for (int s = 0; s < 2; s++) {
            uint32_t ah[2][4], al[2][4];
#pragma unroll
            for (int mt = 0; mt < 2; mt++) {
                uint32_t row = 32 * wm + 16 * mt + ((lane >> 3) & 1) * 8 + (lane & 7);
                uint32_t kb  = (lane >> 4) * 16 + s * 32;
                uint32_t ad  = bb + row * 80 + kb;
                ldsm4(ah[mt][0], ah[mt][1], ah[mt][2], ah[mt][3], ad);
                ldsm4(al[mt][0], al[mt][1], al[mt][2], al[mt][3], ad + 10240);
            }
#pragma unroll
            for (int np = 0; np < 4; np++) {
                uint32_t row = 64 * wn + 16 * np + ((lane >> 4) & 1) * 8 + (lane & 7);
                uint32_t kb  = ((lane >> 3) & 1) * 16 + s * 32;
                uint32_t bd  = bb + 20480 + row * 80 + kb;
                uint32_t bh0, bh1, bh2, bh3, bl0, bl1, bl2, bl3;
                ldsm4(bh0, bh1, bh2, bh3, bd);
                ldsm4(bl0, bl1, bl2, bl3, bd + 10240);
                // pass-outer, accumulator-inner: dependent-chain distance = 4
#pragma unroll
                for (int p = 0; p < 3; p++) {
                    const uint32_t* a0 = (p == 1) ? al[0] : ah[0];
                    const uint32_t* a1 = (p == 1) ? al[1] : ah[1];
                    uint32_t c0 = (p == 2) ? bl0 : bh0, c1 = (p == 2) ? bl1 : bh1;
                    uint32_t c2 = (p == 2) ? bl2 : bh2, c3 = (p == 2) ? bl3 : bh3;
                    mma_bf(acc[0][2 * np],     a0, c0, c1);
                    mma_bf(acc[1][2 * np],     a1, c0, c1);
                    mma_bf(acc[0][2 * np + 1], a0, c2, c3);
                    mma_bf(acc[1][2 * np + 1], a1, c2, c3);
                }
            }
        }
        __syncthreads();
        if (c + 2 < 32) { ldchunk(c & 1, c + 2); CP_COMMIT(); }
    }

    const int grp = lane >> 2, qr = lane & 3;
#pragma unroll
    for (int mt = 0; mt < 2; mt++) {
        size_t r0 = (size_t)mb * 128 + 32 * wm + 16 * mt + grp;
#pragma unroll
        for (int nt = 0; nt < 8; nt++) {
            int col = nb * 128 + 64 * wn + 8 * nt + 2 * qr;
            float* c4 = acc[mt][nt];
            if (MODE == 0) {
                *(float2*)&C[r0 * N + col]       = make_float2(c4[0], c4[1]);
                *(float2*)&C[(r0 + 8) * N + col] = make_float2(c4[2], c4[3]);
            } else {
                uint32_t h0 = packbf(c4[0], c4[1]), l0 = packres(c4[0], c4[1], h0);
                uint32_t h1 = packbf(c4[2], c4[3]), l1 = packres(c4[2], c4[3], h1);
                *(uint32_t*)&Ch[r0 * N + col]       = h0;
                *(uint32_t*)&Cl[r0 * N + col]       = l0;
                *(uint32_t*)&Ch[(r0 + 8) * N + col] = h1;
                *(uint32_t*)&Cl[(r0 + 8) * N + col] = l1;
            }
        }
    }
}

// ---------------- Flash attention via mma.sync ----------------
#define FPITCH 144          /* bytes per smem row */
#define FTILE  9216         /* 64*144 */
#define FSTAGE 36864        /* 4 tensors */
#define NKT    (SEQ/64)     /* 32 key tiles */

__global__ __launch_bounds__(256, 2)
void flash_mma(const __nv_bfloat16* __restrict__ Qh, const __nv_bfloat16* __restrict__ Ql,
               __nv_bfloat16* __restrict__ Oh, __nv_bfloat16* __restrict__ Ol) {
    extern __shared__ __align__(16) char smraw[];
    uint32_t smb = cvta_smem(smraw);

    const int tid = threadIdx.x, lane = tid & 31, w = tid >> 5;
    const int grp = lane >> 2, qr = lane & 3;
    const int qt = blockIdx.x, h = blockIdx.y, b = blockIdx.z;

    const size_t batch_row = (size_t)b * SEQ;

    const __nv_bfloat16* kvsrc[4] = {
        Qh + batch_row * QKVN + EMB + h * HDIM,          // Kh
        Ql + batch_row * QKVN + EMB + h * HDIM,          // Kl
        Qh + batch_row * QKVN + 2 * EMB + h * HDIM,      // Vh
        Ql + batch_row * QKVN + 2 * EMB + h * HDIM };    // Vl

    auto ldtile = [&](int buf, int kt) {
        uint32_t bb = smb + buf * FSTAGE;
        size_t rbase = (size_t)kt * 64;
#pragma unroll
        for (int q = 0; q < 8; q++) {
            int i = q * 256 + tid;
            int t = i >> 9;
            int r = (i >> 3) & 63;
            int sg = i & 7;
            cp16(bb + t * FTILE + r * FPITCH + sg * 16,
                 kvsrc[t] + (rbase + r) * QKVN + sg * 8);
        }
    };

    uint32_t qh[4][4], ql[4][4];
    {
        size_t r0 = batch_row + (size_t)qt * 128 + w * 16 + grp;
        const __nv_bfloat16* qb_h = Qh + r0 * QKVN + h * HDIM;
        const __nv_bfloat16* qb_l = Ql + r0 * QKVN + h * HDIM;
#pragma unroll
        for (int t = 0; t < 4; t++) {
            int c0 = t * 16 + 2 * qr;
            qh[t][0] = *(const uint32_t*)(qb_h + c0);
            qh[t][1] = *(const uint32_t*)(qb_h + 8 * QKVN + c0);
            qh[t][2] = *(const uint32_t*)(qb_h + c0 + 8);
            qh[t][3] = *(const uint32_t*)(qb_h + 8 * QKVN + c0 + 8);
            ql[t][0] = *(const uint32_t*)(qb_l + c0);
            ql[t][1] = *(const uint32_t*)(qb_l + 8 * QKVN + c0);
            ql[t][2] = *(const uint32_t*)(qb_l + c0 + 8);
            ql[t][3] = *(const uint32_t*)(qb_l + 8 * QKVN + c0 + 8);
        }
    }

    float o[8][4];
#pragma unroll
    for (int j = 0; j < 8; j++)
#pragma unroll
        for (int c = 0; c < 4; c++) o[j][c] = 0.f;
    float m0 = -1e30f, m1 = -1e30f, l0 = 0.f, l1 = 0.f;

    ldtile(0, 0); CP_COMMIT();
    ldtile(1, 1); CP_COMMIT();

    for (int kt = 0; kt < NKT; kt++) {
        if (kt < NKT - 1) CP_WAIT1(); else CP_WAIT0();
        __syncthreads();
        uint32_t sb  = smb + (kt & 1) * FSTAGE;
        uint32_t khb = sb, vhb = sb + 2 * FTILE;

        // ---- S = Q K^T (16 x 64 per warp), 3-pass split ----
        float s[8][4];
#pragma unroll
        for (int j = 0; j < 8; j++) {
            uint32_t ka = khb + (8 * j + (lane & 7)) * FPITCH + (lane >> 3) * 16;
            uint32_t la = ka + FTILE;
            uint32_t h0, h1, h2, h3, h4, h5, h6, h7;
            uint32_t e0, e1, e2, e3, e4, e5, e6, e7;
            ldsm4(h0, h1, h2, h3, ka);
            ldsm4(h4, h5, h6, h7, ka + 64);
            ldsm4(e0, e1, e2, e3, la);
            ldsm4(e4, e5, e6, e7, la + 64);
            s[j][0] = s[j][1] = s[j][2] = s[j][3] = 0.f;
            mma_bf(s[j], qh[0], h0, h1); mma_bf(s[j], ql[0], h0, h1); mma_bf(s[j], qh[0], e0, e1);
            mma_bf(s[j], qh[1], h2, h3); mma_bf(s[j], ql[1], h2, h3); mma_bf(s[j], qh[1], e2, e3);
            mma_bf(s[j], qh[2], h4, h5); mma_bf(s[j], ql[2], h4, h5); mma_bf(s[j], qh[2], e4, e5);
            mma_bf(s[j], qh[3], h6, h7); mma_bf(s[j], ql[3], h6, h7); mma_bf(s[j], qh[3], e6, e7);
        }

        // ---- online softmax (rows grp, grp+8) ----
        float n0 = m0, n1 = m1;
#pragma unroll
        for (int j = 0; j < 8; j++) {
            n0 = fmaxf(n0, fmaxf(s[j][0], s[j][1]));
            n1 = fmaxf(n1, fmaxf(s[j][2], s[j][3]));
        }
        n0 = fmaxf(n0, __shfl_xor_sync(0xffffffffu, n0, 1));
        n0 = fmaxf(n0, __shfl_xor_sync(0xffffffffu, n0, 2));
        n1 = fmaxf(n1, __shfl_xor_sync(0xffffffffu, n1, 1));
        n1 = fmaxf(n1, __shfl_xor_sync(0xffffffffu, n1, 2));
        float a0 = __expf(m0 - n0), a1 = __expf(m1 - n1);
        m0 = n0; m1 = n1;
        float rs0 = 0.f, rs1 = 0.f;
#pragma unroll
        for (int j = 0; j < 8; j++) {
            s[j][0] = __expf(s[j][0] - n0); rs0 += s[j][0];
            s[j][1] = __expf(s[j][1] - n0); rs0 += s[j][1];
            s[j][2] = __expf(s[j][2] - n1); rs1 += s[j][2];
            s[j][3] = __expf(s[j][3] - n1); rs1 += s[j][3];
        }
        rs0 += __shfl_xor_sync(0xffffffffu, rs0, 1);
        rs0 += __shfl_xor_sync(0xffffffffu, rs0, 2);
        rs1 += __shfl_xor_sync(0xffffffffu, rs1, 1);
        rs1 += __shfl_xor_sync(0xffffffffu, rs1, 2);
        l0 = l0 * a0 + rs0;
        l1 = l1 * a1 + rs1;
#pragma unroll
        for (int j = 0; j < 8; j++) {
            o[j][0] *= a0; o[j][1] *= a0; o[j][2] *= a1; o[j][3] *= a1;
        }

        // ---- O += P V, P split in regs, 3-pass ----
#pragma unroll
        for (int kcp = 0; kcp < 2; kcp++) {
            uint32_t ph[2][4], pl[2][4];
#pragma unroll
            for (int u = 0; u < 2; u++) {
                int nt = 4 * kcp + 2 * u;
                ph[u][0] = packbf(s[nt][0], s[nt][1]);     pl[u][0] = packres(s[nt][0], s[nt][1], ph[u][0]);
                ph[u][1] = packbf(s[nt][2], s[nt][3]);     pl[u][1] = packres(s[nt][2], s[nt][3], ph[u][1]);
                ph[u][2] = packbf(s[nt+1][0], s[nt+1][1]); pl[u][2] = packres(s[nt+1][0], s[nt+1][1], ph[u][2]);
                ph[u][3] = packbf(s[nt+1][2], s[nt+1][3]); pl[u][3] = packres(s[nt+1][2], s[nt+1][3], ph[u][3]);
            }
#pragma unroll
            for (int j2 = 0; j2 < 8; j2++) {
                uint32_t va = vhb + (32 * kcp + lane) * FPITCH + j2 * 16;
                uint32_t v0, v1, v2, v3, u0, u1, u2, u3;
                ldsm4t(v0, v1, v2, v3, va);
                ldsm4t(u0, u1, u2, u3, va + FTILE);
                mma_bf(o[j2], ph[0], v0, v1);
                mma_bf(o[j2], pl[0], v0, v1);
                mma_bf(o[j2], ph[0], u0, u1);
                mma_bf(o[j2], ph[1], v2, v3);
                mma_bf(o[j2], pl[1], v2, v3);
                mma_bf(o[j2], ph[1], u2, u3);
            }
        }

        __syncthreads();
        if (kt + 2 < NKT) { ldtile(kt & 1, kt + 2); CP_COMMIT(); }
    }

    // ---- epilogue: normalize, split bf16, store ----
    float inv0 = 1.f / l0, inv1 = 1.f / l1;
    size_t r0 = batch_row + (size_t)qt * 128 + w * 16 + grp;
#pragma unroll
    for (int j2 = 0; j2 < 8; j2++) {
        int c = h * HDIM + 8 * j2 + 2 * qr;
        float x0 = o[j2][0] * inv0, x1 = o[j2][1] * inv0;
        float x2 = o[j2][2] * inv1, x3 = o[j2][3] * inv1;
        uint32_t h0 = packbf(x0, x1), lo0 = packres(x0, x1, h0);
        uint32_t h1 = packbf(x2, x3), lo1 = packres(x2, x3, h1);
        *(uint32_t*)&Oh[r0 * EMB + c]       = h0;
        *(uint32_t*)&Ol[r0 * EMB + c]       = lo0;
        *(uint32_t*)&Oh[(r0 + 8) * EMB + c] = h1;
        *(uint32_t*)&Ol[(r0 + 8) * EMB + c] = lo1;
    }
}

// ------------------------------------------------------------------
extern "C" void kernel_launch(void* const* d_in, const int* in_sizes, int n_in,
                              void* d_out, int out_size) {
    const float* x  = (const float*)d_in[0];
    const float* Wq = (const float*)d_in[1];
    const float* Wk = (const float*)d_in[2];
    const float* Wv = (const float*)d_in[3];
    const float* Wo = (const float*)d_in[4];
    float* out = (float*)d_out;

    __nv_bfloat16 *gxh, *gxl, *gBqh, *gBql, *gBoh, *gBol, *gQh, *gQl, *gAh, *gAl;
    cudaGetSymbolAddress((void**)&gxh,  g_xh);
    cudaGetSymbolAddress((void**)&gxl,  g_xl);
    cudaGetSymbolAddress((void**)&gBqh, g_Bqh);
    cudaGetSymbolAddress((void**)&gBql, g_Bql);
    cudaGetSymbolAddress((void**)&gBoh, g_Boh);
    cudaGetSymbolAddress((void**)&gBol, g_Bol);
    cudaGetSymbolAddress((void**)&gQh,  g_QKVh);
    cudaGetSymbolAddress((void**)&gQl,  g_QKVl);
    cudaGetSymbolAddress((void**)&gAh,  g_Ah);
    cudaGetSymbolAddress((void**)&gAl,  g_Al);

    const int GSMEM = 2 * 40960;
    const int FSMEM = 2 * FSTAGE;
    cudaFuncSetAttribute(gemm_mma<0>, cudaFuncAttributeMaxDynamicSharedMemorySize, GSMEM);
    cudaFuncSetAttribute(gemm_mma<1>, cudaFuncAttributeMaxDynamicSharedMemorySize, GSMEM);
    cudaFuncSetAttribute(flash_mma,   cudaFuncAttributeMaxDynamicSharedMemorySize, FSMEM);

    split_x<<<(MROWS * EMB + 255) / 256, 256>>>(x, gxh, gxl, MROWS * EMB);
    pack_qkv<<<(QKVN * EMB + 255) / 256, 256>>>(Wq, Wk, Wv, gBqh, gBql);
    pack_wo<<<(EMB * EMB + 255) / 256, 256>>>(Wo, gBoh, gBol);

    gemm_mma<1><<<dim3(QKVN / 128, MROWS / 128), 256, GSMEM>>>(
        gxh, gxl, gBqh, gBql, nullptr, gQh, gQl, QKVN);

    flash_mma<<<dim3(SEQ / 128, HEADS, BATCH), 256, FSMEM>>>(gQh, gQl, gAh, gAl);

    gemm_mma<0><<<dim3(EMB / 128, MROWS / 128), 256, GSMEM>>>(
        gAh, gAl, gBoh, gBol, out, nullptr, nullptr, EMB);
}

// round 6
// speedup vs baseline: 3.2751x; 1.0789x over previous
#include <cuda_runtime.h>
#include <cuda_bf16.h>
#include <cuda_fp16.h>
#include <stdint.h>
#include <math.h>

#define BATCH 2
#define SEQ   2048
#define EMB   1024
#define HEADS 16
#define HDIM  64
#define MROWS (BATCH*SEQ)   /* 4096 */
#define QKVN  (3*EMB)       /* 3072 */
#define KDIM  EMB

#define QSCALE  0.02209708691207961f                 /* 1/sqrt(2048) */
#define QSCALE2 (QSCALE * 1.4426950408889634f)       /* fold log2(e): softmax in exp2 domain */

// ---------------- scratch (device globals; allocation-free) ----------------
__device__ __align__(256) __nv_bfloat16 g_xh [(size_t)MROWS*EMB];
__device__ __align__(256) __nv_bfloat16 g_xl [(size_t)MROWS*EMB];
__device__ __align__(256) __nv_bfloat16 g_Bqh[(size_t)QKVN*EMB];
__device__ __align__(256) __nv_bfloat16 g_Bql[(size_t)QKVN*EMB];
__device__ __align__(256) __nv_bfloat16 g_Boh[(size_t)EMB*EMB];
__device__ __align__(256) __nv_bfloat16 g_Bol[(size_t)EMB*EMB];
__device__ __align__(256) __nv_bfloat16 g_QKVh[(size_t)MROWS*QKVN];   /* V region holds fp16 bits */
__device__ __align__(256) __nv_bfloat16 g_QKVl[(size_t)MROWS*QKVN];
__device__ __align__(256) __nv_bfloat16 g_Ah [(size_t)MROWS*EMB];
__device__ __align__(256) __nv_bfloat16 g_Al [(size_t)MROWS*EMB];

// ---------------- helpers ----------------
__device__ __forceinline__ uint32_t cvta_smem(const void* p) {
    uint32_t a;
    asm("{ .reg .u64 t; cvta.to.shared.u64 t, %1; cvt.u32.u64 %0, t; }" : "=r"(a) : "l"(p));
    return a;
}
__device__ __forceinline__ void cp16(uint32_t dst, const void* src) {
    asm volatile("cp.async.cg.shared.global [%0], [%1], 16;" :: "r"(dst), "l"(src));
}
#define CP_COMMIT() asm volatile("cp.async.commit_group;" ::: "memory")
#define CP_WAIT2()  asm volatile("cp.async.wait_group 2;" ::: "memory")
#define CP_WAIT1()  asm volatile("cp.async.wait_group 1;" ::: "memory")
#define CP_WAIT0()  asm volatile("cp.async.wait_group 0;" ::: "memory")

__device__ __forceinline__ void ldsm4(uint32_t& r0, uint32_t& r1, uint32_t& r2, uint32_t& r3,
                                      uint32_t addr) {
    asm volatile("ldmatrix.sync.aligned.m8n8.x4.shared.b16 {%0,%1,%2,%3},[%4];"
                 : "=r"(r0), "=r"(r1), "=r"(r2), "=r"(r3) : "r"(addr));
}
__device__ __forceinline__ void ldsm4t(uint32_t& r0, uint32_t& r1, uint32_t& r2, uint32_t& r3,
                                       uint32_t addr) {
    asm volatile("ldmatrix.sync.aligned.m8n8.x4.trans.shared.b16 {%0,%1,%2,%3},[%4];"
                 : "=r"(r0), "=r"(r1), "=r"(r2), "=r"(r3) : "r"(addr));
}
__device__ __forceinline__ void mma_bf(float c[4], const uint32_t a[4], uint32_t b0, uint32_t b1) {
    asm("mma.sync.aligned.m16n8k16.row.col.f32.bf16.bf16.f32 "
        "{%0,%1,%2,%3}, {%4,%5,%6,%7}, {%8,%9}, {%0,%1,%2,%3};"
        : "+f"(c[0]), "+f"(c[1]), "+f"(c[2]), "+f"(c[3])
        : "r"(a[0]), "r"(a[1]), "r"(a[2]), "r"(a[3]), "r"(b0), "r"(b1));
}
__device__ __forceinline__ void mma_hf(float c[4], const uint32_t a[4], uint32_t b0, uint32_t b1) {
    asm("mma.sync.aligned.m16n8k16.row.col.f32.f16.f16.f32 "
        "{%0,%1,%2,%3}, {%4,%5,%6,%7}, {%8,%9}, {%0,%1,%2,%3};"
        : "+f"(c[0]), "+f"(c[1]), "+f"(c[2]), "+f"(c[3])
        : "r"(a[0]), "r"(a[1]), "r"(a[2]), "r"(a[3]), "r"(b0), "r"(b1));
}

__device__ __forceinline__ float ex2(float x) {
    float r;
    asm("ex2.approx.ftz.f32 %0, %1;" : "=f"(r) : "f"(x));
    return r;
}

__device__ __forceinline__ uint32_t packbf(float x, float y) {
    __nv_bfloat162 t = __floats2bfloat162_rn(x, y);
    return *reinterpret_cast<uint32_t*>(&t);
}
__device__ __forceinline__ uint32_t packres(float x, float y, uint32_t h) {
    __nv_bfloat162 hh = *reinterpret_cast<__nv_bfloat162*>(&h);
    return packbf(x - __bfloat162float(hh.x), y - __bfloat162float(hh.y));
}
__device__ __forceinline__ uint32_t packh(float x, float y) {
    __half2 t = __floats2half2_rn(x, y);
    return *reinterpret_cast<uint32_t*>(&t);
}
__device__ __forceinline__ void split2(float v, __nv_bfloat16& hi, __nv_bfloat16& lo) {
    hi = __float2bfloat16(v);
    lo = __float2bfloat16(v - __bfloat162float(hi));
}

// ---------------- packing kernels ----------------
__global__ void split_x(const float* __restrict__ x,
                        __nv_bfloat16* __restrict__ hi, __nv_bfloat16* __restrict__ lo, int n) {
    int i = blockIdx.x * blockDim.x + threadIdx.x;
    if (i >= n) return;
    split2(x[i], hi[i], lo[i]);
}

// Coalesced transpose pack: B_qkv[n][k] = W_wh[hid][k][i], n = wh*1024+hid*64+i.
// grid (16 kblk, 16 hid, 3 wh), 256 thr; smem 64x65 tile, both gmem sides coalesced.
__global__ void pack_qkv_t(const float* __restrict__ Wq, const float* __restrict__ Wk,
                           const float* __restrict__ Wv,
                           __nv_bfloat16* __restrict__ hi, __nv_bfloat16* __restrict__ lo) {
    __shared__ float ts[64][65];
    const int tid = threadIdx.x;
    const int kb = blockIdx.x, hid = blockIdx.y, wh = blockIdx.z;
    const float* src = (wh == 0) ? Wq : (wh == 1) ? Wk : Wv;
    const float sc = (wh == 0) ? QSCALE2 : 1.0f;

#pragma unroll
    for (int p = 0; p < 16; p++) {
        int kr = (tid >> 6) + p * 4;
        int i  = tid & 63;
        ts[kr][i] = src[(size_t)hid * (EMB * HDIM) + (size_t)(kb * 64 + kr) * HDIM + i];
    }
    __syncthreads();
#pragma unroll
    for (int p = 0; p < 16; p++) {
        int i = (tid >> 6) + p * 4;
        int k = tid & 63;
        float v = ts[k][i] * sc;
        size_t o = ((size_t)(wh * 1024 + hid * 64 + i) << 10) + kb * 64 + k;
        split2(v, hi[o], lo[o]);
    }
}

__global__ void pack_wo(const float* __restrict__ Wo,
                        __nv_bfloat16* __restrict__ hi, __nv_bfloat16* __restrict__ lo) {
    int idx = blockIdx.x * blockDim.x + threadIdx.x;
    if (idx >= EMB * EMB) return;
    split2(Wo[idx], hi[idx], lo[idx]);
}

// ---------------- GEMM: C[M,N] = A[M,K] * B[N,K]^T, bf16 3-pass split, mma.sync ----------------
// 256 thr (8 warps 4x2), tile 128x128, BK=32, 2-stage cp.async, 2 CTAs/SM.
// MODE 0: fp32 C out. MODE 1: bf16 hi/lo out; V columns (nb>=16) written as fp16 hi/lo.
template<int MODE>
__global__ __launch_bounds__(256, 2)
void gemm_mma(const __nv_bfloat16* __restrict__ Ah, const __nv_bfloat16* __restrict__ Al,
              const __nv_bfloat16* __restrict__ Bh, const __nv_bfloat16* __restrict__ Bl,
              float* __restrict__ C, __nv_bfloat16* __restrict__ Ch,
              __nv_bfloat16* __restrict__ Cl, int N) {
    extern __shared__ __align__(16) char smraw[];
    uint32_t smb = cvta_smem(smraw);
    const int tid = threadIdx.x, lane = tid & 31, wid = tid >> 5;
    const int wm = wid & 3, wn = wid >> 2;
    const int nb = blockIdx.x, mb = blockIdx.y;

    const __nv_bfloat16* gsrc[4] = {
        Ah + (size_t)mb * 128 * KDIM, Al + (size_t)mb * 128 * KDIM,
        Bh + (size_t)nb * 128 * KDIM, Bl + (size_t)nb * 128 * KDIM };

    auto ldchunk = [&](int buf, int ck) {
        uint32_t bb = smb + buf * 40960;
#pragma unroll
        for (int q = 0; q < 8; q++) {
            int i = q * 256 + tid;
            int t = i >> 9;
            int r = (i >> 2) & 127;
            int sg = i & 3;
            cp16(bb + t * 10240 + r * 80 + sg * 16,
                 gsrc[t] + (size_t)r * KDIM + ck * 32 + sg * 8);
        }
    };

    ldchunk(0, 0); CP_COMMIT();
    ldchunk(1, 1); CP_COMMIT();

    float acc[2][8][4];
#pragma unroll
    for (int a = 0; a < 2; a++)
#pragma unroll
        for (int b = 0; b < 8; b++)
#pragma unroll
            for (int c = 0; c < 4; c++) acc[a][b][c] = 0.f;

    for (int c = 0; c < 32; c++) {
        if (c < 31) CP_WAIT1(); else CP_WAIT0();
        __syncthreads();
        uint32_t bb = smb + (c & 1) * 40960;

#pragma unroll
        for (int s = 0; s < 2; s++) {
            uint32_t ah[2][4], al[2][4];
#pragma unroll
            for (int mt = 0; mt < 2; mt++) {
                uint32_t row = 32 * wm + 16 * mt + ((lane >> 3) & 1) * 8 + (lane & 7);
                uint32_t kb  = (lane >> 4) * 16 + s * 32;
                uint32_t ad  = bb + row * 80 + kb;
                ldsm4(ah[mt][0], ah[mt][1], ah[mt][2], ah[mt][3], ad);
                ldsm4(al[mt][0], al[mt][1], al[mt][2], al[mt][3], ad + 10240);
            }
#pragma unroll
            for (int np = 0; np < 4; np++) {
                uint32_t row = 64 * wn + 16 * np + ((lane >> 4) & 1) * 8 + (lane & 7);
                uint32_t kb  = ((lane >> 3) & 1) * 16 + s * 32;
                uint32_t bd  = bb + 20480 + row * 80 + kb;
                uint32_t bh0, bh1, bh2, bh3, bl0, bl1, bl2, bl3;
                ldsm4(bh0, bh1, bh2, bh3, bd);
                ldsm4(bl0, bl1, bl2, bl3, bd + 10240);
#pragma unroll
                for (int p = 0; p < 3; p++) {
                    const uint32_t* a0 = (p == 1) ? al[0] : ah[0];
                    const uint32_t* a1 = (p == 1) ? al[1] : ah[1];
                    uint32_t c0 = (p == 2) ? bl0 : bh0, c1 = (p == 2) ? bl1 : bh1;
                    uint32_t c2 = (p == 2) ? bl2 : bh2, c3 = (p == 2) ? bl3 : bh3;
                    mma_bf(acc[0][2 * np],     a0, c0, c1);
                    mma_bf(acc[1][2 * np],     a1, c0, c1);
                    mma_bf(acc[0][2 * np + 1], a0, c2, c3);
                    mma_bf(acc[1][2 * np + 1], a1, c2, c3);
                }
            }
        }
        __syncthreads();
        if (c + 2 < 32) { ldchunk(c & 1, c + 2); CP_COMMIT(); }
    }

    const int grp = lane >> 2, qr = lane & 3;
    const bool vpart = (MODE == 1) && (nb >= 16);   // V columns -> fp16 storage
#pragma unroll
    for (int mt = 0; mt < 2; mt++) {
        size_t r0 = (size_t)mb * 128 + 32 * wm + 16 * mt + grp;
#pragma unroll
        for (int nt = 0; nt < 8; nt++) {
            int col = nb * 128 + 64 * wn + 8 * nt + 2 * qr;
            float* c4 = acc[mt][nt];
            if (MODE == 0) {
                *(float2*)&C[r0 * N + col]       = make_float2(c4[0], c4[1]);
                *(float2*)&C[(r0 + 8) * N + col] = make_float2(c4[2], c4[3]);
            } else if (vpart) {
                uint32_t h0 = packh(c4[0], c4[1]);
                __half2 hh0 = *reinterpret_cast<__half2*>(&h0);
                uint32_t l0 = packh(c4[0] - __half2float(__low2half(hh0)),
                                    c4[1] - __half2float(__high2half(hh0)));
                uint32_t h1 = packh(c4[2], c4[3]);
                __half2 hh1 = *reinterpret_cast<__half2*>(&h1);
                uint32_t l1 = packh(c4[2] - __half2float(__low2half(hh1)),
                                    c4[3] - __half2float(__high2half(hh1)));
                *(uint32_t*)&Ch[r0 * N + col]       = h0;
                *(uint32_t*)&Cl[r0 * N + col]       = l0;
                *(uint32_t*)&Ch[(r0 + 8) * N + col] = h1;
                *(uint32_t*)&Cl[(r0 + 8) * N + col] = l1;
            } else {
                uint32_t h0 = packbf(c4[0], c4[1]), l0 = packres(c4[0], c4[1], h0);
                uint32_t h1 = packbf(c4[2], c4[3]), l1 = packres(c4[2], c4[3], h1);
                *(uint32_t*)&Ch[r0 * N + col]       = h0;
                *(uint32_t*)&Cl[r0 * N + col]       = l0;
                *(uint32_t*)&Ch[(r0 + 8) * N + col] = h1;
                *(uint32_t*)&Cl[(r0 + 8) * N + col] = l1;
            }
        }
    }
}

// ---------------- Flash attention via mma.sync ----------------
// S: bf16 3-pass (logit precision). PV: fp16, P single + V hi/lo (2-pass).
// 3-stage cp.async pipeline: 3 x 36KB = 108KB/CTA, 2 CTAs/SM.
#define FPITCH 144
#define FTILE  9216          /* 64*144 */
#define FSTAGE 36864         /* Kh,Kl,Vh,Vl */
#define NKT    (SEQ/64)

__global__ __launch_bounds__(256, 2)
void flash_mma(const __nv_bfloat16* __restrict__ Qh, const __nv_bfloat16* __restrict__ Ql,
               __nv_bfloat16* __restrict__ Oh, __nv_bfloat16* __restrict__ Ol) {
    extern __shared__ __align__(16) char smraw[];
    uint32_t smb = cvta_smem(smraw);

    const int tid = threadIdx.x, lane = tid & 31, w = tid >> 5;
    const int grp = lane >> 2, qr = lane & 3;
    const int qt = blockIdx.x, h = blockIdx.y, b = blockIdx.z;

    const size_t batch_row = (size_t)b * SEQ;

    const __nv_bfloat16* kvsrc[4] = {
        Qh + batch_row * QKVN + EMB + h * HDIM,          // Kh (bf16)
        Ql + batch_row * QKVN + EMB + h * HDIM,          // Kl (bf16)
        Qh + batch_row * QKVN + 2 * EMB + h * HDIM,      // Vh (fp16 bits)
        Ql + batch_row * QKVN + 2 * EMB + h * HDIM };    // Vl (fp16 bits)

    auto ldtile = [&](int buf, int kt) {
        uint32_t bb = smb + buf * FSTAGE;
        size_t rbase = (size_t)kt * 64;
#pragma unroll
        for (int q = 0; q < 8; q++) {
            int i = q * 256 + tid;
            int t = i >> 9;
            int r = (i >> 3) & 63;
            int sg = i & 7;
            cp16(bb + t * FTILE + r * FPITCH + sg * 16,
                 kvsrc[t] + (rbase + r) * QKVN + sg * 8);
        }
    };

    uint32_t qh[4][4], ql[4][4];
    {
        size_t r0 = batch_row + (size_t)qt * 128 + w * 16 + grp;
        const __nv_bfloat16* qb_h = Qh + r0 * QKVN + h * HDIM;
        const __nv_bfloat16* qb_l = Ql + r0 * QKVN + h * HDIM;
#pragma unroll
        for (int t = 0; t < 4; t++) {
            int c0 = t * 16 + 2 * qr;
            qh[t][0] = *(const uint32_t*)(qb_h + c0);
            qh[t][1] = *(const uint32_t*)(qb_h + 8 * QKVN + c0);
            qh[t][2] = *(const uint32_t*)(qb_h + c0 + 8);
            qh[t][3] = *(const uint32_t*)(qb_h + 8 * QKVN + c0 + 8);
            ql[t][0] = *(const uint32_t*)(qb_l + c0);
            ql[t][1] = *(const uint32_t*)(qb_l + 8 * QKVN + c0);
            ql[t][2] = *(const uint32_t*)(qb_l + c0 + 8);
            ql[t][3] = *(const uint32_t*)(qb_l + 8 * QKVN + c0 + 8);
        }
    }

    float o[8][4];
#pragma unroll
    for (int j = 0; j < 8; j++)
#pragma unroll
        for (int c = 0; c < 4; c++) o[j][c] = 0.f;
    float m0 = -1e30f, m1 = -1e30f, l0 = 0.f, l1 = 0.f;

    ldtile(0, 0); CP_COMMIT();
    ldtile(1, 1); CP_COMMIT();
    ldtile(2, 2); CP_COMMIT();

    int buf = 0;
    for (int kt = 0; kt < NKT; kt++) {
        if (kt + 3 <= NKT) CP_WAIT2();
        else if (kt + 2 == NKT) CP_WAIT1();
        else CP_WAIT0();
        __syncthreads();
        uint32_t sb  = smb + buf * FSTAGE;
        uint32_t khb = sb, vhb = sb + 2 * FTILE;

        // ---- S = Q K^T (16 x 64 per warp), bf16 3-pass ----
        float s[8][4];
#pragma unroll
        for (int j = 0; j < 8; j++) {
            uint32_t ka = khb + (8 * j + (lane & 7)) * FPITCH + (lane >> 3) * 16;
            uint32_t la = ka + FTILE;
            uint32_t h0, h1, h2, h3, h4, h5, h6, h7;
            uint32_t e0, e1, e2, e3, e4, e5, e6, e7;
            ldsm4(h0, h1, h2, h3, ka);
            ldsm4(h4, h5, h6, h7, ka + 64);
            ldsm4(e0, e1, e2, e3, la);
            ldsm4(e4, e5, e6, e7, la + 64);
            s[j][0] = s[j][1] = s[j][2] = s[j][3] = 0.f;
            mma_bf(s[j], qh[0], h0, h1); mma_bf(s[j], ql[0], h0, h1); mma_bf(s[j], qh[0], e0, e1);
            mma_bf(s[j], qh[1], h2, h3); mma_bf(s[j], ql[1], h2, h3); mma_bf(s[j], qh[1], e2, e3);
            mma_bf(s[j], qh[2], h4, h5); mma_bf(s[j], ql[2], h4, h5); mma_bf(s[j], qh[2], e4, e5);
            mma_bf(s[j], qh[3], h6, h7); mma_bf(s[j], ql[3], h6, h7); mma_bf(s[j], qh[3], e6, e7);
        }

        // ---- online softmax (exp2 domain; Q pre-scaled by 1/sqrt(T)*log2e) ----
        float n0 = m0, n1 = m1;
#pragma unroll
        for (int j = 0; j < 8; j++) {
            n0 = fmaxf(n0, fmaxf(s[j][0], s[j][1]));
            n1 = fmaxf(n1, fmaxf(s[j][2], s[j][3]));
        }
        n0 = fmaxf(n0, __shfl_xor_sync(0xffffffffu, n0, 1));
        n0 = fmaxf(n0, __shfl_xor_sync(0xffffffffu, n0, 2));
        n1 = fmaxf(n1, __shfl_xor_sync(0xffffffffu, n1, 1));
        n1 = fmaxf(n1, __shfl_xor_sync(0xffffffffu, n1, 2));
        float a0 = ex2(m0 - n0), a1 = ex2(m1 - n1);
        m0 = n0; m1 = n1;
        float rs0 = 0.f, rs1 = 0.f;
#pragma unroll
        for (int j = 0; j < 8; j++) {
            s[j][0] = ex2(s[j][0] - n0); rs0 += s[j][0];
            s[j][1] = ex2(s[j][1] - n0); rs0 += s[j][1];
            s[j][2] = ex2(s[j][2] - n1); rs1 += s[j][2];
            s[j][3] = ex2(s[j][3] - n1); rs1 += s[j][3];
        }
        rs0 += __shfl_xor_sync(0xffffffffu, rs0, 1);
        rs0 += __shfl_xor_sync(0xffffffffu, rs0, 2);
        rs1 += __shfl_xor_sync(0xffffffffu, rs1, 1);
        rs1 += __shfl_xor_sync(0xffffffffu, rs1, 2);
        l0 = l0 * a0 + rs0;
        l1 = l1 * a1 + rs1;
#pragma unroll
        for (int j = 0; j < 8; j++) {
            o[j][0] *= a0; o[j][1] *= a0; o[j][2] *= a1; o[j][3] *= a1;
        }

        // ---- O += P V : fp16, P single-pass + V hi/lo 2-pass ----
#pragma unroll
        for (int kcp = 0; kcp < 2; kcp++) {
            uint32_t ph[2][4];
#pragma unroll
            for (int u = 0; u < 2; u++) {
                int nt = 4 * kcp + 2 * u;
                ph[u][0] = packh(s[nt][0],     s[nt][1]);
                ph[u][1] = packh(s[nt][2],     s[nt][3]);
                ph[u][2] = packh(s[nt + 1][0], s[nt + 1][1]);
                ph[u][3] = packh(s[nt + 1][2], s[nt + 1][3]);
            }
#pragma unroll
            for (int j2 = 0; j2 < 8; j2++) {
                uint32_t va = vhb + (32 * kcp + lane) * FPITCH + j2 * 16;
                uint32_t v0, v1, v2, v3, u0, u1, u2, u3;
                ldsm4t(v0, v1, v2, v3, va);
                ldsm4t(u0, u1, u2, u3, va + FTILE);
                mma_hf(o[j2], ph[0], v0, v1);
                mma_hf(o[j2], ph[0], u0, u1);
                mma_hf(o[j2], ph[1], v2, v3);
                mma_hf(o[j2], ph[1], u2, u3);
            }
        }

        __syncthreads();
        if (kt + 3 < NKT) { ldtile(buf, kt + 3); CP_COMMIT(); }
        buf = (buf == 2) ? 0 : buf + 1;
    }

    // ---- epilogue: normalize, split bf16, store ----
    float inv0 = 1.f / l0, inv1 = 1.f / l1;
    size_t r0 = batch_row + (size_t)qt * 128 + w * 16 + grp;
#pragma unroll
    for (int j2 = 0; j2 < 8; j2++) {
        int c = h * HDIM + 8 * j2 + 2 * qr;
        float x0 = o[j2][0] * inv0, x1 = o[j2][1] * inv0;
        float x2 = o[j2][2] * inv1, x3 = o[j2][3] * inv1;
        uint32_t h0 = packbf(x0, x1), lo0 = packres(x0, x1, h0);
        uint32_t h1 = packbf(x2, x3), lo1 = packres(x2, x3, h1);
        *(uint32_t*)&Oh[r0 * EMB + c]       = h0;
        *(uint32_t*)&Ol[r0 * EMB + c]       = lo0;
        *(uint32_t*)&Oh[(r0 + 8) * EMB + c] = h1;
        *(uint32_t*)&Ol[(r0 + 8) * EMB + c] = lo1;
    }
}

// ------------------------------------------------------------------
extern "C" void kernel_launch(void* const* d_in, const int* in_sizes, int n_in,
                              void* d_out, int out_size) {
    const float* x  = (const float*)d_in[0];
    const float* Wq = (const float*)d_in[1];
    const float* Wk = (const float*)d_in[2];
    const float* Wv = (const float*)d_in[3];
    const float* Wo = (const float*)d_in[4];
    float* out = (float*)d_out;

    __nv_bfloat16 *gxh, *gxl, *gBqh, *gBql, *gBoh, *gBol, *gQh, *gQl, *gAh, *gAl;
    cudaGetSymbolAddress((void**)&gxh,  g_xh);
    cudaGetSymbolAddress((void**)&gxl,  g_xl);
    cudaGetSymbolAddress((void**)&gBqh, g_Bqh);
    cudaGetSymbolAddress((void**)&gBql, g_Bql);
    cudaGetSymbolAddress((void**)&gBoh, g_Boh);
    cudaGetSymbolAddress((void**)&gBol, g_Bol);
    cudaGetSymbolAddress((void**)&gQh,  g_QKVh);
    cudaGetSymbolAddress((void**)&gQl,  g_QKVl);
    cudaGetSymbolAddress((void**)&gAh,  g_Ah);
    cudaGetSymbolAddress((void**)&gAl,  g_Al);

    const int GSMEM = 2 * 40960;
    const int FSMEM = 3 * FSTAGE;
    cudaFuncSetAttribute(gemm_mma<0>, cudaFuncAttributeMaxDynamicSharedMemorySize, GSMEM);
    cudaFuncSetAttribute(gemm_mma<1>, cudaFuncAttributeMaxDynamicSharedMemorySize, GSMEM);
    cudaFuncSetAttribute(flash_mma,   cudaFuncAttributeMaxDynamicSharedMemorySize, FSMEM);

    split_x<<<(MROWS * EMB + 255) / 256, 256>>>(x, gxh, gxl, MROWS * EMB);
    pack_qkv_t<<<dim3(16, 16, 3), 256>>>(Wq, Wk, Wv, gBqh, gBql);
    pack_wo<<<(EMB * EMB + 255) / 256, 256>>>(Wo, gBoh, gBol);

    gemm_mma<1><<<dim3(QKVN / 128, MROWS / 128), 256, GSMEM>>>(
        gxh, gxl, gBqh, gBql, nullptr, gQh, gQl, QKVN);

    flash_mma<<<dim3(SEQ / 128, HEADS, BATCH), 256, FSMEM>>>(gQh, gQl, gAh, gAl);

    gemm_mma<0><<<dim3(EMB / 128, MROWS / 128), 256, GSMEM>>>(
        gAh, gAl, gBoh, gBol, out, nullptr, nullptr, EMB);
}

// round 7
// speedup vs baseline: 4.0227x; 1.2283x over previous
#include <cuda_runtime.h>
#include <cuda_bf16.h>
#include <cuda_fp16.h>
#include <stdint.h>
#include <math.h>

#define BATCH 2
#define SEQ   2048
#define EMB   1024
#define HEADS 16
#define HDIM  64
#define MROWS (BATCH*SEQ)   /* 4096 */
#define QKVN  (3*EMB)       /* 3072 */
#define KDIM  EMB

#define QSCALE  0.02209708691207961f                 /* 1/sqrt(2048) */
#define QSCALE2 (QSCALE * 1.4426950408889634f)       /* fold log2(e): softmax in exp2 domain */

// ---------------- scratch (device globals; allocation-free) ----------------
__device__ __align__(256) __nv_bfloat16 g_xh [(size_t)MROWS*EMB];
__device__ __align__(256) __nv_bfloat16 g_xl [(size_t)MROWS*EMB];
__device__ __align__(256) __nv_bfloat16 g_Bqh[(size_t)QKVN*EMB];
__device__ __align__(256) __nv_bfloat16 g_Bql[(size_t)QKVN*EMB];
__device__ __align__(256) __nv_bfloat16 g_Boh[(size_t)EMB*EMB];
__device__ __align__(256) __nv_bfloat16 g_Bol[(size_t)EMB*EMB];
__device__ __align__(256) __nv_bfloat16 g_QKVh[(size_t)MROWS*QKVN];   /* V region = fp16 bits */
__device__ __align__(256) __nv_bfloat16 g_QKVl[(size_t)MROWS*QKVN];   /* V region unused */
__device__ __align__(256) __nv_bfloat16 g_Ah [(size_t)MROWS*EMB];
__device__ __align__(256) __nv_bfloat16 g_Al [(size_t)MROWS*EMB];

// ---------------- helpers ----------------
__device__ __forceinline__ uint32_t cvta_smem(const void* p) {
    uint32_t a;
    asm("{ .reg .u64 t; cvta.to.shared.u64 t, %1; cvt.u32.u64 %0, t; }" : "=r"(a) : "l"(p));
    return a;
}
__device__ __forceinline__ void cp16(uint32_t dst, const void* src) {
    asm volatile("cp.async.cg.shared.global [%0], [%1], 16;" :: "r"(dst), "l"(src));
}
#define CP_COMMIT() asm volatile("cp.async.commit_group;" ::: "memory")
#define CP_WAIT1()  asm volatile("cp.async.wait_group 1;" ::: "memory")
#define CP_WAIT0()  asm volatile("cp.async.wait_group 0;" ::: "memory")

__device__ __forceinline__ void ldsm4(uint32_t& r0, uint32_t& r1, uint32_t& r2, uint32_t& r3,
                                      uint32_t addr) {
    asm volatile("ldmatrix.sync.aligned.m8n8.x4.shared.b16 {%0,%1,%2,%3},[%4];"
                 : "=r"(r0), "=r"(r1), "=r"(r2), "=r"(r3) : "r"(addr));
}
__device__ __forceinline__ void ldsm4t(uint32_t& r0, uint32_t& r1, uint32_t& r2, uint32_t& r3,
                                       uint32_t addr) {
    asm volatile("ldmatrix.sync.aligned.m8n8.x4.trans.shared.b16 {%0,%1,%2,%3},[%4];"
                 : "=r"(r0), "=r"(r1), "=r"(r2), "=r"(r3) : "r"(addr));
}
__device__ __forceinline__ void mma_bf(float c[4], const uint32_t a[4], uint32_t b0, uint32_t b1) {
    asm("mma.sync.aligned.m16n8k16.row.col.f32.bf16.bf16.f32 "
        "{%0,%1,%2,%3}, {%4,%5,%6,%7}, {%8,%9}, {%0,%1,%2,%3};"
        : "+f"(c[0]), "+f"(c[1]), "+f"(c[2]), "+f"(c[3])
        : "r"(a[0]), "r"(a[1]), "r"(a[2]), "r"(a[3]), "r"(b0), "r"(b1));
}
__device__ __forceinline__ void mma_hf(float c[4], const uint32_t a[4], uint32_t b0, uint32_t b1) {
    asm("mma.sync.aligned.m16n8k16.row.col.f32.f16.f16.f32 "
        "{%0,%1,%2,%3}, {%4,%5,%6,%7}, {%8,%9}, {%0,%1,%2,%3};"
        : "+f"(c[0]), "+f"(c[1]), "+f"(c[2]), "+f"(c[3])
        : "r"(a[0]), "r"(a[1]), "r"(a[2]), "r"(a[3]), "r"(b0), "r"(b1));
}
__device__ __forceinline__ float ex2(float x) {
    float r;
    asm("ex2.approx.ftz.f32 %0, %1;" : "=f"(r) : "f"(x));
    return r;
}
__device__ __forceinline__ uint32_t packbf(float x, float y) {
    __nv_bfloat162 t = __floats2bfloat162_rn(x, y);
    return *reinterpret_cast<uint32_t*>(&t);
}
__device__ __forceinline__ uint32_t packres(float x, float y, uint32_t h) {
    __nv_bfloat162 hh = *reinterpret_cast<__nv_bfloat162*>(&h);
    return packbf(x - __bfloat162float(hh.x), y - __bfloat162float(hh.y));
}
__device__ __forceinline__ uint32_t packh(float x, float y) {
    __half2 t = __floats2half2_rn(x, y);
    return *reinterpret_cast<uint32_t*>(&t);
}
__device__ __forceinline__ void split2(float v, __nv_bfloat16& hi, __nv_bfloat16& lo) {
    hi = __float2bfloat16(v);
    lo = __float2bfloat16(v - __bfloat162float(hi));
}

// ---------------- packing kernels ----------------
__global__ void split_x(const float* __restrict__ x,
                        __nv_bfloat16* __restrict__ hi, __nv_bfloat16* __restrict__ lo, int n) {
    int i = blockIdx.x * blockDim.x + threadIdx.x;
    if (i >= n) return;
    split2(x[i], hi[i], lo[i]);
}

__global__ void pack_qkv_t(const float* __restrict__ Wq, const float* __restrict__ Wk,
                           const float* __restrict__ Wv,
                           __nv_bfloat16* __restrict__ hi, __nv_bfloat16* __restrict__ lo) {
    __shared__ float ts[64][65];
    const int tid = threadIdx.x;
    const int kb = blockIdx.x, hid = blockIdx.y, wh = blockIdx.z;
    const float* src = (wh == 0) ? Wq : (wh == 1) ? Wk : Wv;
    const float sc = (wh == 0) ? QSCALE2 : 1.0f;

#pragma unroll
    for (int p = 0; p < 16; p++) {
        int kr = (tid >> 6) + p * 4;
        int i  = tid & 63;
        ts[kr][i] = src[(size_t)hid * (EMB * HDIM) + (size_t)(kb * 64 + kr) * HDIM + i];
    }
    __syncthreads();
#pragma unroll
    for (int p = 0; p < 16; p++) {
        int i = (tid >> 6) + p * 4;
        int k = tid & 63;
        float v = ts[k][i] * sc;
        size_t o = ((size_t)(wh * 1024 + hid * 64 + i) << 10) + kb * 64 + k;
        split2(v, hi[o], lo[o]);
    }
}

__global__ void pack_wo(const float* __restrict__ Wo,
                        __nv_bfloat16* __restrict__ hi, __nv_bfloat16* __restrict__ lo) {
    int idx = blockIdx.x * blockDim.x + threadIdx.x;
    if (idx >= EMB * EMB) return;
    split2(Wo[idx], hi[idx], lo[idx]);
}

// ---------------- GEMM: C = A B^T, bf16 3-pass, 3-stage single-barrier pipeline ----------------
// 64B smem pitch with XOR swizzle: phys c16' = c16 ^ ((r>>1)&3). Stage 32KB, 3 stages, 2 CTAs/SM.
#define GTILE  8192
#define GSTAGE 32768
#define GNC    (KDIM/32)    /* 32 chunks */

template<int MODE>
__global__ __launch_bounds__(256, 2)
void gemm_mma(const __nv_bfloat16* __restrict__ Ah, const __nv_bfloat16* __restrict__ Al,
              const __nv_bfloat16* __restrict__ Bh, const __nv_bfloat16* __restrict__ Bl,
              float* __restrict__ C, __nv_bfloat16* __restrict__ Ch,
              __nv_bfloat16* __restrict__ Cl, int N) {
    extern __shared__ __align__(16) char smraw[];
    uint32_t smb = cvta_smem(smraw);
    const int tid = threadIdx.x, lane = tid & 31, wid = tid >> 5;
    const int wm = wid & 3, wn = wid >> 2;
    const int nb = blockIdx.x, mb = blockIdx.y;

    const __nv_bfloat16* gsrc[4] = {
        Ah + (size_t)mb * 128 * KDIM, Al + (size_t)mb * 128 * KDIM,
        Bh + (size_t)nb * 128 * KDIM, Bl + (size_t)nb * 128 * KDIM };

    auto ldchunk = [&](int buf, int ck) {
        uint32_t bb = smb + buf * GSTAGE;
#pragma unroll
        for (int q = 0; q < 8; q++) {
            int i = q * 256 + tid;          // 0..2047
            int t = i >> 9;
            int r = (i >> 2) & 127;
            int c16 = i & 3;
            uint32_t dst = bb + t * GTILE + r * 64 + ((c16 ^ ((r >> 1) & 3)) << 4);
            cp16(dst, gsrc[t] + (size_t)r * KDIM + ck * 32 + c16 * 8);
        }
    };

    ldchunk(0, 0); CP_COMMIT();
    ldchunk(1, 1); CP_COMMIT();

    float acc[2][8][4];
#pragma unroll
    for (int a = 0; a < 2; a++)
#pragma unroll
        for (int b = 0; b < 8; b++)
#pragma unroll
            for (int c = 0; c < 4; c++) acc[a][b][c] = 0.f;

    int buf = 0, rb = 2;
    for (int c = 0; c < GNC; c++) {
        if (c + 1 < GNC) CP_WAIT1(); else CP_WAIT0();
        __syncthreads();
        // refill target rb == buffer read at iter c-1; barrier above protects it
        if (c + 2 < GNC) {
            ldchunk(rb, c + 2); CP_COMMIT();
            rb = (rb == 2) ? 0 : rb + 1;
        }
        uint32_t bb = smb + buf * GSTAGE;

#pragma unroll
        for (int s = 0; s < 2; s++) {
            uint32_t ah[2][4], al[2][4];
#pragma unroll
            for (int mt = 0; mt < 2; mt++) {
                uint32_t row = 32 * wm + 16 * mt + ((lane >> 3) & 1) * 8 + (lane & 7);
                uint32_t kb  = (lane >> 4) * 16 + s * 32;
                uint32_t ad  = bb + row * 64 + ((((kb >> 4)) ^ ((row >> 1) & 3)) << 4);
                ldsm4(ah[mt][0], ah[mt][1], ah[mt][2], ah[mt][3], ad);
                ldsm4(al[mt][0], al[mt][1], al[mt][2], al[mt][3], ad + GTILE);
            }
#pragma unroll
            for (int np = 0; np < 4; np++) {
                uint32_t row = 64 * wn + 16 * np + ((lane >> 4) & 1) * 8 + (lane & 7);
                uint32_t kb  = ((lane >> 3) & 1) * 16 + s * 32;
                uint32_t bd  = bb + 2 * GTILE + row * 64 + ((((kb >> 4)) ^ ((row >> 1) & 3)) << 4);
                uint32_t bh0, bh1, bh2, bh3, bl0, bl1, bl2, bl3;
                ldsm4(bh0, bh1, bh2, bh3, bd);
                ldsm4(bl0, bl1, bl2, bl3, bd + GTILE);
#pragma unroll
                for (int p = 0; p < 3; p++) {
                    const uint32_t* a0 = (p == 1) ? al[0] : ah[0];
                    const uint32_t* a1 = (p == 1) ? al[1] : ah[1];
                    uint32_t c0 = (p == 2) ? bl0 : bh0, c1 = (p == 2) ? bl1 : bh1;
                    uint32_t c2 = (p == 2) ? bl2 : bh2, c3 = (p == 2) ? bl3 : bh3;
                    mma_bf(acc[0][2 * np],     a0, c0, c1);
                    mma_bf(acc[1][2 * np],     a1, c0, c1);
                    mma_bf(acc[0][2 * np + 1], a0, c2, c3);
                    mma_bf(acc[1][2 * np + 1], a1, c2, c3);
                }
            }
        }
        buf = (buf == 2) ? 0 : buf + 1;
    }

    const int grp = lane >> 2, qr = lane & 3;
    const bool vpart = (MODE == 1) && (nb >= 16);   // V columns -> single fp16
#pragma unroll
    for (int mt = 0; mt < 2; mt++) {
        size_t r0 = (size_t)mb * 128 + 32 * wm + 16 * mt + grp;
#pragma unroll
        for (int nt = 0; nt < 8; nt++) {
            int col = nb * 128 + 64 * wn + 8 * nt + 2 * qr;
            float* c4 = acc[mt][nt];
            if (MODE == 0) {
                *(float2*)&C[r0 * N + col]       = make_float2(c4[0], c4[1]);
                *(float2*)&C[(r0 + 8) * N + col] = make_float2(c4[2], c4[3]);
            } else if (vpart) {
                *(uint32_t*)&Ch[r0 * N + col]       = packh(c4[0], c4[1]);
                *(uint32_t*)&Ch[(r0 + 8) * N + col] = packh(c4[2], c4[3]);
            } else {
                uint32_t h0 = packbf(c4[0], c4[1]), l0 = packres(c4[0], c4[1], h0);
                uint32_t h1 = packbf(c4[2], c4[3]), l1 = packres(c4[2], c4[3], h1);
                *(uint32_t*)&Ch[r0 * N + col]       = h0;
                *(uint32_t*)&Cl[r0 * N + col]       = l0;
                *(uint32_t*)&Ch[(r0 + 8) * N + col] = h1;
                *(uint32_t*)&Cl[(r0 + 8) * N + col] = l1;
            }
        }
    }
}

// ---------------- Flash attention: S bf16 3-pass; PV fp16 P x fp16 V single-pass ----------------
// Stage = Kh,Kl,Vh (3 x 9216 = 27648B); 3 stages, single barrier per tile; 2 CTAs/SM.
#define FPITCH 144
#define FTILE  9216
#define FSTAGE 27648
#define NKT    (SEQ/64)

__global__ __launch_bounds__(256, 2)
void flash_mma(const __nv_bfloat16* __restrict__ Qh, const __nv_bfloat16* __restrict__ Ql,
               __nv_bfloat16* __restrict__ Oh, __nv_bfloat16* __restrict__ Ol) {
    extern __shared__ __align__(16) char smraw[];
    uint32_t smb = cvta_smem(smraw);

    const int tid = threadIdx.x, lane = tid & 31, w = tid >> 5;
    const int grp = lane >> 2, qr = lane & 3;
    const int qt = blockIdx.x, h = blockIdx.y, b = blockIdx.z;

    const size_t batch_row = (size_t)b * SEQ;

    const __nv_bfloat16* kvsrc[3] = {
        Qh + batch_row * QKVN + EMB + h * HDIM,          // Kh (bf16)
        Ql + batch_row * QKVN + EMB + h * HDIM,          // Kl (bf16)
        Qh + batch_row * QKVN + 2 * EMB + h * HDIM };    // Vh (fp16 bits)

    auto ldtile = [&](int bf, int kt) {
        uint32_t bb = smb + bf * FSTAGE;
        size_t rbase = (size_t)kt * 64;
#pragma unroll
        for (int q = 0; q < 6; q++) {
            int i = q * 256 + tid;          // 0..1535
            int t = i >> 9;
            int r = (i >> 3) & 63;
            int sg = i & 7;
            cp16(bb + t * FTILE + r * FPITCH + sg * 16,
                 kvsrc[t] + (rbase + r) * QKVN + sg * 8);
        }
    };

    uint32_t qh[4][4], ql[4][4];
    {
        size_t r0 = batch_row + (size_t)qt * 128 + w * 16 + grp;
        const __nv_bfloat16* qb_h = Qh + r0 * QKVN + h * HDIM;
        const __nv_bfloat16* qb_l = Ql + r0 * QKVN + h * HDIM;
#pragma unroll
        for (int t = 0; t < 4; t++) {
            int c0 = t * 16 + 2 * qr;
            qh[t][0] = *(const uint32_t*)(qb_h + c0);
            qh[t][1] = *(const uint32_t*)(qb_h + 8 * QKVN + c0);
            qh[t][2] = *(const uint32_t*)(qb_h + c0 + 8);
            qh[t][3] = *(const uint32_t*)(qb_h + 8 * QKVN + c0 + 8);
            ql[t][0] = *(const uint32_t*)(qb_l + c0);
            ql[t][1] = *(const uint32_t*)(qb_l + 8 * QKVN + c0);
            ql[t][2] = *(const uint32_t*)(qb_l + c0 + 8);
            ql[t][3] = *(const uint32_t*)(qb_l + 8 * QKVN + c0 + 8);
        }
    }

    float o[8][4];
#pragma unroll
    for (int j = 0; j < 8; j++)
#pragma unroll
        for (int c = 0; c < 4; c++) o[j][c] = 0.f;
    float m0 = -1e30f, m1 = -1e30f, l0 = 0.f, l1 = 0.f;

    ldtile(0, 0); CP_COMMIT();
    ldtile(1, 1); CP_COMMIT();

    int buf = 0, rb = 2;
    for (int kt = 0; kt < NKT; kt++) {
        if (kt + 1 < NKT) CP_WAIT1(); else CP_WAIT0();
        __syncthreads();
        if (kt + 2 < NKT) {
            ldtile(rb, kt + 2); CP_COMMIT();
            rb = (rb == 2) ? 0 : rb + 1;
        }
        uint32_t sb  = smb + buf * FSTAGE;
        uint32_t khb = sb, vhb = sb + 2 * FTILE;

        // ---- S = Q K^T (16 x 64 per warp), bf16 3-pass ----
        float s[8][4];
#pragma unroll
        for (int j = 0; j < 8; j++) {
            uint32_t ka = khb + (8 * j + (lane & 7)) * FPITCH + (lane >> 3) * 16;
            uint32_t la = ka + FTILE;
            uint32_t h0, h1, h2, h3, h4, h5, h6, h7;
            uint32_t e0, e1, e2, e3, e4, e5, e6, e7;
            ldsm4(h0, h1, h2, h3, ka);
            ldsm4(h4, h5, h6, h7, ka + 64);
            ldsm4(e0, e1, e2, e3, la);
            ldsm4(e4, e5, e6, e7, la + 64);
            s[j][0] = s[j][1] = s[j][2] = s[j][3] = 0.f;
            mma_bf(s[j], qh[0], h0, h1); mma_bf(s[j], ql[0], h0, h1); mma_bf(s[j], qh[0], e0, e1);
            mma_bf(s[j], qh[1], h2, h3); mma_bf(s[j], ql[1], h2, h3); mma_bf(s[j], qh[1], e2, e3);
            mma_bf(s[j], qh[2], h4, h5); mma_bf(s[j], ql[2], h4, h5); mma_bf(s[j], qh[2], e4, e5);
            mma_bf(s[j], qh[3], h6, h7); mma_bf(s[j], ql[3], h6, h7); mma_bf(s[j], qh[3], e6, e7);
        }

        // ---- online softmax (exp2 domain) ----
        float n0 = m0, n1 = m1;
#pragma unroll
        for (int j = 0; j < 8; j++) {
            n0 = fmaxf(n0, fmaxf(s[j][0], s[j][1]));
            n1 = fmaxf(n1, fmaxf(s[j][2], s[j][3]));
        }
        n0 = fmaxf(n0, __shfl_xor_sync(0xffffffffu, n0, 1));
        n0 = fmaxf(n0, __shfl_xor_sync(0xffffffffu, n0, 2));
        n1 = fmaxf(n1, __shfl_xor_sync(0xffffffffu, n1, 1));
        n1 = fmaxf(n1, __shfl_xor_sync(0xffffffffu, n1, 2));
        float a0 = ex2(m0 - n0), a1 = ex2(m1 - n1);
        m0 = n0; m1 = n1;
        float rs0 = 0.f, rs1 = 0.f;
#pragma unroll
        for (int j = 0; j < 8; j++) {
            s[j][0] = ex2(s[j][0] - n0); rs0 += s[j][0];
            s[j][1] = ex2(s[j][1] - n0); rs0 += s[j][1];
            s[j][2] = ex2(s[j][2] - n1); rs1 += s[j][2];
            s[j][3] = ex2(s[j][3] - n1); rs1 += s[j][3];
        }
        rs0 += __shfl_xor_sync(0xffffffffu, rs0, 1);
        rs0 += __shfl_xor_sync(0xffffffffu, rs0, 2);
        rs1 += __shfl_xor_sync(0xffffffffu, rs1, 1);
        rs1 += __shfl_xor_sync(0xffffffffu, rs1, 2);
        l0 = l0 * a0 + rs0;
        l1 = l1 * a1 + rs1;
#pragma unroll
        for (int j = 0; j < 8; j++) {
            o[j][0] *= a0; o[j][1] *= a0; o[j][2] *= a1; o[j][3] *= a1;
        }

        // ---- O += P V : fp16 single-pass ----
#pragma unroll
        for (int kcp = 0; kcp < 2; kcp++) {
            uint32_t ph[2][4];
#pragma unroll
            for (int u = 0; u < 2; u++) {
                int nt = 4 * kcp + 2 * u;
                ph[u][0] = packh(s[nt][0],     s[nt][1]);
                ph[u][1] = packh(s[nt][2],     s[nt][3]);
                ph[u][2] = packh(s[nt + 1][0], s[nt + 1][1]);
                ph[u][3] = packh(s[nt + 1][2], s[nt + 1][3]);
            }
#pragma unroll
            for (int j2 = 0; j2 < 8; j2++) {
                uint32_t va = vhb + (32 * kcp + lane) * FPITCH + j2 * 16;
                uint32_t v0, v1, v2, v3;
                ldsm4t(v0, v1, v2, v3, va);
                mma_hf(o[j2], ph[0], v0, v1);
                mma_hf(o[j2], ph[1], v2, v3);
            }
        }
        buf = (buf == 2) ? 0 : buf + 1;
    }

    // ---- epilogue: normalize, split bf16, store ----
    float inv0 = 1.f / l0, inv1 = 1.f / l1;
    size_t r0 = batch_row + (size_t)qt * 128 + w * 16 + grp;
#pragma unroll
    for (int j2 = 0; j2 < 8; j2++) {
        int c = h * HDIM + 8 * j2 + 2 * qr;
        float x0 = o[j2][0] * inv0, x1 = o[j2][1] * inv0;
        float x2 = o[j2][2] * inv1, x3 = o[j2][3] * inv1;
        uint32_t h0 = packbf(x0, x1), lo0 = packres(x0, x1, h0);
        uint32_t h1 = packbf(x2, x3), lo1 = packres(x2, x3, h1);
        *(uint32_t*)&Oh[r0 * EMB + c]       = h0;
        *(uint32_t*)&Ol[r0 * EMB + c]       = lo0;
        *(uint32_t*)&Oh[(r0 + 8) * EMB + c] = h1;
        *(uint32_t*)&Ol[(r0 + 8) * EMB + c] = lo1;
    }
}

// ------------------------------------------------------------------
extern "C" void kernel_launch(void* const* d_in, const int* in_sizes, int n_in,
                              void* d_out, int out_size) {
    const float* x  = (const float*)d_in[0];
    const float* Wq = (const float*)d_in[1];
    const float* Wk = (const float*)d_in[2];
    const float* Wv = (const float*)d_in[3];
    const float* Wo = (const float*)d_in[4];
    float* out = (float*)d_out;

    __nv_bfloat16 *gxh, *gxl, *gBqh, *gBql, *gBoh, *gBol, *gQh, *gQl, *gAh, *gAl;
    cudaGetSymbolAddress((void**)&gxh,  g_xh);
    cudaGetSymbolAddress((void**)&gxl,  g_xl);
    cudaGetSymbolAddress((void**)&gBqh, g_Bqh);
    cudaGetSymbolAddress((void**)&gBql, g_Bql);
    cudaGetSymbolAddress((void**)&gBoh, g_Boh);
    cudaGetSymbolAddress((void**)&gBol, g_Bol);
    cudaGetSymbolAddress((void**)&gQh,  g_QKVh);
    cudaGetSymbolAddress((void**)&gQl,  g_QKVl);
    cudaGetSymbolAddress((void**)&gAh,  g_Ah);
    cudaGetSymbolAddress((void**)&gAl,  g_Al);

    const int GSMEM = 3 * GSTAGE;     // 98304
    const int FSMEM = 3 * FSTAGE;     // 82944
    cudaFuncSetAttribute(gemm_mma<0>, cudaFuncAttributeMaxDynamicSharedMemorySize, GSMEM);
    cudaFuncSetAttribute(gemm_mma<1>, cudaFuncAttributeMaxDynamicSharedMemorySize, GSMEM);
    cudaFuncSetAttribute(flash_mma,   cudaFuncAttributeMaxDynamicSharedMemorySize, FSMEM);

    split_x<<<(MROWS * EMB + 255) / 256, 256>>>(x, gxh, gxl, MROWS * EMB);
    pack_qkv_t<<<dim3(16, 16, 3), 256>>>(Wq, Wk, Wv, gBqh, gBql);
    pack_wo<<<(EMB * EMB + 255) / 256, 256>>>(Wo, gBoh, gBol);

    gemm_mma<1><<<dim3(QKVN / 128, MROWS / 128), 256, GSMEM>>>(
        gxh, gxl, gBqh, gBql, nullptr, gQh, gQl, QKVN);

    flash_mma<<<dim3(SEQ / 128, HEADS, BATCH), 256, FSMEM>>>(gQh, gQl, gAh, gAl);

    gemm_mma<0><<<dim3(EMB / 128, MROWS / 128), 256, GSMEM>>>(
        gAh, gAl, gBoh, gBol, out, nullptr, nullptr, EMB);
}

// round 8
// speedup vs baseline: 4.2565x; 1.0581x over previous
#include <cuda_runtime.h>
#include <cuda_bf16.h>
#include <cuda_fp16.h>
#include <stdint.h>
#include <math.h>

#define BATCH 2
#define SEQ   2048
#define EMB   1024
#define HEADS 16
#define HDIM  64
#define MROWS (BATCH*SEQ)   /* 4096 */
#define QKVN  (3*EMB)       /* 3072 */
#define KDIM  EMB

#define QSCALE  0.02209708691207961f                 /* 1/sqrt(2048) */
#define QSCALE2 (QSCALE * 1.4426950408889634f)       /* fold log2(e) */

// ---------------- scratch ----------------
__device__ __align__(256) __nv_bfloat16 g_xh [(size_t)MROWS*EMB];
__device__ __align__(256) __nv_bfloat16 g_xl [(size_t)MROWS*EMB];
__device__ __align__(256) __nv_bfloat16 g_Bqh[(size_t)QKVN*EMB];
__device__ __align__(256) __nv_bfloat16 g_Bql[(size_t)QKVN*EMB];
__device__ __align__(256) __half        g_Boh[(size_t)EMB*EMB];
__device__ __align__(256) __half        g_Bol[(size_t)EMB*EMB];
__device__ __align__(256) __nv_bfloat16 g_QKVh[(size_t)MROWS*QKVN];   /* V region = fp16 bits */
__device__ __align__(256) __nv_bfloat16 g_QKVl[(size_t)MROWS*QKVN];   /* V region unused */
__device__ __align__(256) __half        g_At [(size_t)MROWS*EMB];     /* attended, fp16 */

// ---------------- helpers ----------------
__device__ __forceinline__ uint32_t cvta_smem(const void* p) {
    uint32_t a;
    asm("{ .reg .u64 t; cvta.to.shared.u64 t, %1; cvt.u32.u64 %0, t; }" : "=r"(a) : "l"(p));
    return a;
}
__device__ __forceinline__ void cp16(uint32_t dst, const void* src) {
    asm volatile("cp.async.cg.shared.global [%0], [%1], 16;" :: "r"(dst), "l"(src));
}
#define CP_COMMIT() asm volatile("cp.async.commit_group;" ::: "memory")
#define CP_WAIT2()  asm volatile("cp.async.wait_group 2;" ::: "memory")
#define CP_WAIT1()  asm volatile("cp.async.wait_group 1;" ::: "memory")
#define CP_WAIT0()  asm volatile("cp.async.wait_group 0;" ::: "memory")

__device__ __forceinline__ void ldsm4(uint32_t& r0, uint32_t& r1, uint32_t& r2, uint32_t& r3,
                                      uint32_t addr) {
    asm volatile("ldmatrix.sync.aligned.m8n8.x4.shared.b16 {%0,%1,%2,%3},[%4];"
                 : "=r"(r0), "=r"(r1), "=r"(r2), "=r"(r3) : "r"(addr));
}
__device__ __forceinline__ void ldsm4t(uint32_t& r0, uint32_t& r1, uint32_t& r2, uint32_t& r3,
                                       uint32_t addr) {
    asm volatile("ldmatrix.sync.aligned.m8n8.x4.trans.shared.b16 {%0,%1,%2,%3},[%4];"
                 : "=r"(r0), "=r"(r1), "=r"(r2), "=r"(r3) : "r"(addr));
}
__device__ __forceinline__ void mma_bf(float c[4], const uint32_t a[4], uint32_t b0, uint32_t b1) {
    asm("mma.sync.aligned.m16n8k16.row.col.f32.bf16.bf16.f32 "
        "{%0,%1,%2,%3}, {%4,%5,%6,%7}, {%8,%9}, {%0,%1,%2,%3};"
        : "+f"(c[0]), "+f"(c[1]), "+f"(c[2]), "+f"(c[3])
        : "r"(a[0]), "r"(a[1]), "r"(a[2]), "r"(a[3]), "r"(b0), "r"(b1));
}
__device__ __forceinline__ void mma_hf(float c[4], const uint32_t a[4], uint32_t b0, uint32_t b1) {
    asm("mma.sync.aligned.m16n8k16.row.col.f32.f16.f16.f32 "
        "{%0,%1,%2,%3}, {%4,%5,%6,%7}, {%8,%9}, {%0,%1,%2,%3};"
        : "+f"(c[0]), "+f"(c[1]), "+f"(c[2]), "+f"(c[3])
        : "r"(a[0]), "r"(a[1]), "r"(a[2]), "r"(a[3]), "r"(b0), "r"(b1));
}
__device__ __forceinline__ float ex2(float x) {
    float r;
    asm("ex2.approx.ftz.f32 %0, %1;" : "=f"(r) : "f"(x));
    return r;
}
__device__ __forceinline__ uint32_t packbf(float x, float y) {
    __nv_bfloat162 t = __floats2bfloat162_rn(x, y);
    return *reinterpret_cast<uint32_t*>(&t);
}
__device__ __forceinline__ uint32_t packres(float x, float y, uint32_t h) {
    __nv_bfloat162 hh = *reinterpret_cast<__nv_bfloat162*>(&h);
    return packbf(x - __bfloat162float(hh.x), y - __bfloat162float(hh.y));
}
__device__ __forceinline__ uint32_t packh(float x, float y) {
    __half2 t = __floats2half2_rn(x, y);
    return *reinterpret_cast<uint32_t*>(&t);
}
__device__ __forceinline__ void split2(float v, __nv_bfloat16& hi, __nv_bfloat16& lo) {
    hi = __float2bfloat16(v);
    lo = __float2bfloat16(v - __bfloat162float(hi));
}

// ---------------- packing kernels ----------------
__global__ void split_x(const float* __restrict__ x,
                        __nv_bfloat16* __restrict__ hi, __nv_bfloat16* __restrict__ lo, int n) {
    int i = blockIdx.x * blockDim.x + threadIdx.x;
    if (i >= n) return;
    split2(x[i], hi[i], lo[i]);
}

__global__ void pack_qkv_t(const float* __restrict__ Wq, const float* __restrict__ Wk,
                           const float* __restrict__ Wv,
                           __nv_bfloat16* __restrict__ hi, __nv_bfloat16* __restrict__ lo) {
    __shared__ float ts[64][65];
    const int tid = threadIdx.x;
    const int kb = blockIdx.x, hid = blockIdx.y, wh = blockIdx.z;
    const float* src = (wh == 0) ? Wq : (wh == 1) ? Wk : Wv;
    const float sc = (wh == 0) ? QSCALE2 : 1.0f;

#pragma unroll
    for (int p = 0; p < 16; p++) {
        int kr = (tid >> 6) + p * 4;
        int i  = tid & 63;
        ts[kr][i] = src[(size_t)hid * (EMB * HDIM) + (size_t)(kb * 64 + kr) * HDIM + i];
    }
    __syncthreads();
#pragma unroll
    for (int p = 0; p < 16; p++) {
        int i = (tid >> 6) + p * 4;
        int k = tid & 63;
        float v = ts[k][i] * sc;
        size_t o = ((size_t)(wh * 1024 + hid * 64 + i) << 10) + kb * 64 + k;
        split2(v, hi[o], lo[o]);
    }
}

__global__ void pack_wo(const float* __restrict__ Wo,
                        __half* __restrict__ hi, __half* __restrict__ lo) {
    int idx = blockIdx.x * blockDim.x + threadIdx.x;
    if (idx >= EMB * EMB) return;
    float w = Wo[idx];
    __half h = __float2half(w);
    hi[idx] = h;
    lo[idx] = __float2half(w - __half2float(h));
}

// ---------------- GEMM1: QKV = x * W^T, bf16 3-pass, 3-stage pipeline ----------------
#define GTILE  8192
#define GSTAGE 32768
#define GNC    (KDIM/32)

__global__ __launch_bounds__(256, 2)
void gemm_qkv(const __nv_bfloat16* __restrict__ Ah, const __nv_bfloat16* __restrict__ Al,
              const __nv_bfloat16* __restrict__ Bh, const __nv_bfloat16* __restrict__ Bl,
              __nv_bfloat16* __restrict__ Ch, __nv_bfloat16* __restrict__ Cl, int N) {
    extern __shared__ __align__(16) char smraw[];
    uint32_t smb = cvta_smem(smraw);
    const int tid = threadIdx.x, lane = tid & 31, wid = tid >> 5;
    const int wm = wid & 3, wn = wid >> 2;
    const int nb = blockIdx.x, mb = blockIdx.y;

    const __nv_bfloat16* gsrc[4] = {
        Ah + (size_t)mb * 128 * KDIM, Al + (size_t)mb * 128 * KDIM,
        Bh + (size_t)nb * 128 * KDIM, Bl + (size_t)nb * 128 * KDIM };

    auto ldchunk = [&](int buf, int ck) {
        uint32_t bb = smb + buf * GSTAGE;
#pragma unroll
        for (int q = 0; q < 8; q++) {
            int i = q * 256 + tid;
            int t = i >> 9;
            int r = (i >> 2) & 127;
            int c16 = i & 3;
            uint32_t dst = bb + t * GTILE + r * 64 + ((c16 ^ ((r >> 1) & 3)) << 4);
            cp16(dst, gsrc[t] + (size_t)r * KDIM + ck * 32 + c16 * 8);
        }
    };

    ldchunk(0, 0); CP_COMMIT();
    ldchunk(1, 1); CP_COMMIT();

    float acc[2][8][4];
#pragma unroll
    for (int a = 0; a < 2; a++)
#pragma unroll
        for (int b = 0; b < 8; b++)
#pragma unroll
            for (int c = 0; c < 4; c++) acc[a][b][c] = 0.f;

    int buf = 0, rb = 2;
    for (int c = 0; c < GNC; c++) {
        if (c + 1 < GNC) CP_WAIT1(); else CP_WAIT0();
        __syncthreads();
        if (c + 2 < GNC) {
            ldchunk(rb, c + 2); CP_COMMIT();
            rb = (rb == 2) ? 0 : rb + 1;
        }
        uint32_t bb = smb + buf * GSTAGE;

#pragma unroll
        for (int s = 0; s < 2; s++) {
            uint32_t ah[2][4], al[2][4];
#pragma unroll
            for (int mt = 0; mt < 2; mt++) {
                uint32_t row = 32 * wm + 16 * mt + ((lane >> 3) & 1) * 8 + (lane & 7);
                uint32_t kb  = (lane >> 4) * 16 + s * 32;
                uint32_t ad  = bb + row * 64 + ((((kb >> 4)) ^ ((row >> 1) & 3)) << 4);
                ldsm4(ah[mt][0], ah[mt][1], ah[mt][2], ah[mt][3], ad);
                ldsm4(al[mt][0], al[mt][1], al[mt][2], al[mt][3], ad + GTILE);
            }
#pragma unroll
            for (int np = 0; np < 4; np++) {
                uint32_t row = 64 * wn + 16 * np + ((lane >> 4) & 1) * 8 + (lane & 7);
                uint32_t kb  = ((lane >> 3) & 1) * 16 + s * 32;
                uint32_t bd  = bb + 2 * GTILE + row * 64 + ((((kb >> 4)) ^ ((row >> 1) & 3)) << 4);
                uint32_t bh0, bh1, bh2, bh3, bl0, bl1, bl2, bl3;
                ldsm4(bh0, bh1, bh2, bh3, bd);
                ldsm4(bl0, bl1, bl2, bl3, bd + GTILE);
#pragma unroll
                for (int p = 0; p < 3; p++) {
                    const uint32_t* a0 = (p == 1) ? al[0] : ah[0];
                    const uint32_t* a1 = (p == 1) ? al[1] : ah[1];
                    uint32_t c0 = (p == 2) ? bl0 : bh0, c1 = (p == 2) ? bl1 : bh1;
                    uint32_t c2 = (p == 2) ? bl2 : bh2, c3 = (p == 2) ? bl3 : bh3;
                    mma_bf(acc[0][2 * np],     a0, c0, c1);
                    mma_bf(acc[1][2 * np],     a1, c0, c1);
                    mma_bf(acc[0][2 * np + 1], a0, c2, c3);
                    mma_bf(acc[1][2 * np + 1], a1, c2, c3);
                }
            }
        }
        buf = (buf == 2) ? 0 : buf + 1;
    }

    const int grp = lane >> 2, qr = lane & 3;
    const bool vpart = (nb >= 16);   // V columns -> single fp16
#pragma unroll
    for (int mt = 0; mt < 2; mt++) {
        size_t r0 = (size_t)mb * 128 + 32 * wm + 16 * mt + grp;
#pragma unroll
        for (int nt = 0; nt < 8; nt++) {
            int col = nb * 128 + 64 * wn + 8 * nt + 2 * qr;
            float* c4 = acc[mt][nt];
            if (vpart) {
                *(uint32_t*)&Ch[r0 * N + col]       = packh(c4[0], c4[1]);
                *(uint32_t*)&Ch[(r0 + 8) * N + col] = packh(c4[2], c4[3]);
            } else {
                uint32_t h0 = packbf(c4[0], c4[1]), l0 = packres(c4[0], c4[1], h0);
                uint32_t h1 = packbf(c4[2], c4[3]), l1 = packres(c4[2], c4[3], h1);
                *(uint32_t*)&Ch[r0 * N + col]       = h0;
                *(uint32_t*)&Cl[r0 * N + col]       = l0;
                *(uint32_t*)&Ch[(r0 + 8) * N + col] = h1;
                *(uint32_t*)&Cl[(r0 + 8) * N + col] = l1;
            }
        }
    }
}

// ---------------- GEMM2: out = attended * Wo^T, fp16 2-pass, 4-stage ----------------
#define GOTILE  8192
#define GOSTAGE 24576     /* A, Bh, Bl */

__global__ __launch_bounds__(256, 2)
void gemm_o(const __half* __restrict__ A, const __half* __restrict__ Bh,
            const __half* __restrict__ Bl, float* __restrict__ C, int N) {
    extern __shared__ __align__(16) char smraw[];
    uint32_t smb = cvta_smem(smraw);
    const int tid = threadIdx.x, lane = tid & 31, wid = tid >> 5;
    const int wm = wid & 3, wn = wid >> 2;
    const int nb = blockIdx.x, mb = blockIdx.y;

    const __half* gsrc[3] = {
        A + (size_t)mb * 128 * KDIM,
        Bh + (size_t)nb * 128 * KDIM, Bl + (size_t)nb * 128 * KDIM };

    auto ldchunk = [&](int buf, int ck) {
        uint32_t bb = smb + buf * GOSTAGE;
#pragma unroll
        for (int q = 0; q < 6; q++) {
            int i = q * 256 + tid;          // 0..1535
            int t = i >> 9;
            int r = (i >> 2) & 127;
            int c16 = i & 3;
            uint32_t dst = bb + t * GOTILE + r * 64 + ((c16 ^ ((r >> 1) & 3)) << 4);
            cp16(dst, gsrc[t] + (size_t)r * KDIM + ck * 32 + c16 * 8);
        }
    };

    ldchunk(0, 0); CP_COMMIT();
    ldchunk(1, 1); CP_COMMIT();
    ldchunk(2, 2); CP_COMMIT();

    float acc[2][8][4];
#pragma unroll
    for (int a = 0; a < 2; a++)
#pragma unroll
        for (int b = 0; b < 8; b++)
#pragma unroll
            for (int c = 0; c < 4; c++) acc[a][b][c] = 0.f;

    int rb = 3;
    for (int c = 0; c < GNC; c++) {
        int rem = GNC - c;
        if (rem >= 3) CP_WAIT2(); else if (rem == 2) CP_WAIT1(); else CP_WAIT0();
        __syncthreads();
        if (c + 3 < GNC) {
            ldchunk(rb, c + 3); CP_COMMIT();
            rb = (rb + 1) & 3;
        }
        uint32_t bb = smb + (c & 3) * GOSTAGE;

#pragma unroll
        for (int s = 0; s < 2; s++) {
            uint32_t ah[2][4];
#pragma unroll
            for (int mt = 0; mt < 2; mt++) {
                uint32_t row = 32 * wm + 16 * mt + ((lane >> 3) & 1) * 8 + (lane & 7);
                uint32_t kb  = (lane >> 4) * 16 + s * 32;
                uint32_t ad  = bb + row * 64 + ((((kb >> 4)) ^ ((row >> 1) & 3)) << 4);
                ldsm4(ah[mt][0], ah[mt][1], ah[mt][2], ah[mt][3], ad);
            }
#pragma unroll
            for (int np = 0; np < 4; np++) {
                uint32_t row = 64 * wn + 16 * np + ((lane >> 4) & 1) * 8 + (lane & 7);
                uint32_t kb  = ((lane >> 3) & 1) * 16 + s * 32;
                uint32_t bd  = bb + GOTILE + row * 64 + ((((kb >> 4)) ^ ((row >> 1) & 3)) << 4);
                uint32_t bh0, bh1, bh2, bh3, bl0, bl1, bl2, bl3;
                ldsm4(bh0, bh1, bh2, bh3, bd);
                ldsm4(bl0, bl1, bl2, bl3, bd + GOTILE);
#pragma unroll
                for (int p = 0; p < 2; p++) {
                    uint32_t c0 = p ? bl0 : bh0, c1 = p ? bl1 : bh1;
                    uint32_t c2 = p ? bl2 : bh2, c3 = p ? bl3 : bh3;
                    mma_hf(acc[0][2 * np],     ah[0], c0, c1);
                    mma_hf(acc[1][2 * np],     ah[1], c0, c1);
                    mma_hf(acc[0][2 * np + 1], ah[0], c2, c3);
                    mma_hf(acc[1][2 * np + 1], ah[1], c2, c3);
                }
            }
        }
    }

    const int grp = lane >> 2, qr = lane & 3;
#pragma unroll
    for (int mt = 0; mt < 2; mt++) {
        size_t r0 = (size_t)mb * 128 + 32 * wm + 16 * mt + grp;
#pragma unroll
        for (int nt = 0; nt < 8; nt++) {
            int col = nb * 128 + 64 * wn + 8 * nt + 2 * qr;
            float* c4 = acc[mt][nt];
            *(float2*)&C[r0 * N + col]       = make_float2(c4[0], c4[1]);
            *(float2*)&C[(r0 + 8) * N + col] = make_float2(c4[2], c4[3]);
        }
    }
}

// ---------------- Flash attention: S bf16 3-pass; PV fp16 single; 4-stage ----------------
#define FPITCH 144
#define FTILE  9216
#define FSTAGE 27648
#define NKT    (SEQ/64)

__global__ __launch_bounds__(256, 2)
void flash_mma(const __nv_bfloat16* __restrict__ Qh, const __nv_bfloat16* __restrict__ Ql,
               __half* __restrict__ Out) {
    extern __shared__ __align__(16) char smraw[];
    uint32_t smb = cvta_smem(smraw);

    const int tid = threadIdx.x, lane = tid & 31, w = tid >> 5;
    const int grp = lane >> 2, qr = lane & 3;
    const int qt = blockIdx.x, h = blockIdx.y, b = blockIdx.z;

    const size_t batch_row = (size_t)b * SEQ;

    const __nv_bfloat16* kvsrc[3] = {
        Qh + batch_row * QKVN + EMB + h * HDIM,          // Kh (bf16)
        Ql + batch_row * QKVN + EMB + h * HDIM,          // Kl (bf16)
        Qh + batch_row * QKVN + 2 * EMB + h * HDIM };    // Vh (fp16 bits)

    auto ldtile = [&](int bf, int kt) {
        uint32_t bb = smb + bf * FSTAGE;
        size_t rbase = (size_t)kt * 64;
#pragma unroll
        for (int q = 0; q < 6; q++) {
            int i = q * 256 + tid;
            int t = i >> 9;
            int r = (i >> 3) & 63;
            int sg = i & 7;
            cp16(bb + t * FTILE + r * FPITCH + sg * 16,
                 kvsrc[t] + (rbase + r) * QKVN + sg * 8);
        }
    };

    uint32_t qh[4][4], ql[4][4];
    {
        size_t r0 = batch_row + (size_t)qt * 128 + w * 16 + grp;
        const __nv_bfloat16* qb_h = Qh + r0 * QKVN + h * HDIM;
        const __nv_bfloat16* qb_l = Ql + r0 * QKVN + h * HDIM;
#pragma unroll
        for (int t = 0; t < 4; t++) {
            int c0 = t * 16 + 2 * qr;
            qh[t][0] = *(const uint32_t*)(qb_h + c0);
            qh[t][1] = *(const uint32_t*)(qb_h + 8 * QKVN + c0);
            qh[t][2] = *(const uint32_t*)(qb_h + c0 + 8);
            qh[t][3] = *(const uint32_t*)(qb_h + 8 * QKVN + c0 + 8);
            ql[t][0] = *(const uint32_t*)(qb_l + c0);
            ql[t][1] = *(const uint32_t*)(qb_l + 8 * QKVN + c0);
            ql[t][2] = *(const uint32_t*)(qb_l + c0 + 8);
            ql[t][3] = *(const uint32_t*)(qb_l + 8 * QKVN + c0 + 8);
        }
    }

    float o[8][4];
#pragma unroll
    for (int j = 0; j < 8; j++)
#pragma unroll
        for (int c = 0; c < 4; c++) o[j][c] = 0.f;
    float m0 = -1e30f, m1 = -1e30f, l0 = 0.f, l1 = 0.f;

    ldtile(0, 0); CP_COMMIT();
    ldtile(1, 1); CP_COMMIT();
    ldtile(2, 2); CP_COMMIT();

    int rb = 3;
    for (int kt = 0; kt < NKT; kt++) {
        int rem = NKT - kt;
        if (rem >= 3) CP_WAIT2(); else if (rem == 2) CP_WAIT1(); else CP_WAIT0();
        __syncthreads();
        if (kt + 3 < NKT) {
            ldtile(rb, kt + 3); CP_COMMIT();
            rb = (rb + 1) & 3;
        }
        uint32_t sb  = smb + (kt & 3) * FSTAGE;
        uint32_t khb = sb, vhb = sb + 2 * FTILE;

        // ---- S = Q K^T (16 x 64 per warp), bf16 3-pass ----
        float s[8][4];
#pragma unroll
        for (int j = 0; j < 8; j++) {
            uint32_t ka = khb + (8 * j + (lane & 7)) * FPITCH + (lane >> 3) * 16;
            uint32_t la = ka + FTILE;
            uint32_t h0, h1, h2, h3, h4, h5, h6, h7;
            uint32_t e0, e1, e2, e3, e4, e5, e6, e7;
            ldsm4(h0, h1, h2, h3, ka);
            ldsm4(h4, h5, h6, h7, ka + 64);
            ldsm4(e0, e1, e2, e3, la);
            ldsm4(e4, e5, e6, e7, la + 64);
            s[j][0] = s[j][1] = s[j][2] = s[j][3] = 0.f;
            mma_bf(s[j], qh[0], h0, h1); mma_bf(s[j], ql[0], h0, h1); mma_bf(s[j], qh[0], e0, e1);
            mma_bf(s[j], qh[1], h2, h3); mma_bf(s[j], ql[1], h2, h3); mma_bf(s[j], qh[1], e2, e3);
            mma_bf(s[j], qh[2], h4, h5); mma_bf(s[j], ql[2], h4, h5); mma_bf(s[j], qh[2], e4, e5);
            mma_bf(s[j], qh[3], h6, h7); mma_bf(s[j], ql[3], h6, h7); mma_bf(s[j], qh[3], e6, e7);
        }

        // ---- online softmax (exp2 domain; lazy l: per-lane partial sums) ----
        float n0 = m0, n1 = m1;
#pragma unroll
        for (int j = 0; j < 8; j++) {
            n0 = fmaxf(n0, fmaxf(s[j][0], s[j][1]));
            n1 = fmaxf(n1, fmaxf(s[j][2], s[j][3]));
        }
        n0 = fmaxf(n0, __shfl_xor_sync(0xffffffffu, n0, 1));
        n0 = fmaxf(n0, __shfl_xor_sync(0xffffffffu, n0, 2));
        n1 = fmaxf(n1, __shfl_xor_sync(0xffffffffu, n1, 1));
        n1 = fmaxf(n1, __shfl_xor_sync(0xffffffffu, n1, 2));
        float a0 = ex2(m0 - n0), a1 = ex2(m1 - n1);
        m0 = n0; m1 = n1;
        float rs0 = 0.f, rs1 = 0.f;
#pragma unroll
        for (int j = 0; j < 8; j++) {
            s[j][0] = ex2(s[j][0] - n0); rs0 += s[j][0];
            s[j][1] = ex2(s[j][1] - n0); rs0 += s[j][1];
            s[j][2] = ex2(s[j][2] - n1); rs1 += s[j][2];
            s[j][3] = ex2(s[j][3] - n1); rs1 += s[j][3];
        }
        l0 = l0 * a0 + rs0;     // per-lane partial; reduced once in epilogue
        l1 = l1 * a1 + rs1;
#pragma unroll
        for (int j = 0; j < 8; j++) {
            o[j][0] *= a0; o[j][1] *= a0; o[j][2] *= a1; o[j][3] *= a1;
        }

        // ---- O += P V : fp16 single-pass ----
#pragma unroll
        for (int kcp = 0; kcp < 2; kcp++) {
            uint32_t ph[2][4];
#pragma unroll
            for (int u = 0; u < 2; u++) {
                int nt = 4 * kcp + 2 * u;
                ph[u][0] = packh(s[nt][0],     s[nt][1]);
                ph[u][1] = packh(s[nt][2],     s[nt][3]);
                ph[u][2] = packh(s[nt + 1][0], s[nt + 1][1]);
                ph[u][3] = packh(s[nt + 1][2], s[nt + 1][3]);
            }
#pragma unroll
            for (int j2 = 0; j2 < 8; j2++) {
                uint32_t va = vhb + (32 * kcp + lane) * FPITCH + j2 * 16;
                uint32_t v0, v1, v2, v3;
                ldsm4t(v0, v1, v2, v3, va);
                mma_hf(o[j2], ph[0], v0, v1);
                mma_hf(o[j2], ph[1], v2, v3);
            }
        }
    }

    // ---- epilogue: reduce l across quad, normalize, fp16 store ----
    l0 += __shfl_xor_sync(0xffffffffu, l0, 1);
    l0 += __shfl_xor_sync(0xffffffffu, l0, 2);
    l1 += __shfl_xor_sync(0xffffffffu, l1, 1);
    l1 += __shfl_xor_sync(0xffffffffu, l1, 2);
    float inv0 = 1.f / l0, inv1 = 1.f / l1;
    size_t r0 = batch_row + (size_t)qt * 128 + w * 16 + grp;
#pragma unroll
    for (int j2 = 0; j2 < 8; j2++) {
        int c = h * HDIM + 8 * j2 + 2 * qr;
        *(uint32_t*)&Out[r0 * EMB + c]       = packh(o[j2][0] * inv0, o[j2][1] * inv0);
        *(uint32_t*)&Out[(r0 + 8) * EMB + c] = packh(o[j2][2] * inv1, o[j2][3] * inv1);
    }
}

// ------------------------------------------------------------------
extern "C" void kernel_launch(void* const* d_in, const int* in_sizes, int n_in,
                              void* d_out, int out_size) {
    const float* x  = (const float*)d_in[0];
    const float* Wq = (const float*)d_in[1];
    const float* Wk = (const float*)d_in[2];
    const float* Wv = (const float*)d_in[3];
    const float* Wo = (const float*)d_in[4];
    float* out = (float*)d_out;

    __nv_bfloat16 *gxh, *gxl, *gBqh, *gBql, *gQh, *gQl;
    __half *gBoh, *gBol, *gAt;
    cudaGetSymbolAddress((void**)&gxh,  g_xh);
    cudaGetSymbolAddress((void**)&gxl,  g_xl);
    cudaGetSymbolAddress((void**)&gBqh, g_Bqh);
    cudaGetSymbolAddress((void**)&gBql, g_Bql);
    cudaGetSymbolAddress((void**)&gBoh, g_Boh);
    cudaGetSymbolAddress((void**)&gBol, g_Bol);
    cudaGetSymbolAddress((void**)&gQh,  g_QKVh);
    cudaGetSymbolAddress((void**)&gQl,  g_QKVl);
    cudaGetSymbolAddress((void**)&gAt,  g_At);

    const int G1SMEM = 3 * GSTAGE;     // 98304
    const int G2SMEM = 4 * GOSTAGE;    // 98304
    const int FSMEM  = 4 * FSTAGE;     // 110592
    cudaFuncSetAttribute(gemm_qkv, cudaFuncAttributeMaxDynamicSharedMemorySize, G1SMEM);
    cudaFuncSetAttribute(gemm_o,   cudaFuncAttributeMaxDynamicSharedMemorySize, G2SMEM);
    cudaFuncSetAttribute(flash_mma, cudaFuncAttributeMaxDynamicSharedMemorySize, FSMEM);

    split_x<<<(MROWS * EMB + 255) / 256, 256>>>(x, gxh, gxl, MROWS * EMB);
    pack_qkv_t<<<dim3(16, 16, 3), 256>>>(Wq, Wk, Wv, gBqh, gBql);
    pack_wo<<<(EMB * EMB + 255) / 256, 256>>>(Wo, gBoh, gBol);

    gemm_qkv<<<dim3(QKVN / 128, MROWS / 128), 256, G1SMEM>>>(
        gxh, gxl, gBqh, gBql, gQh, gQl, QKVN);

    flash_mma<<<dim3(SEQ / 128, HEADS, BATCH), 256, FSMEM>>>(gQh, gQl, gAt);

    gemm_o<<<dim3(EMB / 128, MROWS / 128), 256, G2SMEM>>>(
        gAt, gBoh, gBol, out, EMB);
}

// round 9
// speedup vs baseline: 4.5043x; 1.0582x over previous
#include <cuda_runtime.h>
#include <cuda_bf16.h>
#include <cuda_fp16.h>
#include <stdint.h>
#include <math.h>

#define BATCH 2
#define SEQ   2048
#define EMB   1024
#define HEADS 16
#define HDIM  64
#define MROWS (BATCH*SEQ)   /* 4096 */
#define QKVN  (3*EMB)       /* 3072 */
#define KDIM  EMB

#define QSCALE  0.02209708691207961f
#define QSCALE2 (QSCALE * 1.4426950408889634f)

// ---------------- scratch ----------------
__device__ __align__(256) __nv_bfloat16 g_xh [(size_t)MROWS*EMB];
__device__ __align__(256) __nv_bfloat16 g_xl [(size_t)MROWS*EMB];
__device__ __align__(256) __half        g_xf [(size_t)MROWS*EMB];
__device__ __align__(256) __nv_bfloat16 g_Bqh[(size_t)2*EMB*EMB];   /* Q,K weights hi */
__device__ __align__(256) __nv_bfloat16 g_Bql[(size_t)2*EMB*EMB];   /* Q,K weights lo */
__device__ __align__(256) __half        g_Bvf[(size_t)EMB*EMB];     /* V weights fp16 */
__device__ __align__(256) __half        g_Boh[(size_t)EMB*EMB];
__device__ __align__(256) __half        g_Bol[(size_t)EMB*EMB];
__device__ __align__(256) __nv_bfloat16 g_QKVh[(size_t)MROWS*QKVN];  /* V region = fp16 bits */
__device__ __align__(256) __nv_bfloat16 g_QKVl[(size_t)MROWS*QKVN];
__device__ __align__(256) __half        g_At [(size_t)MROWS*EMB];

// ---------------- helpers ----------------
__device__ __forceinline__ uint32_t cvta_smem(const void* p) {
    uint32_t a;
    asm("{ .reg .u64 t; cvta.to.shared.u64 t, %1; cvt.u32.u64 %0, t; }" : "=r"(a) : "l"(p));
    return a;
}
__device__ __forceinline__ void cp16(uint32_t dst, const void* src) {
    asm volatile("cp.async.cg.shared.global [%0], [%1], 16;" :: "r"(dst), "l"(src));
}
#define CP_COMMIT() asm volatile("cp.async.commit_group;" ::: "memory")
#define CP_WAIT2()  asm volatile("cp.async.wait_group 2;" ::: "memory")
#define CP_WAIT1()  asm volatile("cp.async.wait_group 1;" ::: "memory")
#define CP_WAIT0()  asm volatile("cp.async.wait_group 0;" ::: "memory")

__device__ __forceinline__ void ldsm4(uint32_t& r0, uint32_t& r1, uint32_t& r2, uint32_t& r3,
                                      uint32_t addr) {
    asm volatile("ldmatrix.sync.aligned.m8n8.x4.shared.b16 {%0,%1,%2,%3},[%4];"
                 : "=r"(r0), "=r"(r1), "=r"(r2), "=r"(r3) : "r"(addr));
}
__device__ __forceinline__ void ldsm4t(uint32_t& r0, uint32_t& r1, uint32_t& r2, uint32_t& r3,
                                       uint32_t addr) {
    asm volatile("ldmatrix.sync.aligned.m8n8.x4.trans.shared.b16 {%0,%1,%2,%3},[%4];"
                 : "=r"(r0), "=r"(r1), "=r"(r2), "=r"(r3) : "r"(addr));
}
__device__ __forceinline__ void mma_bf(float c[4], const uint32_t a[4], uint32_t b0, uint32_t b1) {
    asm("mma.sync.aligned.m16n8k16.row.col.f32.bf16.bf16.f32 "
        "{%0,%1,%2,%3}, {%4,%5,%6,%7}, {%8,%9}, {%0,%1,%2,%3};"
        : "+f"(c[0]), "+f"(c[1]), "+f"(c[2]), "+f"(c[3])
        : "r"(a[0]), "r"(a[1]), "r"(a[2]), "r"(a[3]), "r"(b0), "r"(b1));
}
__device__ __forceinline__ void mma_hf(float c[4], const uint32_t a[4], uint32_t b0, uint32_t b1) {
    asm("mma.sync.aligned.m16n8k16.row.col.f32.f16.f16.f32 "
        "{%0,%1,%2,%3}, {%4,%5,%6,%7}, {%8,%9}, {%0,%1,%2,%3};"
        : "+f"(c[0]), "+f"(c[1]), "+f"(c[2]), "+f"(c[3])
        : "r"(a[0]), "r"(a[1]), "r"(a[2]), "r"(a[3]), "r"(b0), "r"(b1));
}
__device__ __forceinline__ float ex2(float x) {
    float r;
    asm("ex2.approx.ftz.f32 %0, %1;" : "=f"(r) : "f"(x));
    return r;
}
__device__ __forceinline__ uint32_t packbf(float x, float y) {
    __nv_bfloat162 t = __floats2bfloat162_rn(x, y);
    return *reinterpret_cast<uint32_t*>(&t);
}
__device__ __forceinline__ uint32_t packres(float x, float y, uint32_t h) {
    __nv_bfloat162 hh = *reinterpret_cast<__nv_bfloat162*>(&h);
    return packbf(x - __bfloat162float(hh.x), y - __bfloat162float(hh.y));
}
__device__ __forceinline__ uint32_t packh(float x, float y) {
    __half2 t = __floats2half2_rn(x, y);
    return *reinterpret_cast<uint32_t*>(&t);
}
__device__ __forceinline__ void split2(float v, __nv_bfloat16& hi, __nv_bfloat16& lo) {
    hi = __float2bfloat16(v);
    lo = __float2bfloat16(v - __bfloat162float(hi));
}

// ---------------- packing kernels ----------------
__global__ void split_x(const float* __restrict__ x, __nv_bfloat16* __restrict__ hi,
                        __nv_bfloat16* __restrict__ lo, __half* __restrict__ hf, int n) {
    int i = blockIdx.x * blockDim.x + threadIdx.x;
    if (i >= n) return;
    float v = x[i];
    split2(v, hi[i], lo[i]);
    hf[i] = __float2half(v);
}

__global__ void pack_qkv_t(const float* __restrict__ Wq, const float* __restrict__ Wk,
                           const float* __restrict__ Wv,
                           __nv_bfloat16* __restrict__ hi, __nv_bfloat16* __restrict__ lo,
                           __half* __restrict__ vf) {
    __shared__ float ts[64][65];
    const int tid = threadIdx.x;
    const int kb = blockIdx.x, hid = blockIdx.y, wh = blockIdx.z;
    const float* src = (wh == 0) ? Wq : (wh == 1) ? Wk : Wv;
    const float sc = (wh == 0) ? QSCALE2 : 1.0f;

#pragma unroll
    for (int p = 0; p < 16; p++) {
        int kr = (tid >> 6) + p * 4;
        int i  = tid & 63;
        ts[kr][i] = src[(size_t)hid * (EMB * HDIM) + (size_t)(kb * 64 + kr) * HDIM + i];
    }
    __syncthreads();
#pragma unroll
    for (int p = 0; p < 16; p++) {
        int i = (tid >> 6) + p * 4;
        int k = tid & 63;
        float v = ts[k][i] * sc;
        if (wh == 2) {
            size_t o = ((size_t)(hid * 64 + i) << 10) + kb * 64 + k;
            vf[o] = __float2half(v);
        } else {
            size_t o = ((size_t)(wh * 1024 + hid * 64 + i) << 10) + kb * 64 + k;
            split2(v, hi[o], lo[o]);
        }
    }
}

__global__ void pack_wo(const float* __restrict__ Wo,
                        __half* __restrict__ hi, __half* __restrict__ lo) {
    int idx = blockIdx.x * blockDim.x + threadIdx.x;
    if (idx >= EMB * EMB) return;
    float w = Wo[idx];
    __half h = __float2half(w);
    hi[idx] = h;
    lo[idx] = __float2half(w - __half2float(h));
}

// ---------------- GEMM-QK: [4096,1024]x[2048,1024]^T, bf16 3-pass, 3-stage ----------------
#define GTILE  8192
#define GSTAGE 32768
#define GNC    (KDIM/32)

__global__ __launch_bounds__(256, 2)
void gemm_qk(const __nv_bfloat16* __restrict__ Ah, const __nv_bfloat16* __restrict__ Al,
             const __nv_bfloat16* __restrict__ Bh, const __nv_bfloat16* __restrict__ Bl,
             __nv_bfloat16* __restrict__ Ch, __nv_bfloat16* __restrict__ Cl) {
    extern __shared__ __align__(16) char smraw[];
    uint32_t smb = cvta_smem(smraw);
    const int tid = threadIdx.x, lane = tid & 31, wid = tid >> 5;
    const int wm = wid & 3, wn = wid >> 2;
    const int nb = blockIdx.x, mb = blockIdx.y;

    const __nv_bfloat16* gsrc[4] = {
        Ah + (size_t)mb * 128 * KDIM, Al + (size_t)mb * 128 * KDIM,
        Bh + (size_t)nb * 128 * KDIM, Bl + (size_t)nb * 128 * KDIM };

    auto ldchunk = [&](int buf, int ck) {
        uint32_t bb = smb + buf * GSTAGE;
#pragma unroll
        for (int q = 0; q < 8; q++) {
            int i = q * 256 + tid;
            int t = i >> 9;
            int r = (i >> 2) & 127;
            int c16 = i & 3;
            uint32_t dst = bb + t * GTILE + r * 64 + ((c16 ^ ((r >> 1) & 3)) << 4);
            cp16(dst, gsrc[t] + (size_t)r * KDIM + ck * 32 + c16 * 8);
        }
    };

    ldchunk(0, 0); CP_COMMIT();
    ldchunk(1, 1); CP_COMMIT();

    float acc[2][8][4];
#pragma unroll
    for (int a = 0; a < 2; a++)
#pragma unroll
        for (int b = 0; b < 8; b++)
#pragma unroll
            for (int c = 0; c < 4; c++) acc[a][b][c] = 0.f;

    int buf = 0, rb = 2;
    for (int c = 0; c < GNC; c++) {
        if (c + 1 < GNC) CP_WAIT1(); else CP_WAIT0();
        __syncthreads();
        if (c + 2 < GNC) {
            ldchunk(rb, c + 2); CP_COMMIT();
            rb = (rb == 2) ? 0 : rb + 1;
        }
        uint32_t bb = smb + buf * GSTAGE;

#pragma unroll
        for (int s = 0; s < 2; s++) {
            uint32_t ah[2][4], al[2][4];
#pragma unroll
            for (int mt = 0; mt < 2; mt++) {
                uint32_t row = 32 * wm + 16 * mt + ((lane >> 3) & 1) * 8 + (lane & 7);
                uint32_t kb  = (lane >> 4) * 16 + s * 32;
                uint32_t ad  = bb + row * 64 + ((((kb >> 4)) ^ ((row >> 1) & 3)) << 4);
                ldsm4(ah[mt][0], ah[mt][1], ah[mt][2], ah[mt][3], ad);
                ldsm4(al[mt][0], al[mt][1], al[mt][2], al[mt][3], ad + GTILE);
            }
#pragma unroll
            for (int np = 0; np < 4; np++) {
                uint32_t row = 64 * wn + 16 * np + ((lane >> 4) & 1) * 8 + (lane & 7);
                uint32_t kb  = ((lane >> 3) & 1) * 16 + s * 32;
                uint32_t bd  = bb + 2 * GTILE + row * 64 + ((((kb >> 4)) ^ ((row >> 1) & 3)) << 4);
                uint32_t bh0, bh1, bh2, bh3, bl0, bl1, bl2, bl3;
                ldsm4(bh0, bh1, bh2, bh3, bd);
                ldsm4(bl0, bl1, bl2, bl3, bd + GTILE);
#pragma unroll
                for (int p = 0; p < 3; p++) {
                    const uint32_t* a0 = (p == 1) ? al[0] : ah[0];
                    const uint32_t* a1 = (p == 1) ? al[1] : ah[1];
                    uint32_t c0 = (p == 2) ? bl0 : bh0, c1 = (p == 2) ? bl1 : bh1;
                    uint32_t c2 = (p == 2) ? bl2 : bh2, c3 = (p == 2) ? bl3 : bh3;
                    mma_bf(acc[0][2 * np],     a0, c0, c1);
                    mma_bf(acc[1][2 * np],     a1, c0, c1);
                    mma_bf(acc[0][2 * np + 1], a0, c2, c3);
                    mma_bf(acc[1][2 * np + 1], a1, c2, c3);
                }
            }
        }
        buf = (buf == 2) ? 0 : buf + 1;
    }

    const int grp = lane >> 2, qr = lane & 3;
#pragma unroll
    for (int mt = 0; mt < 2; mt++) {
        size_t r0 = (size_t)mb * 128 + 32 * wm + 16 * mt + grp;
#pragma unroll
        for (int nt = 0; nt < 8; nt++) {
            int col = nb * 128 + 64 * wn + 8 * nt + 2 * qr;
            float* c4 = acc[mt][nt];
            uint32_t h0 = packbf(c4[0], c4[1]), l0 = packres(c4[0], c4[1], h0);
            uint32_t h1 = packbf(c4[2], c4[3]), l1 = packres(c4[2], c4[3], h1);
            *(uint32_t*)&Ch[r0 * QKVN + col]       = h0;
            *(uint32_t*)&Cl[r0 * QKVN + col]       = l0;
            *(uint32_t*)&Ch[(r0 + 8) * QKVN + col] = h1;
            *(uint32_t*)&Cl[(r0 + 8) * QKVN + col] = l1;
        }
    }
}

// ---------------- GEMM-V: [4096,1024]x[1024,1024]^T, fp16 1-pass, 4-stage ----------------
#define GVSTAGE 16384    /* A tile + B tile */

__global__ __launch_bounds__(256, 2)
void gemm_v(const __half* __restrict__ A, const __half* __restrict__ B,
            __half* __restrict__ C) {
    extern __shared__ __align__(16) char smraw[];
    uint32_t smb = cvta_smem(smraw);
    const int tid = threadIdx.x, lane = tid & 31, wid = tid >> 5;
    const int wm = wid & 3, wn = wid >> 2;
    const int nb = blockIdx.x, mb = blockIdx.y;

    const __half* gsrc[2] = { A + (size_t)mb * 128 * KDIM, B + (size_t)nb * 128 * KDIM };

    auto ldchunk = [&](int buf, int ck) {
        uint32_t bb = smb + buf * GVSTAGE;
#pragma unroll
        for (int q = 0; q < 4; q++) {
            int i = q * 256 + tid;          // 0..1023
            int t = i >> 9;
            int r = (i >> 2) & 127;
            int c16 = i & 3;
            uint32_t dst = bb + t * GTILE + r * 64 + ((c16 ^ ((r >> 1) & 3)) << 4);
            cp16(dst, gsrc[t] + (size_t)r * KDIM + ck * 32 + c16 * 8);
        }
    };

    ldchunk(0, 0); CP_COMMIT();
    ldchunk(1, 1); CP_COMMIT();
    ldchunk(2, 2); CP_COMMIT();

    float acc[2][8][4];
#pragma unroll
    for (int a = 0; a < 2; a++)
#pragma unroll
        for (int b = 0; b < 8; b++)
#pragma unroll
            for (int c = 0; c < 4; c++) acc[a][b][c] = 0.f;

    int rb = 3;
    for (int c = 0; c < GNC; c++) {
        int rem = GNC - c;
        if (rem >= 3) CP_WAIT2(); else if (rem == 2) CP_WAIT1(); else CP_WAIT0();
        __syncthreads();
        if (c + 3 < GNC) {
            ldchunk(rb, c + 3); CP_COMMIT();
            rb = (rb + 1) & 3;
        }
        uint32_t bb = smb + (c & 3) * GVSTAGE;

#pragma unroll
        for (int s = 0; s < 2; s++) {
            uint32_t ah[2][4];
#pragma unroll
            for (int mt = 0; mt < 2; mt++) {
                uint32_t row = 32 * wm + 16 * mt + ((lane >> 3) & 1) * 8 + (lane & 7);
                uint32_t kb  = (lane >> 4) * 16 + s * 32;
                uint32_t ad  = bb + row * 64 + ((((kb >> 4)) ^ ((row >> 1) & 3)) << 4);
                ldsm4(ah[mt][0], ah[mt][1], ah[mt][2], ah[mt][3], ad);
            }
#pragma unroll
            for (int np = 0; np < 4; np++) {
                uint32_t row = 64 * wn + 16 * np + ((lane >> 4) & 1) * 8 + (lane & 7);
                uint32_t kb  = ((lane >> 3) & 1) * 16 + s * 32;
                uint32_t bd  = bb + GTILE + row * 64 + ((((kb >> 4)) ^ ((row >> 1) & 3)) << 4);
                uint32_t b0, b1, b2, b3;
                ldsm4(b0, b1, b2, b3, bd);
                mma_hf(acc[0][2 * np],     ah[0], b0, b1);
                mma_hf(acc[1][2 * np],     ah[1], b0, b1);
                mma_hf(acc[0][2 * np + 1], ah[0], b2, b3);
                mma_hf(acc[1][2 * np + 1], ah[1], b2, b3);
            }
        }
    }

    const int grp = lane >> 2, qr = lane & 3;
#pragma unroll
    for (int mt = 0; mt < 2; mt++) {
        size_t r0 = (size_t)mb * 128 + 32 * wm + 16 * mt + grp;
#pragma unroll
        for (int nt = 0; nt < 8; nt++) {
            int col = nb * 128 + 64 * wn + 8 * nt + 2 * qr;
            float* c4 = acc[mt][nt];
            *(uint32_t*)&C[r0 * QKVN + col]       = packh(c4[0], c4[1]);
            *(uint32_t*)&C[(r0 + 8) * QKVN + col] = packh(c4[2], c4[3]);
        }
    }
}

// ---------------- GEMM-O: out = attended * Wo^T, fp16 2-pass, 4-stage ----------------
#define GOTILE  8192
#define GOSTAGE 24576

__global__ __launch_bounds__(256, 2)
void gemm_o(const __half* __restrict__ A, const __half* __restrict__ Bh,
            const __half* __restrict__ Bl, float* __restrict__ C, int N) {
    extern __shared__ __align__(16) char smraw[];
    uint32_t smb = cvta_smem(smraw);
    const int tid = threadIdx.x, lane = tid & 31, wid = tid >> 5;
    const int wm = wid & 3, wn = wid >> 2;
    const int nb = blockIdx.x, mb = blockIdx.y;

    const __half* gsrc[3] = {
        A + (size_t)mb * 128 * KDIM,
        Bh + (size_t)nb * 128 * KDIM, Bl + (size_t)nb * 128 * KDIM };

    auto ldchunk = [&](int buf, int ck) {
        uint32_t bb = smb + buf * GOSTAGE;
#pragma unroll
        for (int q = 0; q < 6; q++) {
            int i = q * 256 + tid;
            int t = i >> 9;
            int r = (i >> 2) & 127;
            int c16 = i & 3;
            uint32_t dst = bb + t * GOTILE + r * 64 + ((c16 ^ ((r >> 1) & 3)) << 4);
            cp16(dst, gsrc[t] + (size_t)r * KDIM + ck * 32 + c16 * 8);
        }
    };

    ldchunk(0, 0); CP_COMMIT();
    ldchunk(1, 1); CP_COMMIT();
    ldchunk(2, 2); CP_COMMIT();

    float acc[2][8][4];
#pragma unroll
    for (int a = 0; a < 2; a++)
#pragma unroll
        for (int b = 0; b < 8; b++)
#pragma unroll
            for (int c = 0; c < 4; c++) acc[a][b][c] = 0.f;

    int rb = 3;
    for (int c = 0; c < GNC; c++) {
        int rem = GNC - c;
        if (rem >= 3) CP_WAIT2(); else if (rem == 2) CP_WAIT1(); else CP_WAIT0();
        __syncthreads();
        if (c + 3 < GNC) {
            ldchunk(rb, c + 3); CP_COMMIT();
            rb = (rb + 1) & 3;
        }
        uint32_t bb = smb + (c & 3) * GOSTAGE;

#pragma unroll
        for (int s = 0; s < 2; s++) {
            uint32_t ah[2][4];
#pragma unroll
            for (int mt = 0; mt < 2; mt++) {
                uint32_t row = 32 * wm + 16 * mt + ((lane >> 3) & 1) * 8 + (lane & 7);
                uint32_t kb  = (lane >> 4) * 16 + s * 32;
                uint32_t ad  = bb + row * 64 + ((((kb >> 4)) ^ ((row >> 1) & 3)) << 4);
                ldsm4(ah[mt][0], ah[mt][1], ah[mt][2], ah[mt][3], ad);
            }
#pragma unroll
            for (int np = 0; np < 4; np++) {
                uint32_t row = 64 * wn + 16 * np + ((lane >> 4) & 1) * 8 + (lane & 7);
                uint32_t kb  = ((lane >> 3) & 1) * 16 + s * 32;
                uint32_t bd  = bb + GOTILE + row * 64 + ((((kb >> 4)) ^ ((row >> 1) & 3)) << 4);
                uint32_t bh0, bh1, bh2, bh3, bl0, bl1, bl2, bl3;
                ldsm4(bh0, bh1, bh2, bh3, bd);
                ldsm4(bl0, bl1, bl2, bl3, bd + GOTILE);
#pragma unroll
                for (int p = 0; p < 2; p++) {
                    uint32_t c0 = p ? bl0 : bh0, c1 = p ? bl1 : bh1;
                    uint32_t c2 = p ? bl2 : bh2, c3 = p ? bl3 : bh3;
                    mma_hf(acc[0][2 * np],     ah[0], c0, c1);
                    mma_hf(acc[1][2 * np],     ah[1], c0, c1);
                    mma_hf(acc[0][2 * np + 1], ah[0], c2, c3);
                    mma_hf(acc[1][2 * np + 1], ah[1], c2, c3);
                }
            }
        }
    }

    const int grp = lane >> 2, qr = lane & 3;
#pragma unroll
    for (int mt = 0; mt < 2; mt++) {
        size_t r0 = (size_t)mb * 128 + 32 * wm + 16 * mt + grp;
#pragma unroll
        for (int nt = 0; nt < 8; nt++) {
            int col = nb * 128 + 64 * wn + 8 * nt + 2 * qr;
            float* c4 = acc[mt][nt];
            *(float2*)&C[r0 * N + col]       = make_float2(c4[0], c4[1]);
            *(float2*)&C[(r0 + 8) * N + col] = make_float2(c4[2], c4[3]);
        }
    }
}

// ---------------- Flash attention: S bf16 3-pass; PV fp16 single; 4-stage ----------------
#define FPITCH 144
#define FTILE  9216
#define FSTAGE 27648
#define NKT    (SEQ/64)

__global__ __launch_bounds__(256, 2)
void flash_mma(const __nv_bfloat16* __restrict__ Qh, const __nv_bfloat16* __restrict__ Ql,
               __half* __restrict__ Out) {
    extern __shared__ __align__(16) char smraw[];
    uint32_t smb = cvta_smem(smraw);

    const int tid = threadIdx.x, lane = tid & 31, w = tid >> 5;
    const int grp = lane >> 2, qr = lane & 3;
    const int qt = blockIdx.x, h = blockIdx.y, b = blockIdx.z;

    const size_t batch_row = (size_t)b * SEQ;

    const __nv_bfloat16* kvsrc[3] = {
        Qh + batch_row * QKVN + EMB + h * HDIM,
        Ql + batch_row * QKVN + EMB + h * HDIM,
        Qh + batch_row * QKVN + 2 * EMB + h * HDIM };

    auto ldtile = [&](int bf, int kt) {
        uint32_t bb = smb + bf * FSTAGE;
        size_t rbase = (size_t)kt * 64;
#pragma unroll
        for (int q = 0; q < 6; q++) {
            int i = q * 256 + tid;
            int t = i >> 9;
            int r = (i >> 3) & 63;
            int sg = i & 7;
            cp16(bb + t * FTILE + r * FPITCH + sg * 16,
                 kvsrc[t] + (rbase + r) * QKVN + sg * 8);
        }
    };

    uint32_t qh[4][4], ql[4][4];
    {
        size_t r0 = batch_row + (size_t)qt * 128 + w * 16 + grp;
        const __nv_bfloat16* qb_h = Qh + r0 * QKVN + h * HDIM;
        const __nv_bfloat16* qb_l = Ql + r0 * QKVN + h * HDIM;
#pragma unroll
        for (int t = 0; t < 4; t++) {
            int c0 = t * 16 + 2 * qr;
            qh[t][0] = *(const uint32_t*)(qb_h + c0);
            qh[t][1] = *(const uint32_t*)(qb_h + 8 * QKVN + c0);
            qh[t][2] = *(const uint32_t*)(qb_h + c0 + 8);
            qh[t][3] = *(const uint32_t*)(qb_h + 8 * QKVN + c0 + 8);
            ql[t][0] = *(const uint32_t*)(qb_l + c0);
            ql[t][1] = *(const uint32_t*)(qb_l + 8 * QKVN + c0);
            ql[t][2] = *(const uint32_t*)(qb_l + c0 + 8);
            ql[t][3] = *(const uint32_t*)(qb_l + 8 * QKVN + c0 + 8);
        }
    }

    float o[8][4];
#pragma unroll
    for (int j = 0; j < 8; j++)
#pragma unroll
        for (int c = 0; c < 4; c++) o[j][c] = 0.f;
    float m0 = -1e30f, m1 = -1e30f, l0 = 0.f, l1 = 0.f;

    ldtile(0, 0); CP_COMMIT();
    ldtile(1, 1); CP_COMMIT();
    ldtile(2, 2); CP_COMMIT();

    int rb = 3;
    for (int kt = 0; kt < NKT; kt++) {
        int rem = NKT - kt;
        if (rem >= 3) CP_WAIT2(); else if (rem == 2) CP_WAIT1(); else CP_WAIT0();
        __syncthreads();
        if (kt + 3 < NKT) {
            ldtile(rb, kt + 3); CP_COMMIT();
            rb = (rb + 1) & 3;
        }
        uint32_t sb  = smb + (kt & 3) * FSTAGE;
        uint32_t khb = sb, vhb = sb + 2 * FTILE;

        float s[8][4];
#pragma unroll
        for (int j = 0; j < 8; j++) {
            uint32_t ka = khb + (8 * j + (lane & 7)) * FPITCH + (lane >> 3) * 16;
            uint32_t la = ka + FTILE;
            uint32_t h0, h1, h2, h3, h4, h5, h6, h7;
            uint32_t e0, e1, e2, e3, e4, e5, e6, e7;
            ldsm4(h0, h1, h2, h3, ka);
            ldsm4(h4, h5, h6, h7, ka + 64);
            ldsm4(e0, e1, e2, e3, la);
            ldsm4(e4, e5, e6, e7, la + 64);
            s[j][0] = s[j][1] = s[j][2] = s[j][3] = 0.f;
            mma_bf(s[j], qh[0], h0, h1); mma_bf(s[j], ql[0], h0, h1); mma_bf(s[j], qh[0], e0, e1);
            mma_bf(s[j], qh[1], h2, h3); mma_bf(s[j], ql[1], h2, h3); mma_bf(s[j], qh[1], e2, e3);
            mma_bf(s[j], qh[2], h4, h5); mma_bf(s[j], ql[2], h4, h5); mma_bf(s[j], qh[2], e4, e5);
            mma_bf(s[j], qh[3], h6, h7); mma_bf(s[j], ql[3], h6, h7); mma_bf(s[j], qh[3], e6, e7);
        }

        float n0 = m0, n1 = m1;
#pragma unroll
        for (int j = 0; j < 8; j++) {
            n0 = fmaxf(n0, fmaxf(s[j][0], s[j][1]));
            n1 = fmaxf(n1, fmaxf(s[j][2], s[j][3]));
        }
        n0 = fmaxf(n0, __shfl_xor_sync(0xffffffffu, n0, 1));
        n0 = fmaxf(n0, __shfl_xor_sync(0xffffffffu, n0, 2));
        n1 = fmaxf(n1, __shfl_xor_sync(0xffffffffu, n1, 1));
        n1 = fmaxf(n1, __shfl_xor_sync(0xffffffffu, n1, 2));
        float a0 = ex2(m0 - n0), a1 = ex2(m1 - n1);
        m0 = n0; m1 = n1;
        float rs0 = 0.f, rs1 = 0.f;
#pragma unroll
        for (int j = 0; j < 8; j++) {
            s[j][0] = ex2(s[j][0] - n0); rs0 += s[j][0];
            s[j][1] = ex2(s[j][1] - n0); rs0 += s[j][1];
            s[j][2] = ex2(s[j][2] - n1); rs1 += s[j][2];
            s[j][3] = ex2(s[j][3] - n1); rs1 += s[j][3];
        }
        l0 = l0 * a0 + rs0;
        l1 = l1 * a1 + rs1;
#pragma unroll
        for (int j = 0; j < 8; j++) {
            o[j][0] *= a0; o[j][1] *= a0; o[j][2] *= a1; o[j][3] *= a1;
        }

#pragma unroll
        for (int kcp = 0; kcp < 2; kcp++) {
            uint32_t ph[2][4];
#pragma unroll
            for (int u = 0; u < 2; u++) {
                int nt = 4 * kcp + 2 * u;
                ph[u][0] = packh(s[nt][0],     s[nt][1]);
                ph[u][1] = packh(s[nt][2],     s[nt][3]);
                ph[u][2] = packh(s[nt + 1][0], s[nt + 1][1]);
                ph[u][3] = packh(s[nt + 1][2], s[nt + 1][3]);
            }
#pragma unroll
            for (int j2 = 0; j2 < 8; j2++) {
                uint32_t va = vhb + (32 * kcp + lane) * FPITCH + j2 * 16;
                uint32_t v0, v1, v2, v3;
                ldsm4t(v0, v1, v2, v3, va);
                mma_hf(o[j2], ph[0], v0, v1);
                mma_hf(o[j2], ph[1], v2, v3);
            }
        }
    }

    l0 += __shfl_xor_sync(0xffffffffu, l0, 1);
    l0 += __shfl_xor_sync(0xffffffffu, l0, 2);
    l1 += __shfl_xor_sync(0xffffffffu, l1, 1);
    l1 += __shfl_xor_sync(0xffffffffu, l1, 2);
    float inv0 = 1.f / l0, inv1 = 1.f / l1;
    size_t r0 = batch_row + (size_t)qt * 128 + w * 16 + grp;
#pragma unroll
    for (int j2 = 0; j2 < 8; j2++) {
        int c = h * HDIM + 8 * j2 + 2 * qr;
        *(uint32_t*)&Out[r0 * EMB + c]       = packh(o[j2][0] * inv0, o[j2][1] * inv0);
        *(uint32_t*)&Out[(r0 + 8) * EMB + c] = packh(o[j2][2] * inv1, o[j2][3] * inv1);
    }
}

// ------------------------------------------------------------------
extern "C" void kernel_launch(void* const* d_in, const int* in_sizes, int n_in,
                              void* d_out, int out_size) {
    const float* x  = (const float*)d_in[0];
    const float* Wq = (const float*)d_in[1];
    const float* Wk = (const float*)d_in[2];
    const float* Wv = (const float*)d_in[3];
    const float* Wo = (const float*)d_in[4];
    float* out = (float*)d_out;

    __nv_bfloat16 *gxh, *gxl, *gBqh, *gBql, *gQh, *gQl;
    __half *gxf, *gBvf, *gBoh, *gBol, *gAt;
    cudaGetSymbolAddress((void**)&gxh,  g_xh);
    cudaGetSymbolAddress((void**)&gxl,  g_xl);
    cudaGetSymbolAddress((void**)&gxf,  g_xf);
    cudaGetSymbolAddress((void**)&gBqh, g_Bqh);
    cudaGetSymbolAddress((void**)&gBql, g_Bql);
    cudaGetSymbolAddress((void**)&gBvf, g_Bvf);
    cudaGetSymbolAddress((void**)&gBoh, g_Boh);
    cudaGetSymbolAddress((void**)&gBol, g_Bol);
    cudaGetSymbolAddress((void**)&gQh,  g_QKVh);
    cudaGetSymbolAddress((void**)&gQl,  g_QKVl);
    cudaGetSymbolAddress((void**)&gAt,  g_At);

    const int GQKSMEM = 3 * GSTAGE;     // 98304
    const int GVSMEM  = 4 * GVSTAGE;    // 65536
    const int GOSMEM  = 4 * GOSTAGE;    // 98304
    const int FSMEM   = 4 * FSTAGE;     // 110592
    cudaFuncSetAttribute(gemm_qk,  cudaFuncAttributeMaxDynamicSharedMemorySize, GQKSMEM);
    cudaFuncSetAttribute(gemm_v,   cudaFuncAttributeMaxDynamicSharedMemorySize, GVSMEM);
    cudaFuncSetAttribute(gemm_o,   cudaFuncAttributeMaxDynamicSharedMemorySize, GOSMEM);
    cudaFuncSetAttribute(flash_mma, cudaFuncAttributeMaxDynamicSharedMemorySize, FSMEM);

    split_x<<<(MROWS * EMB + 255) / 256, 256>>>(x, gxh, gxl, gxf, MROWS * EMB);
    pack_qkv_t<<<dim3(16, 16, 3), 256>>>(Wq, Wk, Wv, gBqh, gBql, gBvf);
    pack_wo<<<(EMB * EMB + 255) / 256, 256>>>(Wo, gBoh, gBol);

    // Q,K projection (bf16 3-pass), cols [0,2048)
    gemm_qk<<<dim3(16, MROWS / 128), 256, GQKSMEM>>>(gxh, gxl, gBqh, gBql, gQh, gQl);

    // V projection (fp16 1-pass), cols [2048,3072) — fp16 bits into V region of g_QKVh
    gemm_v<<<dim3(8, MROWS / 128), 256, GVSMEM>>>(
        gxf, gBvf, reinterpret_cast<__half*>(gQh) + 2 * EMB);

    // attention
    flash_mma<<<dim3(SEQ / 128, HEADS, BATCH), 256, FSMEM>>>(gQh, gQl, gAt);

    // output projection (fp16 2-pass)
    gemm_o<<<dim3(EMB / 128, MROWS / 128), 256, GOSMEM>>>(gAt, gBoh, gBol, out, EMB);
}

// round 11
// speedup vs baseline: 4.5679x; 1.0141x over previous
#include <cuda_runtime.h>
#include <cuda_bf16.h>
#include <cuda_fp16.h>
#include <stdint.h>
#include <math.h>

#define BATCH 2
#define SEQ   2048
#define EMB   1024
#define HEADS 16
#define HDIM  64
#define MROWS (BATCH*SEQ)   /* 4096 */
#define QKVN  (3*EMB)       /* 3072 */
#define KDIM  EMB

#define QSCALE  0.02209708691207961f
#define QSCALE2 (QSCALE * 1.4426950408889634f)
#define SKIP_T  25.0f       /* exp2-domain skip threshold: dropped mass < 2048*2^-25 ~ 6e-5 */

// ---------------- scratch ----------------
__device__ __align__(256) __nv_bfloat16 g_xh [(size_t)MROWS*EMB];
__device__ __align__(256) __nv_bfloat16 g_xl [(size_t)MROWS*EMB];
__device__ __align__(256) __half        g_xf [(size_t)MROWS*EMB];
__device__ __align__(256) __nv_bfloat16 g_Bqh[(size_t)2*EMB*EMB];
__device__ __align__(256) __nv_bfloat16 g_Bql[(size_t)2*EMB*EMB];
__device__ __align__(256) __half        g_Bvf[(size_t)EMB*EMB];
__device__ __align__(256) __half        g_Boh[(size_t)EMB*EMB];
__device__ __align__(256) __half        g_Bol[(size_t)EMB*EMB];
__device__ __align__(256) __nv_bfloat16 g_QKVh[(size_t)MROWS*QKVN];  /* V region = fp16 bits */
__device__ __align__(256) __nv_bfloat16 g_QKVl[(size_t)MROWS*QKVN];
__device__ __align__(256) __half        g_At [(size_t)MROWS*EMB];

// ---------------- helpers ----------------
__device__ __forceinline__ uint32_t cvta_smem(const void* p) {
    uint32_t a;
    asm("{ .reg .u64 t; cvta.to.shared.u64 t, %1; cvt.u32.u64 %0, t; }" : "=r"(a) : "l"(p));
    return a;
}
__device__ __forceinline__ void cp16(uint32_t dst, const void* src) {
    asm volatile("cp.async.cg.shared.global [%0], [%1], 16;" :: "r"(dst), "l"(src));
}
#define CP_COMMIT() asm volatile("cp.async.commit_group;" ::: "memory")
#define CP_WAIT2()  asm volatile("cp.async.wait_group 2;" ::: "memory")
#define CP_WAIT1()  asm volatile("cp.async.wait_group 1;" ::: "memory")
#define CP_WAIT0()  asm volatile("cp.async.wait_group 0;" ::: "memory")

__device__ __forceinline__ void ldsm4(uint32_t& r0, uint32_t& r1, uint32_t& r2, uint32_t& r3,
                                      uint32_t addr) {
    asm volatile("ldmatrix.sync.aligned.m8n8.x4.shared.b16 {%0,%1,%2,%3},[%4];"
                 : "=r"(r0), "=r"(r1), "=r"(r2), "=r"(r3) : "r"(addr));
}
__device__ __forceinline__ void ldsm4t(uint32_t& r0, uint32_t& r1, uint32_t& r2, uint32_t& r3,
                                       uint32_t addr) {
    asm volatile("ldmatrix.sync.aligned.m8n8.x4.trans.shared.b16 {%0,%1,%2,%3},[%4];"
                 : "=r"(r0), "=r"(r1), "=r"(r2), "=r"(r3) : "r"(addr));
}
__device__ __forceinline__ void mma_bf(float c[4], const uint32_t a[4], uint32_t b0, uint32_t b1) {
    asm("mma.sync.aligned.m16n8k16.row.col.f32.bf16.bf16.f32 "
        "{%0,%1,%2,%3}, {%4,%5,%6,%7}, {%8,%9}, {%0,%1,%2,%3};"
        : "+f"(c[0]), "+f"(c[1]), "+f"(c[2]), "+f"(c[3])
        : "r"(a[0]), "r"(a[1]), "r"(a[2]), "r"(a[3]), "r"(b0), "r"(b1));
}
__device__ __forceinline__ void mma_hf(float c[4], const uint32_t a[4], uint32_t b0, uint32_t b1) {
    asm("mma.sync.aligned.m16n8k16.row.col.f32.f16.f16.f32 "
        "{%0,%1,%2,%3}, {%4,%5,%6,%7}, {%8,%9}, {%0,%1,%2,%3};"
        : "+f"(c[0]), "+f"(c[1]), "+f"(c[2]), "+f"(c[3])
        : "r"(a[0]), "r"(a[1]), "r"(a[2]), "r"(a[3]), "r"(b0), "r"(b1));
}
__device__ __forceinline__ float ex2(float x) {
    float r;
    asm("ex2.approx.ftz.f32 %0, %1;" : "=f"(r) : "f"(x));
    return r;
}
__device__ __forceinline__ uint32_t packbf(float x, float y) {
    __nv_bfloat162 t = __floats2bfloat162_rn(x, y);
    return *reinterpret_cast<uint32_t*>(&t);
}
__device__ __forceinline__ uint32_t packres(float x, float y, uint32_t h) {
    __nv_bfloat162 hh = *reinterpret_cast<__nv_bfloat162*>(&h);
    return packbf(x - __bfloat162float(hh.x), y - __bfloat162float(hh.y));
}
__device__ __forceinline__ uint32_t packh(float x, float y) {
    __half2 t = __floats2half2_rn(x, y);
    return *reinterpret_cast<uint32_t*>(&t);
}
__device__ __forceinline__ void split2(float v, __nv_bfloat16& hi, __nv_bfloat16& lo) {
    hi = __float2bfloat16(v);
    lo = __float2bfloat16(v - __bfloat162float(hi));
}

// ---------------- packing kernels ----------------
__global__ void split_x(const float* __restrict__ x, __nv_bfloat16* __restrict__ hi,
                        __nv_bfloat16* __restrict__ lo, __half* __restrict__ hf, int n) {
    int i = blockIdx.x * blockDim.x + threadIdx.x;
    if (i >= n) return;
    float v = x[i];
    split2(v, hi[i], lo[i]);
    hf[i] = __float2half(v);
}

__global__ void pack_qkv_t(const float* __restrict__ Wq, const float* __restrict__ Wk,
                           const float* __restrict__ Wv,
                           __nv_bfloat16* __restrict__ hi, __nv_bfloat16* __restrict__ lo,
                           __half* __restrict__ vf) {
    __shared__ float ts[64][65];
    const int tid = threadIdx.x;
    const int kb = blockIdx.x, hid = blockIdx.y, wh = blockIdx.z;
    const float* src = (wh == 0) ? Wq : (wh == 1) ? Wk : Wv;
    const float sc = (wh == 0) ? QSCALE2 : 1.0f;

#pragma unroll
    for (int p = 0; p < 16; p++) {
        int kr = (tid >> 6) + p * 4;
        int i  = tid & 63;
        ts[kr][i] = src[(size_t)hid * (EMB * HDIM) + (size_t)(kb * 64 + kr) * HDIM + i];
    }
    __syncthreads();
#pragma unroll
    for (int p = 0; p < 16; p++) {
        int i = (tid >> 6) + p * 4;
        int k = tid & 63;
        float v = ts[k][i] * sc;
        if (wh == 2) {
            size_t o = ((size_t)(hid * 64 + i) << 10) + kb * 64 + k;
            vf[o] = __float2half(v);
        } else {
            size_t o = ((size_t)(wh * 1024 + hid * 64 + i) << 10) + kb * 64 + k;
            split2(v, hi[o], lo[o]);
        }
    }
}

__global__ void pack_wo(const float* __restrict__ Wo,
                        __half* __restrict__ hi, __half* __restrict__ lo) {
    int idx = blockIdx.x * blockDim.x + threadIdx.x;
    if (idx >= EMB * EMB) return;
    float w = Wo[idx];
    __half h = __float2half(w);
    hi[idx] = h;
    lo[idx] = __float2half(w - __half2float(h));
}

// ---------------- GEMM-QK: bf16 3-pass, 3-stage ----------------
#define GTILE  8192
#define GSTAGE 32768
#define GNC    (KDIM/32)

__global__ __launch_bounds__(256, 2)
void gemm_qk(const __nv_bfloat16* __restrict__ Ah, const __nv_bfloat16* __restrict__ Al,
             const __nv_bfloat16* __restrict__ Bh, const __nv_bfloat16* __restrict__ Bl,
             __nv_bfloat16* __restrict__ Ch, __nv_bfloat16* __restrict__ Cl) {
    extern __shared__ __align__(16) char smraw[];
    uint32_t smb = cvta_smem(smraw);
    const int tid = threadIdx.x, lane = tid & 31, wid = tid >> 5;
    const int wm = wid & 3, wn = wid >> 2;
    const int nb = blockIdx.x, mb = blockIdx.y;

    const __nv_bfloat16* gsrc[4] = {
        Ah + (size_t)mb * 128 * KDIM, Al + (size_t)mb * 128 * KDIM,
        Bh + (size_t)nb * 128 * KDIM, Bl + (size_t)nb * 128 * KDIM };

    auto ldchunk = [&](int buf, int ck) {
        uint32_t bb = smb + buf * GSTAGE;
#pragma unroll
        for (int q = 0; q < 8; q++) {
            int i = q * 256 + tid;
            int t = i >> 9;
            int r = (i >> 2) & 127;
            int c16 = i & 3;
            uint32_t dst = bb + t * GTILE + r * 64 + ((c16 ^ ((r >> 1) & 3)) << 4);
            cp16(dst, gsrc[t] + (size_t)r * KDIM + ck * 32 + c16 * 8);
        }
    };

    ldchunk(0, 0); CP_COMMIT();
    ldchunk(1, 1); CP_COMMIT();

    float acc[2][8][4];
#pragma unroll
    for (int a = 0; a < 2; a++)
#pragma unroll
        for (int b = 0; b < 8; b++)
#pragma unroll
            for (int c = 0; c < 4; c++) acc[a][b][c] = 0.f;

    int buf = 0, rb = 2;
    for (int c = 0; c < GNC; c++) {
        if (c + 1 < GNC) CP_WAIT1(); else CP_WAIT0();
        __syncthreads();
        if (c + 2 < GNC) {
            ldchunk(rb, c + 2); CP_COMMIT();
            rb = (rb == 2) ? 0 : rb + 1;
        }
        uint32_t bb = smb + buf * GSTAGE;

#pragma unroll
        for (int s = 0; s < 2; s++) {
            uint32_t ah[2][4], al[2][4];
#pragma unroll
            for (int mt = 0; mt < 2; mt++) {
                uint32_t row = 32 * wm + 16 * mt + ((lane >> 3) & 1) * 8 + (lane & 7);
                uint32_t kb  = (lane >> 4) * 16 + s * 32;
                uint32_t ad  = bb + row * 64 + ((((kb >> 4)) ^ ((row >> 1) & 3)) << 4);
                ldsm4(ah[mt][0], ah[mt][1], ah[mt][2], ah[mt][3], ad);
                ldsm4(al[mt][0], al[mt][1], al[mt][2], al[mt][3], ad + GTILE);
            }
#pragma unroll
            for (int np = 0; np < 4; np++) {
                uint32_t row = 64 * wn + 16 * np + ((lane >> 4) & 1) * 8 + (lane & 7);
                uint32_t kb  = ((lane >> 3) & 1) * 16 + s * 32;
                uint32_t bd  = bb + 2 * GTILE + row * 64 + ((((kb >> 4)) ^ ((row >> 1) & 3)) << 4);
                uint32_t bh0, bh1, bh2, bh3, bl0, bl1, bl2, bl3;
                ldsm4(bh0, bh1, bh2, bh3, bd);
                ldsm4(bl0, bl1, bl2, bl3, bd + GTILE);
#pragma unroll
                for (int p = 0; p < 3; p++) {
                    const uint32_t* a0 = (p == 1) ? al[0] : ah[0];
                    const uint32_t* a1 = (p == 1) ? al[1] : ah[1];
                    uint32_t c0 = (p == 2) ? bl0 : bh0, c1 = (p == 2) ? bl1 : bh1;
                    uint32_t c2 = (p == 2) ? bl2 : bh2, c3 = (p == 2) ? bl3 : bh3;
                    mma_bf(acc[0][2 * np],     a0, c0, c1);
                    mma_bf(acc[1][2 * np],     a1, c0, c1);
                    mma_bf(acc[0][2 * np + 1], a0, c2, c3);
                    mma_bf(acc[1][2 * np + 1], a1, c2, c3);
                }
            }
        }
        buf = (buf == 2) ? 0 : buf + 1;
    }

    const int grp = lane >> 2, qr = lane & 3;
#pragma unroll
    for (int mt = 0; mt < 2; mt++) {
        size_t r0 = (size_t)mb * 128 + 32 * wm + 16 * mt + grp;
#pragma unroll
        for (int nt = 0; nt < 8; nt++) {
            int col = nb * 128 + 64 * wn + 8 * nt + 2 * qr;
            float* c4 = acc[mt][nt];
            uint32_t h0 = packbf(c4[0], c4[1]), l0 = packres(c4[0], c4[1], h0);
            uint32_t h1 = packbf(c4[2], c4[3]), l1 = packres(c4[2], c4[3], h1);
            *(uint32_t*)&Ch[r0 * QKVN + col]       = h0;
            *(uint32_t*)&Cl[r0 * QKVN + col]       = l0;
            *(uint32_t*)&Ch[(r0 + 8) * QKVN + col] = h1;
            *(uint32_t*)&Cl[(r0 + 8) * QKVN + col] = l1;
        }
    }
}

// ---------------- GEMM-V: fp16 1-pass, 4-stage ----------------
#define GVSTAGE 16384

__global__ __launch_bounds__(256, 2)
void gemm_v(const __half* __restrict__ A, const __half* __restrict__ B,
            __half* __restrict__ C) {
    extern __shared__ __align__(16) char smraw[];
    uint32_t smb = cvta_smem(smraw);
    const int tid = threadIdx.x, lane = tid & 31, wid = tid >> 5;
    const int wm = wid & 3, wn = wid >> 2;
    const int nb = blockIdx.x, mb = blockIdx.y;

    const __half* gsrc[2] = { A + (size_t)mb * 128 * KDIM, B + (size_t)nb * 128 * KDIM };

    auto ldchunk = [&](int buf, int ck) {
        uint32_t bb = smb + buf * GVSTAGE;
#pragma unroll
        for (int q = 0; q < 4; q++) {
            int i = q * 256 + tid;
            int t = i >> 9;
            int r = (i >> 2) & 127;
            int c16 = i & 3;
            uint32_t dst = bb + t * GTILE + r * 64 + ((c16 ^ ((r >> 1) & 3)) << 4);
            cp16(dst, gsrc[t] + (size_t)r * KDIM + ck * 32 + c16 * 8);
        }
    };

    ldchunk(0, 0); CP_COMMIT();
    ldchunk(1, 1); CP_COMMIT();
    ldchunk(2, 2); CP_COMMIT();

    float acc[2][8][4];
#pragma unroll
    for (int a = 0; a < 2; a++)
#pragma unroll
        for (int b = 0; b < 8; b++)
#pragma unroll
            for (int c = 0; c < 4; c++) acc[a][b][c] = 0.f;

    int rb = 3;
    for (int c = 0; c < GNC; c++) {
        int rem = GNC - c;
        if (rem >= 3) CP_WAIT2(); else if (rem == 2) CP_WAIT1(); else CP_WAIT0();
        __syncthreads();
        if (c + 3 < GNC) {
            ldchunk(rb, c + 3); CP_COMMIT();
            rb = (rb + 1) & 3;
        }
        uint32_t bb = smb + (c & 3) * GVSTAGE;

#pragma unroll
        for (int s = 0; s < 2; s++) {
            uint32_t ah[2][4];
#pragma unroll
            for (int mt = 0; mt < 2; mt++) {
                uint32_t row = 32 * wm + 16 * mt + ((lane >> 3) & 1) * 8 + (lane & 7);
                uint32_t kb  = (lane >> 4) * 16 + s * 32;
                uint32_t ad  = bb + row * 64 + ((((kb >> 4)) ^ ((row >> 1) & 3)) << 4);
                ldsm4(ah[mt][0], ah[mt][1], ah[mt][2], ah[mt][3], ad);
            }
#pragma unroll
            for (int np = 0; np < 4; np++) {
                uint32_t row = 64 * wn + 16 * np + ((lane >> 4) & 1) * 8 + (lane & 7);
                uint32_t kb  = ((lane >> 3) & 1) * 16 + s * 32;
                uint32_t bd  = bb + GTILE + row * 64 + ((((kb >> 4)) ^ ((row >> 1) & 3)) << 4);
                uint32_t b0, b1, b2, b3;
                ldsm4(b0, b1, b2, b3, bd);
                mma_hf(acc[0][2 * np],     ah[0], b0, b1);
                mma_hf(acc[1][2 * np],     ah[1], b0, b1);
                mma_hf(acc[0][2 * np + 1], ah[0], b2, b3);
                mma_hf(acc[1][2 * np + 1], ah[1], b2, b3);
            }
        }
    }

    const int grp = lane >> 2, qr = lane & 3;
#pragma unroll
    for (int mt = 0; mt < 2; mt++) {
        size_t r0 = (size_t)mb * 128 + 32 * wm + 16 * mt + grp;
#pragma unroll
        for (int nt = 0; nt < 8; nt++) {
            int col = nb * 128 + 64 * wn + 8 * nt + 2 * qr;
            float* c4 = acc[mt][nt];
            *(uint32_t*)&C[r0 * QKVN + col]       = packh(c4[0], c4[1]);
            *(uint32_t*)&C[(r0 + 8) * QKVN + col] = packh(c4[2], c4[3]);
        }
    }
}

// ---------------- GEMM-O: fp16 2-pass, 4-stage ----------------
#define GOTILE  8192
#define GOSTAGE 24576

__global__ __launch_bounds__(256, 2)
void gemm_o(const __half* __restrict__ A, const __half* __restrict__ Bh,
            const __half* __restrict__ Bl, float* __restrict__ C, int N) {
    extern __shared__ __align__(16) char smraw[];
    uint32_t smb = cvta_smem(smraw);
    const int tid = threadIdx.x, lane = tid & 31, wid = tid >> 5;
    const int wm = wid & 3, wn = wid >> 2;
    const int nb = blockIdx.x, mb = blockIdx.y;

    const __half* gsrc[3] = {
        A + (size_t)mb * 128 * KDIM,
        Bh + (size_t)nb * 128 * KDIM, Bl + (size_t)nb * 128 * KDIM };

    auto ldchunk = [&](int buf, int ck) {
        uint32_t bb = smb + buf * GOSTAGE;
#pragma unroll
        for (int q = 0; q < 6; q++) {
            int i = q * 256 + tid;
            int t = i >> 9;
            int r = (i >> 2) & 127;
            int c16 = i & 3;
            uint32_t dst = bb + t * GOTILE + r * 64 + ((c16 ^ ((r >> 1) & 3)) << 4);
            cp16(dst, gsrc[t] + (size_t)r * KDIM + ck * 32 + c16 * 8);
        }
    };

    ldchunk(0, 0); CP_COMMIT();
    ldchunk(1, 1); CP_COMMIT();
    ldchunk(2, 2); CP_COMMIT();

    float acc[2][8][4];
#pragma unroll
    for (int a = 0; a < 2; a++)
#pragma unroll
        for (int b = 0; b < 8; b++)
#pragma unroll
            for (int c = 0; c < 4; c++) acc[a][b][c] = 0.f;

    int rb = 3;
    for (int c = 0; c < GNC; c++) {
        int rem = GNC - c;
        if (rem >= 3) CP_WAIT2(); else if (rem == 2) CP_WAIT1(); else CP_WAIT0();
        __syncthreads();
        if (c + 3 < GNC) {
            ldchunk(rb, c + 3); CP_COMMIT();
            rb = (rb + 1) & 3;
        }
        uint32_t bb = smb + (c & 3) * GOSTAGE;

#pragma unroll
        for (int s = 0; s < 2; s++) {
            uint32_t ah[2][4];
#pragma unroll
            for (int mt = 0; mt < 2; mt++) {
                uint32_t row = 32 * wm + 16 * mt + ((lane >> 3) & 1) * 8 + (lane & 7);
                uint32_t kb  = (lane >> 4) * 16 + s * 32;
                uint32_t ad  = bb + row * 64 + ((((kb >> 4)) ^ ((row >> 1) & 3)) << 4);
                ldsm4(ah[mt][0], ah[mt][1], ah[mt][2], ah[mt][3], ad);
            }
#pragma unroll
            for (int np = 0; np < 4; np++) {
                uint32_t row = 64 * wn + 16 * np + ((lane >> 4) & 1) * 8 + (lane & 7);
                uint32_t kb  = ((lane >> 3) & 1) * 16 + s * 32;
                uint32_t bd  = bb + GOTILE + row * 64 + ((((kb >> 4)) ^ ((row >> 1) & 3)) << 4);
                uint32_t bh0, bh1, bh2, bh3, bl0, bl1, bl2, bl3;
                ldsm4(bh0, bh1, bh2, bh3, bd);
                ldsm4(bl0, bl1, bl2, bl3, bd + GOTILE);
#pragma unroll
                for (int p = 0; p < 2; p++) {
                    uint32_t c0 = p ? bl0 : bh0, c1 = p ? bl1 : bh1;
                    uint32_t c2 = p ? bl2 : bh2, c3 = p ? bl3 : bh3;
                    mma_hf(acc[0][2 * np],     ah[0], c0, c1);
                    mma_hf(acc[1][2 * np],     ah[1], c0, c1);
                    mma_hf(acc[0][2 * np + 1], ah[0], c2, c3);
                    mma_hf(acc[1][2 * np + 1], ah[1], c2, c3);
                }
            }
        }
    }

    const int grp = lane >> 2, qr = lane & 3;
#pragma unroll
    for (int mt = 0; mt < 2; mt++) {
        size_t r0 = (size_t)mb * 128 + 32 * wm + 16 * mt + grp;
#pragma unroll
        for (int nt = 0; nt < 8; nt++) {
            int col = nb * 128 + 64 * wn + 8 * nt + 2 * qr;
            float* c4 = acc[mt][nt];
            *(float2*)&C[r0 * N + col]       = make_float2(c4[0], c4[1]);
            *(float2*)&C[(r0 + 8) * N + col] = make_float2(c4[2], c4[3]);
        }
    }
}

// ---------------- Flash attention: warp-collective tile skipping ----------------
#define FPITCH 144
#define FTILE  9216
#define FSTAGE 27648
#define NKT    (SEQ/64)

__global__ __launch_bounds__(256, 2)
void flash_mma(const __nv_bfloat16* __restrict__ Qh, const __nv_bfloat16* __restrict__ Ql,
               __half* __restrict__ Out) {
    extern __shared__ __align__(16) char smraw[];
    uint32_t smb = cvta_smem(smraw);

    const int tid = threadIdx.x, lane = tid & 31, w = tid >> 5;
    const int grp = lane >> 2, qr = lane & 3;
    const int qt = blockIdx.x, h = blockIdx.y, b = blockIdx.z;

    const size_t batch_row = (size_t)b * SEQ;

    const __nv_bfloat16* kvsrc[3] = {
        Qh + batch_row * QKVN + EMB + h * HDIM,
        Ql + batch_row * QKVN + EMB + h * HDIM,
        Qh + batch_row * QKVN + 2 * EMB + h * HDIM };

    auto ldtile = [&](int bf, int kt) {
        uint32_t bb = smb + bf * FSTAGE;
        size_t rbase = (size_t)kt * 64;
#pragma unroll
        for (int q = 0; q < 6; q++) {
            int i = q * 256 + tid;
            int t = i >> 9;
            int r = (i >> 3) & 63;
            int sg = i & 7;
            cp16(bb + t * FTILE + r * FPITCH + sg * 16,
                 kvsrc[t] + (rbase + r) * QKVN + sg * 8);
        }
    };

    uint32_t qh[4][4], ql[4][4];
    {
        size_t r0 = batch_row + (size_t)qt * 128 + w * 16 + grp;
        const __nv_bfloat16* qb_h = Qh + r0 * QKVN + h * HDIM;
        const __nv_bfloat16* qb_l = Ql + r0 * QKVN + h * HDIM;
#pragma unroll
        for (int t = 0; t < 4; t++) {
            int c0 = t * 16 + 2 * qr;
            qh[t][0] = *(const uint32_t*)(qb_h + c0);
            qh[t][1] = *(const uint32_t*)(qb_h + 8 * QKVN + c0);
            qh[t][2] = *(const uint32_t*)(qb_h + c0 + 8);
            qh[t][3] = *(const uint32_t*)(qb_h + 8 * QKVN + c0 + 8);
            ql[t][0] = *(const uint32_t*)(qb_l + c0);
            ql[t][1] = *(const uint32_t*)(qb_l + 8 * QKVN + c0);
            ql[t][2] = *(const uint32_t*)(qb_l + c0 + 8);
            ql[t][3] = *(const uint32_t*)(qb_l + 8 * QKVN + c0 + 8);
        }
    }

    float o[8][4];
#pragma unroll
    for (int j = 0; j < 8; j++)
#pragma unroll
        for (int c = 0; c < 4; c++) o[j][c] = 0.f;
    float m0 = -1e30f, m1 = -1e30f, l0 = 0.f, l1 = 0.f;

    ldtile(0, 0); CP_COMMIT();
    ldtile(1, 1); CP_COMMIT();
    ldtile(2, 2); CP_COMMIT();

    int rb = 3;
    for (int kt = 0; kt < NKT; kt++) {
        int rem = NKT - kt;
        if (rem >= 3) CP_WAIT2(); else if (rem == 2) CP_WAIT1(); else CP_WAIT0();
        __syncthreads();
        if (kt + 3 < NKT) {
            ldtile(rb, kt + 3); CP_COMMIT();
            rb = (rb + 1) & 3;
        }
        uint32_t sb  = smb + (kt & 3) * FSTAGE;
        uint32_t khb = sb, vhb = sb + 2 * FTILE;

        // ---- S = Q K^T (16 x 64 per warp), bf16 3-pass ----
        float s[8][4];
#pragma unroll
        for (int j = 0; j < 8; j++) {
            uint32_t ka = khb + (8 * j + (lane & 7)) * FPITCH + (lane >> 3) * 16;
            uint32_t la = ka + FTILE;
            uint32_t h0, h1, h2, h3, h4, h5, h6, h7;
            uint32_t e0, e1, e2, e3, e4, e5, e6, e7;
            ldsm4(h0, h1, h2, h3, ka);
            ldsm4(h4, h5, h6, h7, ka + 64);
            ldsm4(e0, e1, e2, e3, la);
            ldsm4(e4, e5, e6, e7, la + 64);
            s[j][0] = s[j][1] = s[j][2] = s[j][3] = 0.f;
            mma_bf(s[j], qh[0], h0, h1); mma_bf(s[j], ql[0], h0, h1); mma_bf(s[j], qh[0], e0, e1);
            mma_bf(s[j], qh[1], h2, h3); mma_bf(s[j], ql[1], h2, h3); mma_bf(s[j], qh[1], e2, e3);
            mma_bf(s[j], qh[2], h4, h5); mma_bf(s[j], ql[2], h4, h5); mma_bf(s[j], qh[2], e4, e5);
            mma_bf(s[j], qh[3], h6, h7); mma_bf(s[j], ql[3], h6, h7); mma_bf(s[j], qh[3], e6, e7);
        }

        // ---- per-quad tile maxima ----
        float t0 = -1e30f, t1 = -1e30f;
#pragma unroll
        for (int j = 0; j < 8; j++) {
            t0 = fmaxf(t0, fmaxf(s[j][0], s[j][1]));
            t1 = fmaxf(t1, fmaxf(s[j][2], s[j][3]));
        }
        t0 = fmaxf(t0, __shfl_xor_sync(0xffffffffu, t0, 1));
        t0 = fmaxf(t0, __shfl_xor_sync(0xffffffffu, t0, 2));
        t1 = fmaxf(t1, __shfl_xor_sync(0xffffffffu, t1, 1));
        t1 = fmaxf(t1, __shfl_xor_sync(0xffffffffu, t1, 2));

        // ---- WARP-COLLECTIVE skip: all 32 lanes must agree (ldmatrix below is
        //      warp-synchronous; a divergent skip would hang) ----
        bool negl = (t0 < m0 - SKIP_T) && (t1 < m1 - SKIP_T);
        if (__all_sync(0xffffffffu, negl)) continue;

        bool newmax = (t0 > m0) || (t1 > m1);
        float n0 = fmaxf(m0, t0), n1 = fmaxf(m1, t1);
        if (newmax) {       // lane-local arithmetic only; divergence here is safe
            float a0 = ex2(m0 - n0), a1 = ex2(m1 - n1);
            l0 *= a0; l1 *= a1;
#pragma unroll
            for (int j = 0; j < 8; j++) {
                o[j][0] *= a0; o[j][1] *= a0; o[j][2] *= a1; o[j][3] *= a1;
            }
            m0 = n0; m1 = n1;
        }
        float rs0 = 0.f, rs1 = 0.f;
#pragma unroll
        for (int j = 0; j < 8; j++) {
            s[j][0] = ex2(s[j][0] - m0); rs0 += s[j][0];
            s[j][1] = ex2(s[j][1] - m0); rs0 += s[j][1];
            s[j][2] = ex2(s[j][2] - m1); rs1 += s[j][2];
            s[j][3] = ex2(s[j][3] - m1); rs1 += s[j][3];
        }
        l0 += rs0;      // per-lane partial; reduced once in epilogue
        l1 += rs1;

        // ---- O += P V : fp16 single-pass ----
#pragma unroll
        for (int kcp = 0; kcp < 2; kcp++) {
            uint32_t ph[2][4];
#pragma unroll
            for (int u = 0; u < 2; u++) {
                int nt = 4 * kcp + 2 * u;
                ph[u][0] = packh(s[nt][0],     s[nt][1]);
                ph[u][1] = packh(s[nt][2],     s[nt][3]);
                ph[u][2] = packh(s[nt + 1][0], s[nt + 1][1]);
                ph[u][3] = packh(s[nt + 1][2], s[nt + 1][3]);
            }
#pragma unroll
            for (int j2 = 0; j2 < 8; j2++) {
                uint32_t va = vhb + (32 * kcp + lane) * FPITCH + j2 * 16;
                uint32_t v0, v1, v2, v3;
                ldsm4t(v0, v1, v2, v3, va);
                mma_hf(o[j2], ph[0], v0, v1);
                mma_hf(o[j2], ph[1], v2, v3);
            }
        }
    }

    // ---- epilogue: reduce l across quad, normalize, fp16 store ----
    l0 += __shfl_xor_sync(0xffffffffu, l0, 1);
    l0 += __shfl_xor_sync(0xffffffffu, l0, 2);
    l1 += __shfl_xor_sync(0xffffffffu, l1, 1);
    l1 += __shfl_xor_sync(0xffffffffu, l1, 2);
    float inv0 = 1.f / l0, inv1 = 1.f / l1;
    size_t r0 = batch_row + (size_t)qt * 128 + w * 16 + grp;
#pragma unroll
    for (int j2 = 0; j2 < 8; j2++) {
        int c = h * HDIM + 8 * j2 + 2 * qr;
        *(uint32_t*)&Out[r0 * EMB + c]       = packh(o[j2][0] * inv0, o[j2][1] * inv0);
        *(uint32_t*)&Out[(r0 + 8) * EMB + c] = packh(o[j2][2] * inv1, o[j2][3] * inv1);
    }
}

// ------------------------------------------------------------------
extern "C" void kernel_launch(void* const* d_in, const int* in_sizes, int n_in,
                              void* d_out, int out_size) {
    const float* x  = (const float*)d_in[0];
    const float* Wq = (const float*)d_in[1];
    const float* Wk = (const float*)d_in[2];
    const float* Wv = (const float*)d_in[3];
    const float* Wo = (const float*)d_in[4];
    float* out = (float*)d_out;

    __nv_bfloat16 *gxh, *gxl, *gBqh, *gBql, *gQh, *gQl;
    __half *gxf, *gBvf, *gBoh, *gBol, *gAt;
    cudaGetSymbolAddress((void**)&gxh,  g_xh);
    cudaGetSymbolAddress((void**)&gxl,  g_xl);
    cudaGetSymbolAddress((void**)&gxf,  g_xf);
    cudaGetSymbolAddress((void**)&gBqh, g_Bqh);
    cudaGetSymbolAddress((void**)&gBql, g_Bql);
    cudaGetSymbolAddress((void**)&gBvf, g_Bvf);
    cudaGetSymbolAddress((void**)&gBoh, g_Boh);
    cudaGetSymbolAddress((void**)&gBol, g_Bol);
    cudaGetSymbolAddress((void**)&gQh,  g_QKVh);
    cudaGetSymbolAddress((void**)&gQl,  g_QKVl);
    cudaGetSymbolAddress((void**)&gAt,  g_At);

    const int GQKSMEM = 3 * GSTAGE;
    const int GVSMEM  = 4 * GVSTAGE;
    const int GOSMEM  = 4 * GOSTAGE;
    const int FSMEM   = 4 * FSTAGE;
    cudaFuncSetAttribute(gemm_qk,  cudaFuncAttributeMaxDynamicSharedMemorySize, GQKSMEM);
    cudaFuncSetAttribute(gemm_v,   cudaFuncAttributeMaxDynamicSharedMemorySize, GVSMEM);
    cudaFuncSetAttribute(gemm_o,   cudaFuncAttributeMaxDynamicSharedMemorySize, GOSMEM);
    cudaFuncSetAttribute(flash_mma, cudaFuncAttributeMaxDynamicSharedMemorySize, FSMEM);

    split_x<<<(MROWS * EMB + 255) / 256, 256>>>(x, gxh, gxl, gxf, MROWS * EMB);
    pack_qkv_t<<<dim3(16, 16, 3), 256>>>(Wq, Wk, Wv, gBqh, gBql, gBvf);
    pack_wo<<<(EMB * EMB + 255) / 256, 256>>>(Wo, gBoh, gBol);

    gemm_qk<<<dim3(16, MROWS / 128), 256, GQKSMEM>>>(gxh, gxl, gBqh, gBql, gQh, gQl);

    gemm_v<<<dim3(8, MROWS / 128), 256, GVSMEM>>>(
        gxf, gBvf, reinterpret_cast<__half*>(gQh) + 2 * EMB);

    flash_mma<<<dim3(SEQ / 128, HEADS, BATCH), 256, FSMEM>>>(gQh, gQl, gAt);

    gemm_o<<<dim3(EMB / 128, MROWS / 128), 256, GOSMEM>>>(gAt, gBoh, gBol, out, EMB);
}

// round 12
// speedup vs baseline: 4.6997x; 1.0288x over previous
#include <cuda_runtime.h>
#include <cuda_bf16.h>
#include <cuda_fp16.h>
#include <stdint.h>
#include <math.h>

#define BATCH 2
#define SEQ   2048
#define EMB   1024
#define HEADS 16
#define HDIM  64
#define MROWS (BATCH*SEQ)   /* 4096 */
#define QKVN  (3*EMB)       /* 3072 */
#define KDIM  EMB

#define QSCALE  0.02209708691207961f
#define QSCALE2 (QSCALE * 1.4426950408889634f)
#define SKIP_T  25.0f

// ---------------- scratch ----------------
__device__ __align__(256) __nv_bfloat16 g_xh [(size_t)MROWS*EMB];
__device__ __align__(256) __nv_bfloat16 g_xl [(size_t)MROWS*EMB];
__device__ __align__(256) __half        g_xf [(size_t)MROWS*EMB];
__device__ __align__(256) __nv_bfloat16 g_Bqh[(size_t)2*EMB*EMB];
__device__ __align__(256) __nv_bfloat16 g_Bql[(size_t)2*EMB*EMB];
__device__ __align__(256) __half        g_Bvf[(size_t)EMB*EMB];
__device__ __align__(256) __half        g_Boh[(size_t)EMB*EMB];
__device__ __align__(256) __half        g_Bol[(size_t)EMB*EMB];
__device__ __align__(256) __nv_bfloat16 g_QKVh[(size_t)MROWS*QKVN];  /* V region = fp16 bits */
__device__ __align__(256) __nv_bfloat16 g_QKVl[(size_t)MROWS*QKVN];
__device__ __align__(256) __half        g_At [(size_t)MROWS*EMB];

// ---------------- helpers ----------------
__device__ __forceinline__ uint32_t cvta_smem(const void* p) {
    uint32_t a;
    asm("{ .reg .u64 t; cvta.to.shared.u64 t, %1; cvt.u32.u64 %0, t; }" : "=r"(a) : "l"(p));
    return a;
}
__device__ __forceinline__ void cp16(uint32_t dst, const void* src) {
    asm volatile("cp.async.cg.shared.global [%0], [%1], 16;" :: "r"(dst), "l"(src));
}
#define CP_COMMIT() asm volatile("cp.async.commit_group;" ::: "memory")
#define CP_WAIT2()  asm volatile("cp.async.wait_group 2;" ::: "memory")
#define CP_WAIT1()  asm volatile("cp.async.wait_group 1;" ::: "memory")
#define CP_WAIT0()  asm volatile("cp.async.wait_group 0;" ::: "memory")

__device__ __forceinline__ void ldsm4(uint32_t& r0, uint32_t& r1, uint32_t& r2, uint32_t& r3,
                                      uint32_t addr) {
    asm volatile("ldmatrix.sync.aligned.m8n8.x4.shared.b16 {%0,%1,%2,%3},[%4];"
                 : "=r"(r0), "=r"(r1), "=r"(r2), "=r"(r3) : "r"(addr));
}
__device__ __forceinline__ void ldsm4t(uint32_t& r0, uint32_t& r1, uint32_t& r2, uint32_t& r3,
                                       uint32_t addr) {
    asm volatile("ldmatrix.sync.aligned.m8n8.x4.trans.shared.b16 {%0,%1,%2,%3},[%4];"
                 : "=r"(r0), "=r"(r1), "=r"(r2), "=r"(r3) : "r"(addr));
}
__device__ __forceinline__ void mma_bf(float c[4], const uint32_t a[4], uint32_t b0, uint32_t b1) {
    asm("mma.sync.aligned.m16n8k16.row.col.f32.bf16.bf16.f32 "
        "{%0,%1,%2,%3}, {%4,%5,%6,%7}, {%8,%9}, {%0,%1,%2,%3};"
        : "+f"(c[0]), "+f"(c[1]), "+f"(c[2]), "+f"(c[3])
        : "r"(a[0]), "r"(a[1]), "r"(a[2]), "r"(a[3]), "r"(b0), "r"(b1));
}
__device__ __forceinline__ void mma_hf(float c[4], const uint32_t a[4], uint32_t b0, uint32_t b1) {
    asm("mma.sync.aligned.m16n8k16.row.col.f32.f16.f16.f32 "
        "{%0,%1,%2,%3}, {%4,%5,%6,%7}, {%8,%9}, {%0,%1,%2,%3};"
        : "+f"(c[0]), "+f"(c[1]), "+f"(c[2]), "+f"(c[3])
        : "r"(a[0]), "r"(a[1]), "r"(a[2]), "r"(a[3]), "r"(b0), "r"(b1));
}
__device__ __forceinline__ float ex2(float x) {
    float r;
    asm("ex2.approx.ftz.f32 %0, %1;" : "=f"(r) : "f"(x));
    return r;
}
// pack two f32 to half2 (x -> low), then ex2 in half2 domain
__device__ __forceinline__ uint32_t ex2_h2(float x, float y) {
    uint32_t h, r;
    asm("cvt.rn.f16x2.f32 %0, %1, %2;" : "=r"(h) : "f"(y), "f"(x));
    asm("ex2.approx.f16x2 %0, %1;" : "=r"(r) : "r"(h));
    return r;
}
__device__ __forceinline__ uint32_t packbf(float x, float y) {
    __nv_bfloat162 t = __floats2bfloat162_rn(x, y);
    return *reinterpret_cast<uint32_t*>(&t);
}
__device__ __forceinline__ uint32_t packres(float x, float y, uint32_t h) {
    __nv_bfloat162 hh = *reinterpret_cast<__nv_bfloat162*>(&h);
    return packbf(x - __bfloat162float(hh.x), y - __bfloat162float(hh.y));
}
__device__ __forceinline__ uint32_t packh(float x, float y) {
    __half2 t = __floats2half2_rn(x, y);
    return *reinterpret_cast<uint32_t*>(&t);
}
__device__ __forceinline__ void split2(float v, __nv_bfloat16& hi, __nv_bfloat16& lo) {
    hi = __float2bfloat16(v);
    lo = __float2bfloat16(v - __bfloat162float(hi));
}

// ---------------- packing kernels ----------------
__global__ void split_x(const float* __restrict__ x, __nv_bfloat16* __restrict__ hi,
                        __nv_bfloat16* __restrict__ lo, __half* __restrict__ hf, int n) {
    int i = blockIdx.x * blockDim.x + threadIdx.x;
    if (i >= n) return;
    float v = x[i];
    split2(v, hi[i], lo[i]);
    hf[i] = __float2half(v);
}

__global__ void pack_qkv_t(const float* __restrict__ Wq, const float* __restrict__ Wk,
                           const float* __restrict__ Wv,
                           __nv_bfloat16* __restrict__ hi, __nv_bfloat16* __restrict__ lo,
                           __half* __restrict__ vf) {
    __shared__ float ts[64][65];
    const int tid = threadIdx.x;
    const int kb = blockIdx.x, hid = blockIdx.y, wh = blockIdx.z;
    const float* src = (wh == 0) ? Wq : (wh == 1) ? Wk : Wv;
    const float sc = (wh == 0) ? QSCALE2 : 1.0f;

#pragma unroll
    for (int p = 0; p < 16; p++) {
        int kr = (tid >> 6) + p * 4;
        int i  = tid & 63;
        ts[kr][i] = src[(size_t)hid * (EMB * HDIM) + (size_t)(kb * 64 + kr) * HDIM + i];
    }
    __syncthreads();
#pragma unroll
    for (int p = 0; p < 16; p++) {
        int i = (tid >> 6) + p * 4;
        int k = tid & 63;
        float v = ts[k][i] * sc;
        if (wh == 2) {
            size_t o = ((size_t)(hid * 64 + i) << 10) + kb * 64 + k;
            vf[o] = __float2half(v);
        } else {
            size_t o = ((size_t)(wh * 1024 + hid * 64 + i) << 10) + kb * 64 + k;
            split2(v, hi[o], lo[o]);
        }
    }
}

__global__ void pack_wo(const float* __restrict__ Wo,
                        __half* __restrict__ hi, __half* __restrict__ lo) {
    int idx = blockIdx.x * blockDim.x + threadIdx.x;
    if (idx >= EMB * EMB) return;
    float w = Wo[idx];
    __half h = __float2half(w);
    hi[idx] = h;
    lo[idx] = __float2half(w - __half2float(h));
}

// ---------------- merged projection: QK (bf16 3-pass) + V (fp16 1-pass) ----------------
#define GTILE  8192
#define GSTAGE 32768
#define GVSTAGE 16384
#define GNC    (KDIM/32)

__global__ __launch_bounds__(256, 2)
void gemm_proj(const __nv_bfloat16* __restrict__ Ah, const __nv_bfloat16* __restrict__ Al,
               const __nv_bfloat16* __restrict__ Bh, const __nv_bfloat16* __restrict__ Bl,
               __nv_bfloat16* __restrict__ Ch, __nv_bfloat16* __restrict__ Cl,
               const __half* __restrict__ Af, const __half* __restrict__ Bvf,
               __half* __restrict__ Cv) {
    extern __shared__ __align__(16) char smraw[];
    uint32_t smb = cvta_smem(smraw);
    const int tid = threadIdx.x, lane = tid & 31, wid = tid >> 5;
    const int wm = wid & 3, wn = wid >> 2;
    const int mb = blockIdx.y;
    const int grp = lane >> 2, qr = lane & 3;

    float acc[2][8][4];
#pragma unroll
    for (int a = 0; a < 2; a++)
#pragma unroll
        for (int b = 0; b < 8; b++)
#pragma unroll
            for (int c = 0; c < 4; c++) acc[a][b][c] = 0.f;

    if (blockIdx.x < 16) {
        // ---------- QK path: bf16 3-pass, 3-stage ----------
        const int nb = blockIdx.x;
        const __nv_bfloat16* gsrc[4] = {
            Ah + (size_t)mb * 128 * KDIM, Al + (size_t)mb * 128 * KDIM,
            Bh + (size_t)nb * 128 * KDIM, Bl + (size_t)nb * 128 * KDIM };

        auto ldchunk = [&](int buf, int ck) {
            uint32_t bb = smb + buf * GSTAGE;
#pragma unroll
            for (int q = 0; q < 8; q++) {
                int i = q * 256 + tid;
                int t = i >> 9;
                int r = (i >> 2) & 127;
                int c16 = i & 3;
                uint32_t dst = bb + t * GTILE + r * 64 + ((c16 ^ ((r >> 1) & 3)) << 4);
                cp16(dst, gsrc[t] + (size_t)r * KDIM + ck * 32 + c16 * 8);
            }
        };

        ldchunk(0, 0); CP_COMMIT();
        ldchunk(1, 1); CP_COMMIT();

        int buf = 0, rb = 2;
        for (int c = 0; c < GNC; c++) {
            if (c + 1 < GNC) CP_WAIT1(); else CP_WAIT0();
            __syncthreads();
            if (c + 2 < GNC) {
                ldchunk(rb, c + 2); CP_COMMIT();
                rb = (rb == 2) ? 0 : rb + 1;
            }
            uint32_t bb = smb + buf * GSTAGE;

#pragma unroll
            for (int s = 0; s < 2; s++) {
                uint32_t ah[2][4], al[2][4];
#pragma unroll
                for (int mt = 0; mt < 2; mt++) {
                    uint32_t row = 32 * wm + 16 * mt + ((lane >> 3) & 1) * 8 + (lane & 7);
                    uint32_t kb  = (lane >> 4) * 16 + s * 32;
                    uint32_t ad  = bb + row * 64 + ((((kb >> 4)) ^ ((row >> 1) & 3)) << 4);
                    ldsm4(ah[mt][0], ah[mt][1], ah[mt][2], ah[mt][3], ad);
                    ldsm4(al[mt][0], al[mt][1], al[mt][2], al[mt][3], ad + GTILE);
                }
#pragma unroll
                for (int np = 0; np < 4; np++) {
                    uint32_t row = 64 * wn + 16 * np + ((lane >> 4) & 1) * 8 + (lane & 7);
                    uint32_t kb  = ((lane >> 3) & 1) * 16 + s * 32;
                    uint32_t bd  = bb + 2 * GTILE + row * 64 + ((((kb >> 4)) ^ ((row >> 1) & 3)) << 4);
                    uint32_t bh0, bh1, bh2, bh3, bl0, bl1, bl2, bl3;
                    ldsm4(bh0, bh1, bh2, bh3, bd);
                    ldsm4(bl0, bl1, bl2, bl3, bd + GTILE);
#pragma unroll
                    for (int p = 0; p < 3; p++) {
                        const uint32_t* a0 = (p == 1) ? al[0] : ah[0];
                        const uint32_t* a1 = (p == 1) ? al[1] : ah[1];
                        uint32_t c0 = (p == 2) ? bl0 : bh0, c1 = (p == 2) ? bl1 : bh1;
                        uint32_t c2 = (p == 2) ? bl2 : bh2, c3 = (p == 2) ? bl3 : bh3;
                        mma_bf(acc[0][2 * np],     a0, c0, c1);
                        mma_bf(acc[1][2 * np],     a1, c0, c1);
                        mma_bf(acc[0][2 * np + 1], a0, c2, c3);
                        mma_bf(acc[1][2 * np + 1], a1, c2, c3);
                    }
                }
            }
            buf = (buf == 2) ? 0 : buf + 1;
        }

#pragma unroll
        for (int mt = 0; mt < 2; mt++) {
            size_t r0 = (size_t)mb * 128 + 32 * wm + 16 * mt + grp;
#pragma unroll
            for (int nt = 0; nt < 8; nt++) {
                int col = nb * 128 + 64 * wn + 8 * nt + 2 * qr;
                float* c4 = acc[mt][nt];
                uint32_t h0 = packbf(c4[0], c4[1]), l0 = packres(c4[0], c4[1], h0);
                uint32_t h1 = packbf(c4[2], c4[3]), l1 = packres(c4[2], c4[3], h1);
                *(uint32_t*)&Ch[r0 * QKVN + col]       = h0;
                *(uint32_t*)&Cl[r0 * QKVN + col]       = l0;
                *(uint32_t*)&Ch[(r0 + 8) * QKVN + col] = h1;
                *(uint32_t*)&Cl[(r0 + 8) * QKVN + col] = l1;
            }
        }
    } else {
        // ---------- V path: fp16 1-pass, 4-stage ----------
        const int nb = blockIdx.x - 16;
        const __half* gsrc[2] = { Af + (size_t)mb * 128 * KDIM, Bvf + (size_t)nb * 128 * KDIM };

        auto ldchunk = [&](int buf, int ck) {
            uint32_t bb = smb + buf * GVSTAGE;
#pragma unroll
            for (int q = 0; q < 4; q++) {
                int i = q * 256 + tid;
                int t = i >> 9;
                int r = (i >> 2) & 127;
                int c16 = i & 3;
                uint32_t dst = bb + t * GTILE + r * 64 + ((c16 ^ ((r >> 1) & 3)) << 4);
                cp16(dst, gsrc[t] + (size_t)r * KDIM + ck * 32 + c16 * 8);
            }
        };

        ldchunk(0, 0); CP_COMMIT();
        ldchunk(1, 1); CP_COMMIT();
        ldchunk(2, 2); CP_COMMIT();

        int rb = 3;
        for (int c = 0; c < GNC; c++) {
            int rem = GNC - c;
            if (rem >= 3) CP_WAIT2(); else if (rem == 2) CP_WAIT1(); else CP_WAIT0();
            __syncthreads();
            if (c + 3 < GNC) {
                ldchunk(rb, c + 3); CP_COMMIT();
                rb = (rb + 1) & 3;
            }
            uint32_t bb = smb + (c & 3) * GVSTAGE;

#pragma unroll
            for (int s = 0; s < 2; s++) {
                uint32_t ah[2][4];
#pragma unroll
                for (int mt = 0; mt < 2; mt++) {
                    uint32_t row = 32 * wm + 16 * mt + ((lane >> 3) & 1) * 8 + (lane & 7);
                    uint32_t kb  = (lane >> 4) * 16 + s * 32;
                    uint32_t ad  = bb + row * 64 + ((((kb >> 4)) ^ ((row >> 1) & 3)) << 4);
                    ldsm4(ah[mt][0], ah[mt][1], ah[mt][2], ah[mt][3], ad);
                }
#pragma unroll
                for (int np = 0; np < 4; np++) {
                    uint32_t row = 64 * wn + 16 * np + ((lane >> 4) & 1) * 8 + (lane & 7);
                    uint32_t kb  = ((lane >> 3) & 1) * 16 + s * 32;
                    uint32_t bd  = bb + GTILE + row * 64 + ((((kb >> 4)) ^ ((row >> 1) & 3)) << 4);
                    uint32_t b0, b1, b2, b3;
                    ldsm4(b0, b1, b2, b3, bd);
                    mma_hf(acc[0][2 * np],     ah[0], b0, b1);
                    mma_hf(acc[1][2 * np],     ah[1], b0, b1);
                    mma_hf(acc[0][2 * np + 1], ah[0], b2, b3);
                    mma_hf(acc[1][2 * np + 1], ah[1], b2, b3);
                }
            }
        }

#pragma unroll
        for (int mt = 0; mt < 2; mt++) {
            size_t r0 = (size_t)mb * 128 + 32 * wm + 16 * mt + grp;
#pragma unroll
            for (int nt = 0; nt < 8; nt++) {
                int col = nb * 128 + 64 * wn + 8 * nt + 2 * qr;
                float* c4 = acc[mt][nt];
                *(uint32_t*)&Cv[r0 * QKVN + col]       = packh(c4[0], c4[1]);
                *(uint32_t*)&Cv[(r0 + 8) * QKVN + col] = packh(c4[2], c4[3]);
            }
        }
    }
}

// ---------------- GEMM-O: fp16 2-pass, 4-stage ----------------
#define GOTILE  8192
#define GOSTAGE 24576

__global__ __launch_bounds__(256, 2)
void gemm_o(const __half* __restrict__ A, const __half* __restrict__ Bh,
            const __half* __restrict__ Bl, float* __restrict__ C, int N) {
    extern __shared__ __align__(16) char smraw[];
    uint32_t smb = cvta_smem(smraw);
    const int tid = threadIdx.x, lane = tid & 31, wid = tid >> 5;
    const int wm = wid & 3, wn = wid >> 2;
    const int nb = blockIdx.x, mb = blockIdx.y;

    const __half* gsrc[3] = {
        A + (size_t)mb * 128 * KDIM,
        Bh + (size_t)nb * 128 * KDIM, Bl + (size_t)nb * 128 * KDIM };

    auto ldchunk = [&](int buf, int ck) {
        uint32_t bb = smb + buf * GOSTAGE;
#pragma unroll
        for (int q = 0; q < 6; q++) {
            int i = q * 256 + tid;
            int t = i >> 9;
            int r = (i >> 2) & 127;
            int c16 = i & 3;
            uint32_t dst = bb + t * GOTILE + r * 64 + ((c16 ^ ((r >> 1) & 3)) << 4);
            cp16(dst, gsrc[t] + (size_t)r * KDIM + ck * 32 + c16 * 8);
        }
    };

    ldchunk(0, 0); CP_COMMIT();
    ldchunk(1, 1); CP_COMMIT();
    ldchunk(2, 2); CP_COMMIT();

    float acc[2][8][4];
#pragma unroll
    for (int a = 0; a < 2; a++)
#pragma unroll
        for (int b = 0; b < 8; b++)
#pragma unroll
            for (int c = 0; c < 4; c++) acc[a][b][c] = 0.f;

    int rb = 3;
    for (int c = 0; c < GNC; c++) {
        int rem = GNC - c;
        if (rem >= 3) CP_WAIT2(); else if (rem == 2) CP_WAIT1(); else CP_WAIT0();
        __syncthreads();
        if (c + 3 < GNC) {
            ldchunk(rb, c + 3); CP_COMMIT();
            rb = (rb + 1) & 3;
        }
        uint32_t bb = smb + (c & 3) * GOSTAGE;

#pragma unroll
        for (int s = 0; s < 2; s++) {
            uint32_t ah[2][4];
#pragma unroll
            for (int mt = 0; mt < 2; mt++) {
                uint32_t row = 32 * wm + 16 * mt + ((lane >> 3) & 1) * 8 + (lane & 7);
                uint32_t kb  = (lane >> 4) * 16 + s * 32;
                uint32_t ad  = bb + row * 64 + ((((kb >> 4)) ^ ((row >> 1) & 3)) << 4);
                ldsm4(ah[mt][0], ah[mt][1], ah[mt][2], ah[mt][3], ad);
            }
#pragma unroll
            for (int np = 0; np < 4; np++) {
                uint32_t row = 64 * wn + 16 * np + ((lane >> 4) & 1) * 8 + (lane & 7);
                uint32_t kb  = ((lane >> 3) & 1) * 16 + s * 32;
                uint32_t bd  = bb + GOTILE + row * 64 + ((((kb >> 4)) ^ ((row >> 1) & 3)) << 4);
                uint32_t bh0, bh1, bh2, bh3, bl0, bl1, bl2, bl3;
                ldsm4(bh0, bh1, bh2, bh3, bd);
                ldsm4(bl0, bl1, bl2, bl3, bd + GOTILE);
#pragma unroll
                for (int p = 0; p < 2; p++) {
                    uint32_t c0 = p ? bl0 : bh0, c1 = p ? bl1 : bh1;
                    uint32_t c2 = p ? bl2 : bh2, c3 = p ? bl3 : bh3;
                    mma_hf(acc[0][2 * np],     ah[0], c0, c1);
                    mma_hf(acc[1][2 * np],     ah[1], c0, c1);
                    mma_hf(acc[0][2 * np + 1], ah[0], c2, c3);
                    mma_hf(acc[1][2 * np + 1], ah[1], c2, c3);
                }
            }
        }
    }

    const int grp = lane >> 2, qr = lane & 3;
#pragma unroll
    for (int mt = 0; mt < 2; mt++) {
        size_t r0 = (size_t)mb * 128 + 32 * wm + 16 * mt + grp;
#pragma unroll
        for (int nt = 0; nt < 8; nt++) {
            int col = nb * 128 + 64 * wn + 8 * nt + 2 * qr;
            float* c4 = acc[mt][nt];
            *(float2*)&C[r0 * N + col]       = make_float2(c4[0], c4[1]);
            *(float2*)&C[(r0 + 8) * N + col] = make_float2(c4[2], c4[3]);
        }
    }
}

// ---------------- Flash attention: fp16x2 softmax + MMA l-sum ----------------
#define FPITCH 144
#define FTILE  9216
#define FSTAGE 27648
#define NKT    (SEQ/64)
#define ONES2  0x3C003C00u   /* half2(1,1) */

__global__ __launch_bounds__(256, 2)
void flash_mma(const __nv_bfloat16* __restrict__ Qh, const __nv_bfloat16* __restrict__ Ql,
               __half* __restrict__ Out) {
    extern __shared__ __align__(16) char smraw[];
    uint32_t smb = cvta_smem(smraw);

    const int tid = threadIdx.x, lane = tid & 31, w = tid >> 5;
    const int grp = lane >> 2, qr = lane & 3;
    const int qt = blockIdx.x, h = blockIdx.y, b = blockIdx.z;

    const size_t batch_row = (size_t)b * SEQ;

    const __nv_bfloat16* kvsrc[3] = {
        Qh + batch_row * QKVN + EMB + h * HDIM,
        Ql + batch_row * QKVN + EMB + h * HDIM,
        Qh + batch_row * QKVN + 2 * EMB + h * HDIM };

    auto ldtile = [&](int bf, int kt) {
        uint32_t bb = smb + bf * FSTAGE;
        size_t rbase = (size_t)kt * 64;
#pragma unroll
        for (int q = 0; q < 6; q++) {
            int i = q * 256 + tid;
            int t = i >> 9;
            int r = (i >> 3) & 63;
            int sg = i & 7;
            cp16(bb + t * FTILE + r * FPITCH + sg * 16,
                 kvsrc[t] + (rbase + r) * QKVN + sg * 8);
        }
    };

    uint32_t qh[4][4], ql[4][4];
    {
        size_t r0 = batch_row + (size_t)qt * 128 + w * 16 + grp;
        const __nv_bfloat16* qb_h = Qh + r0 * QKVN + h * HDIM;
        const __nv_bfloat16* qb_l = Ql + r0 * QKVN + h * HDIM;
#pragma unroll
        for (int t = 0; t < 4; t++) {
            int c0 = t * 16 + 2 * qr;
            qh[t][0] = *(const uint32_t*)(qb_h + c0);
            qh[t][1] = *(const uint32_t*)(qb_h + 8 * QKVN + c0);
            qh[t][2] = *(const uint32_t*)(qb_h + c0 + 8);
            qh[t][3] = *(const uint32_t*)(qb_h + 8 * QKVN + c0 + 8);
            ql[t][0] = *(const uint32_t*)(qb_l + c0);
            ql[t][1] = *(const uint32_t*)(qb_l + 8 * QKVN + c0);
            ql[t][2] = *(const uint32_t*)(qb_l + c0 + 8);
            ql[t][3] = *(const uint32_t*)(qb_l + 8 * QKVN + c0 + 8);
        }
    }

    float o[8][4];
#pragma unroll
    for (int j = 0; j < 8; j++)
#pragma unroll
        for (int c = 0; c < 4; c++) o[j][c] = 0.f;
    float lacc[4] = {0.f, 0.f, 0.f, 0.f};       // MMA-accumulated row sums of P
    float m0 = -1e30f, m1 = -1e30f;

    ldtile(0, 0); CP_COMMIT();
    ldtile(1, 1); CP_COMMIT();
    ldtile(2, 2); CP_COMMIT();

    int rb = 3;
    for (int kt = 0; kt < NKT; kt++) {
        int rem = NKT - kt;
        if (rem >= 3) CP_WAIT2(); else if (rem == 2) CP_WAIT1(); else CP_WAIT0();
        __syncthreads();
        if (kt + 3 < NKT) {
            ldtile(rb, kt + 3); CP_COMMIT();
            rb = (rb + 1) & 3;
        }
        uint32_t sb  = smb + (kt & 3) * FSTAGE;
        uint32_t khb = sb, vhb = sb + 2 * FTILE;

        // ---- S = Q K^T (16 x 64 per warp), bf16 3-pass ----
        float s[8][4];
#pragma unroll
        for (int j = 0; j < 8; j++) {
            uint32_t ka = khb + (8 * j + (lane & 7)) * FPITCH + (lane >> 3) * 16;
            uint32_t la = ka + FTILE;
            uint32_t h0, h1, h2, h3, h4, h5, h6, h7;
            uint32_t e0, e1, e2, e3, e4, e5, e6, e7;
            ldsm4(h0, h1, h2, h3, ka);
            ldsm4(h4, h5, h6, h7, ka + 64);
            ldsm4(e0, e1, e2, e3, la);
            ldsm4(e4, e5, e6, e7, la + 64);
            s[j][0] = s[j][1] = s[j][2] = s[j][3] = 0.f;
            mma_bf(s[j], qh[0], h0, h1); mma_bf(s[j], ql[0], h0, h1); mma_bf(s[j], qh[0], e0, e1);
            mma_bf(s[j], qh[1], h2, h3); mma_bf(s[j], ql[1], h2, h3); mma_bf(s[j], qh[1], e2, e3);
            mma_bf(s[j], qh[2], h4, h5); mma_bf(s[j], ql[2], h4, h5); mma_bf(s[j], qh[2], e4, e5);
            mma_bf(s[j], qh[3], h6, h7); mma_bf(s[j], ql[3], h6, h7); mma_bf(s[j], qh[3], e6, e7);
        }

        // ---- maxima (quad-reduced) ----
        float t0 = -1e30f, t1 = -1e30f;
#pragma unroll
        for (int j = 0; j < 8; j++) {
            t0 = fmaxf(t0, fmaxf(s[j][0], s[j][1]));
            t1 = fmaxf(t1, fmaxf(s[j][2], s[j][3]));
        }
        t0 = fmaxf(t0, __shfl_xor_sync(0xffffffffu, t0, 1));
        t0 = fmaxf(t0, __shfl_xor_sync(0xffffffffu, t0, 2));
        t1 = fmaxf(t1, __shfl_xor_sync(0xffffffffu, t1, 1));
        t1 = fmaxf(t1, __shfl_xor_sync(0xffffffffu, t1, 2));

        bool negl = (t0 < m0 - SKIP_T) && (t1 < m1 - SKIP_T);
        if (__all_sync(0xffffffffu, negl)) continue;

        bool newmax = (t0 > m0) || (t1 > m1);
        if (newmax) {
            float n0 = fmaxf(m0, t0), n1 = fmaxf(m1, t1);
            float a0 = ex2(m0 - n0), a1 = ex2(m1 - n1);
            lacc[0] *= a0; lacc[1] *= a0; lacc[2] *= a1; lacc[3] *= a1;
#pragma unroll
            for (int j = 0; j < 8; j++) {
                o[j][0] *= a0; o[j][1] *= a0; o[j][2] *= a1; o[j][3] *= a1;
            }
            m0 = n0; m1 = n1;
        }

        // ---- P = exp2(s - m) in fp16x2, as MMA A-fragments ----
        uint32_t pf[4][4];
#pragma unroll
        for (int f = 0; f < 4; f++) {
            int j0 = 2 * f, j1 = 2 * f + 1;
            pf[f][0] = ex2_h2(s[j0][0] - m0, s[j0][1] - m0);
            pf[f][1] = ex2_h2(s[j0][2] - m1, s[j0][3] - m1);
            pf[f][2] = ex2_h2(s[j1][0] - m0, s[j1][1] - m0);
            pf[f][3] = ex2_h2(s[j1][2] - m1, s[j1][3] - m1);
        }

        // ---- l += P · 1 (row sums via MMA; consistent with PV numerator) ----
        mma_hf(lacc, pf[0], ONES2, ONES2);
        mma_hf(lacc, pf[1], ONES2, ONES2);
        mma_hf(lacc, pf[2], ONES2, ONES2);
        mma_hf(lacc, pf[3], ONES2, ONES2);

        // ---- O += P V : fp16 single-pass ----
#pragma unroll
        for (int kcp = 0; kcp < 2; kcp++) {
#pragma unroll
            for (int j2 = 0; j2 < 8; j2++) {
                uint32_t va = vhb + (32 * kcp + lane) * FPITCH + j2 * 16;
                uint32_t v0, v1, v2, v3;
                ldsm4t(v0, v1, v2, v3, va);
                mma_hf(o[j2], pf[2 * kcp],     v0, v1);
                mma_hf(o[j2], pf[2 * kcp + 1], v2, v3);
            }
        }
    }

    // ---- epilogue: lacc already holds complete row sums (no shuffles) ----
    float inv0 = 1.f / lacc[0], inv1 = 1.f / lacc[2];
    size_t r0 = batch_row + (size_t)qt * 128 + w * 16 + grp;
#pragma unroll
    for (int j2 = 0; j2 < 8; j2++) {
        int c = h * HDIM + 8 * j2 + 2 * qr;
        *(uint32_t*)&Out[r0 * EMB + c]       = packh(o[j2][0] * inv0, o[j2][1] * inv0);
        *(uint32_t*)&Out[(r0 + 8) * EMB + c] = packh(o[j2][2] * inv1, o[j2][3] * inv1);
    }
}

// ------------------------------------------------------------------
extern "C" void kernel_launch(void* const* d_in, const int* in_sizes, int n_in,
                              void* d_out, int out_size) {
    const float* x  = (const float*)d_in[0];
    const float* Wq = (const float*)d_in[1];
    const float* Wk = (const float*)d_in[2];
    const float* Wv = (const float*)d_in[3];
    const float* Wo = (const float*)d_in[4];
    float* out = (float*)d_out;

    __nv_bfloat16 *gxh, *gxl, *gBqh, *gBql, *gQh, *gQl;
    __half *gxf, *gBvf, *gBoh, *gBol, *gAt;
    cudaGetSymbolAddress((void**)&gxh,  g_xh);
    cudaGetSymbolAddress((void**)&gxl,  g_xl);
    cudaGetSymbolAddress((void**)&gxf,  g_xf);
    cudaGetSymbolAddress((void**)&gBqh, g_Bqh);
    cudaGetSymbolAddress((void**)&gBql, g_Bql);
    cudaGetSymbolAddress((void**)&gBvf, g_Bvf);
    cudaGetSymbolAddress((void**)&gBoh, g_Boh);
    cudaGetSymbolAddress((void**)&gBol, g_Bol);
    cudaGetSymbolAddress((void**)&gQh,  g_QKVh);
    cudaGetSymbolAddress((void**)&gQl,  g_QKVl);
    cudaGetSymbolAddress((void**)&gAt,  g_At);

    const int GPSMEM = 3 * GSTAGE;     // 98304 (covers 4*GVSTAGE=65536 too)
    const int GOSMEM = 4 * GOSTAGE;
    const int FSMEM  = 4 * FSTAGE;
    cudaFuncSetAttribute(gemm_proj, cudaFuncAttributeMaxDynamicSharedMemorySize, GPSMEM);
    cudaFuncSetAttribute(gemm_o,    cudaFuncAttributeMaxDynamicSharedMemorySize, GOSMEM);
    cudaFuncSetAttribute(flash_mma, cudaFuncAttributeMaxDynamicSharedMemorySize, FSMEM);

    split_x<<<(MROWS * EMB + 255) / 256, 256>>>(x, gxh, gxl, gxf, MROWS * EMB);
    pack_qkv_t<<<dim3(16, 16, 3), 256>>>(Wq, Wk, Wv, gBqh, gBql, gBvf);
    pack_wo<<<(EMB * EMB + 255) / 256, 256>>>(Wo, gBoh, gBol);

    // merged QK (bf16 3-pass) + V (fp16 1-pass) projection
    gemm_proj<<<dim3(24, MROWS / 128), 256, GPSMEM>>>(
        gxh, gxl, gBqh, gBql, gQh, gQl,
        gxf, gBvf, reinterpret_cast<__half*>(gQh) + 2 * EMB);

    flash_mma<<<dim3(SEQ / 128, HEADS, BATCH), 256, FSMEM>>>(gQh, gQl, gAt);

    gemm_o<<<dim3(EMB / 128, MROWS / 128), 256, GOSMEM>>>(gAt, gBoh, gBol, out, EMB);
}